// round 8
// baseline (speedup 1.0000x reference)
#include <cuda_runtime.h>
#include <math.h>
#include <stdint.h>

// ---------------------------------------------------------------------------
// Performer FAVOR+ cross-attention forward.
// B=8, Nq=1024, Nk=4096, D=512, H=8, DH=64, M=256
// Round 7: revert tcgen05 (unsupported on plain sm_100 target).
// Base = R5 (828us). New: tmma256 (256x128 CTA tile, 8 warps) for the
// five NN GEMMs to cut B-side smem wavefronts per MAC by 2x.
// ---------------------------------------------------------------------------

#define BATCH 8
#define NQ 1024
#define NK 4096
#define DMODEL 512
#define NH 8
#define DHD 64
#define MF 256
#define BHN 64          // BATCH * NH

#define DN_SCALE 0.35355339059327379f  // 64^-0.25
#define RATIO 0.0625f                  // 256^-0.5
#define EPSF 1e-4f

// -------------------- scratch (static device allocations) ------------------
__device__ float g_Q[BATCH * NQ * DMODEL];          // 16 MB
__device__ float g_K[BATCH * NK * DMODEL];          // 64 MB
__device__ float g_V[BATCH * NK * DMODEL];          // 64 MB
__device__ float g_projT[DHD * MF];                 // proj transposed [64][256]
__device__ float g_qp[BHN * NQ * MF];               // phi(dashQ), 64 MB
__device__ float g_kp[(size_t)BHN * NK * MF];       // raw dashK, 256 MB
__device__ unsigned g_stabEnc[BHN];
__device__ float g_kcPart[8 * BHN * MF];
__device__ float g_kc[BHN * MF];
__device__ float g_denom[BHN * NQ];
__device__ float g_ctxPart[8 * BHN * MF * DHD];     // 32 MB
__device__ float g_ctx[BHN * MF * DHD];             // 4 MB
__device__ float g_attn[BATCH * NQ * DMODEL];       // 16 MB

// -------------------- helpers ----------------------------------------------
__device__ __forceinline__ uint32_t f2tf32(float f) {
    uint32_t u;
    asm("cvt.rna.tf32.f32 %0, %1;" : "=r"(u) : "f"(f));
    return u;
}
__device__ __forceinline__ float f2tf32f(float f) {
    return __uint_as_float(f2tf32(f));
}

__device__ __forceinline__ unsigned encodeF(float f) {
    unsigned u = __float_as_uint(f);
    return (u & 0x80000000u) ? ~u : (u | 0x80000000u);
}
__device__ __forceinline__ float decodeF(unsigned e) {
    unsigned u = (e & 0x80000000u) ? (e ^ 0x80000000u) : ~e;
    return __uint_as_float(u);
}

#define MMA_TF32(d, a, b)                                               \
    asm volatile(                                                       \
        "mma.sync.aligned.m16n8k8.row.col.f32.tf32.tf32.f32 "           \
        "{%0,%1,%2,%3}, {%4,%5,%6,%7}, {%8,%9}, {%0,%1,%2,%3};\n"       \
        : "+f"(d[0]), "+f"(d[1]), "+f"(d[2]), "+f"(d[3])                \
        : "r"(a[0]), "r"(a[1]), "r"(a[2]), "r"(a[3]),                   \
          "r"(b[0]), "r"(b[1]))

#define LDSM4(r0, r1, r2, r3, addr)                                     \
    asm volatile(                                                       \
        "ldmatrix.sync.aligned.m8n8.x4.shared.b16 {%0,%1,%2,%3}, [%4];" \
        : "=r"(r0), "=r"(r1), "=r"(r2), "=r"(r3) : "r"(addr))

__device__ __forceinline__ float warpRedMax(float v) {
#pragma unroll
    for (int o = 16; o > 0; o >>= 1) v = fmaxf(v, __shfl_xor_sync(0xffffffffu, v, o));
    return v;
}

// ---------------------------------------------------------------------------
// tmma256: TF32 GEMM, CTA tile 256 x 128 x 16, 256 threads, 8 warps (4Mx2N),
// warp tile 64x64, ldmatrix fragments, double-buffered smem (dynamic, 60KB).
// C = alpha * A[M,K] @ B[K,N] (+ bias), row-major. M%256==0, N%128==0, K%16==0.
// Batched over grid.z: z = (z1*d2 + z2)*d3 + z3.
// Optional maxOut: atomicMax of encoded alpha*acc per z.
// ---------------------------------------------------------------------------
__global__ __launch_bounds__(256) void tmma256(
    const float* __restrict__ A, const float* __restrict__ B,
    float* __restrict__ C, const float* __restrict__ bias,
    unsigned* __restrict__ maxOut,
    int K, int lda, int ldb, int ldc,
    int d2, int d3,
    long oA1, long oA2, long oA3,
    long oB1, long oB2, long oB3,
    long oC1, long oC2, long oC3,
    float alpha)
{
    {
        int z = blockIdx.z;
        int z3 = z % d3;
        int zq = z / d3;
        int z2 = zq % d2;
        int z1 = zq / d2;
        A += z1 * oA1 + z2 * oA2 + z3 * oA3;
        B += z1 * oB1 + z2 * oB2 + z3 * oB3;
        C += z1 * oC1 + z2 * oC2 + z3 * oC3;
    }

    extern __shared__ uint32_t smU[];
    uint32_t* AsW = smU;                  // [2][256][20]
    uint32_t* BsW = smU + 2 * 256 * 20;   // [2][128][20]
    __shared__ float redMax[8];

    const int tid = threadIdx.x;
    const int lane = tid & 31;
    const int warp = tid >> 5;            // 0..7
    const int warpM = warp >> 1;          // 0..3
    const int warpN = warp & 1;           // 0..1
    const int gid = lane >> 2;
    const int tig = lane & 3;

    const int m0 = blockIdx.y * 256;
    const int n0 = blockIdx.x * 128;

    const unsigned asU = (unsigned)__cvta_generic_to_shared(AsW);
    const unsigned bsU = (unsigned)__cvta_generic_to_shared(BsW);
    const int ldsmRow = (lane & 7) + ((lane >> 3) & 1) * 8;
    const int ldsmK   = (lane >> 4) * 4;

    const int bn  = tid & 127;            // B column within tile
    const int bkg = (tid >> 7) * 8;       // B k-group: 0 or 8

    float acc[4][8][4];
#pragma unroll
    for (int i = 0; i < 4; i++)
#pragma unroll
        for (int j = 0; j < 8; j++)
#pragma unroll
            for (int r = 0; r < 4; r++) acc[i][j][r] = 0.f;

    const int ntiles = K >> 4;
    float pa[16], pb[8];

    auto loadTile = [&](int k0) {
        const float* Ap = A + (long)(m0 + tid) * lda + k0;
        *(float4*)(pa + 0)  = *(const float4*)(Ap + 0);
        *(float4*)(pa + 4)  = *(const float4*)(Ap + 4);
        *(float4*)(pa + 8)  = *(const float4*)(Ap + 8);
        *(float4*)(pa + 12) = *(const float4*)(Ap + 12);
        const float* Bp = B + (long)(k0 + bkg) * ldb + n0 + bn;
#pragma unroll
        for (int k = 0; k < 8; k++) pb[k] = Bp[(long)k * ldb];
    };

    auto storeTile = [&](int buf) {
#pragma unroll
        for (int g = 0; g < 4; g++) {
            uint4 u;
            u.x = f2tf32(pa[g * 4 + 0]); u.y = f2tf32(pa[g * 4 + 1]);
            u.z = f2tf32(pa[g * 4 + 2]); u.w = f2tf32(pa[g * 4 + 3]);
            *(uint4*)(AsW + buf * 5120 + tid * 20 + g * 4) = u;
        }
#pragma unroll
        for (int g = 0; g < 2; g++) {
            uint4 u;
            u.x = f2tf32(pb[g * 4 + 0]); u.y = f2tf32(pb[g * 4 + 1]);
            u.z = f2tf32(pb[g * 4 + 2]); u.w = f2tf32(pb[g * 4 + 3]);
            *(uint4*)(BsW + buf * 2560 + bn * 20 + bkg + g * 4) = u;
        }
    };

    auto computeTile = [&](int buf) {
#pragma unroll
        for (int ks = 0; ks < 16; ks += 8) {
            uint32_t af[4][4];
            uint32_t bf[8][2];
#pragma unroll
            for (int i = 0; i < 4; i++) {
                unsigned addr = asU + (unsigned)((buf * 5120 +
                    (warpM * 64 + i * 16 + ldsmRow) * 20 + ks + ldsmK) * 4);
                LDSM4(af[i][0], af[i][1], af[i][2], af[i][3], addr);
            }
#pragma unroll
            for (int jj = 0; jj < 4; jj++) {
                unsigned addr = bsU + (unsigned)((buf * 2560 +
                    (warpN * 64 + jj * 16 + ldsmRow) * 20 + ks + ldsmK) * 4);
                uint32_t r0, r1, r2, r3;
                LDSM4(r0, r1, r2, r3, addr);
                bf[jj * 2][0] = r0; bf[jj * 2 + 1][0] = r1;
                bf[jj * 2][1] = r2; bf[jj * 2 + 1][1] = r3;
            }
#pragma unroll
            for (int i = 0; i < 4; i++)
#pragma unroll
                for (int j = 0; j < 8; j++)
                    MMA_TF32(acc[i][j], af[i], bf[j]);
        }
    };

    loadTile(0);
    storeTile(0);
    __syncthreads();
    for (int kt = 0; kt < ntiles; kt++) {
        const int buf = kt & 1;
        const bool more = (kt + 1) < ntiles;
        if (more) loadTile((kt + 1) << 4);
        computeTile(buf);
        if (more) storeTile(buf ^ 1);
        __syncthreads();
    }

    // ---- epilogue ----
    float vmax = -1e30f;
#pragma unroll
    for (int i = 0; i < 4; i++) {
        const int rL = m0 + warpM * 64 + i * 16 + gid;
#pragma unroll
        for (int j = 0; j < 8; j++) {
            const int col = n0 + warpN * 64 + (j >> 1) * 16 + (j & 1) * 8 + tig * 2;
            float v0 = alpha * acc[i][j][0], v1 = alpha * acc[i][j][1];
            float v2 = alpha * acc[i][j][2], v3 = alpha * acc[i][j][3];
            if (maxOut)
                vmax = fmaxf(vmax, fmaxf(fmaxf(v0, v1), fmaxf(v2, v3)));
            if (bias) {
                float2 bv = *(const float2*)(bias + col);
                v0 += bv.x; v1 += bv.y; v2 += bv.x; v3 += bv.y;
            }
            *(float2*)(C + (long)rL * ldc + col) = make_float2(v0, v1);
            *(float2*)(C + (long)(rL + 8) * ldc + col) = make_float2(v2, v3);
        }
    }

    if (maxOut) {
        vmax = warpRedMax(vmax);
        if (lane == 0) redMax[warp] = vmax;
        __syncthreads();
        if (tid == 0) {
            float m = redMax[0];
#pragma unroll
            for (int i = 1; i < 8; i++) m = fmaxf(m, redMax[i]);
            atomicMax(maxOut + blockIdx.z, encodeF(m));
        }
    }
}

// ---------------------------------------------------------------------------
// tmma2 (R3, proven): TF32 GEMM, block 128 x BN x 16, 128 threads, 4 warps.
// Kept for the attn = (qp @ ctx)/denom GEMM (BN=64, rowdiv path).
// ---------------------------------------------------------------------------
template <int BN, bool TRANSA>
__global__ __launch_bounds__(128, 2) void tmma2(
    const float* __restrict__ A, const float* __restrict__ B,
    float* __restrict__ C, const float* __restrict__ bias,
    const float* __restrict__ rowdiv, unsigned* __restrict__ maxOut,
    int K, int lda, int ldb, int ldc,
    int d2, int d3,
    long oA1, long oA2, long oA3,
    long oB1, long oB2, long oB3,
    long oC1, long oC2, long oC3,
    long oD2, long oD3,
    float alpha)
{
    constexpr int WN = BN / 2;
    constexpr int NJ = WN / 8;
    constexpr int NJJ = WN / 16;

    {
        int z = blockIdx.z;
        int z3 = z % d3;
        int zq = z / d3;
        int z2 = zq % d2;
        int z1 = zq / d2;
        A += z1 * oA1 + z2 * oA2 + z3 * oA3;
        B += z1 * oB1 + z2 * oB2 + z3 * oB3;
        C += z1 * oC1 + z2 * oC2 + z3 * oC3;
        if (rowdiv) rowdiv += z2 * oD2 + z3 * oD3;
    }

    __shared__ uint32_t As[2][128][20];
    __shared__ uint32_t Bs[2][BN][20];
    __shared__ float redMax[4];

    const int tid = threadIdx.x;
    const int lane = tid & 31;
    const int warp = tid >> 5;
    const int warpM = warp >> 1;
    const int warpN = warp & 1;
    const int gid = lane >> 2;
    const int tig = lane & 3;

    const int m0 = blockIdx.y * 128;
    const int n0 = blockIdx.x * BN;

    const unsigned asU = (unsigned)__cvta_generic_to_shared(&As[0][0][0]);
    const unsigned bsU = (unsigned)__cvta_generic_to_shared(&Bs[0][0][0]);
    const int ldsmRow = (lane & 7) + ((lane >> 3) & 1) * 8;
    const int ldsmK   = (lane >> 4) * 4;

    float acc[4][NJ][4];
#pragma unroll
    for (int i = 0; i < 4; i++)
#pragma unroll
        for (int j = 0; j < NJ; j++)
#pragma unroll
            for (int r = 0; r < 4; r++) acc[i][j][r] = 0.f;

    const int ntiles = K >> 4;
    float pa[16], pb[16];

    auto loadTile = [&](int k0) {
        if (!TRANSA) {
            const float* Ap = A + (long)(m0 + tid) * lda + k0;
            *(float4*)(pa + 0)  = *(const float4*)(Ap + 0);
            *(float4*)(pa + 4)  = *(const float4*)(Ap + 4);
            *(float4*)(pa + 8)  = *(const float4*)(Ap + 8);
            *(float4*)(pa + 12) = *(const float4*)(Ap + 12);
        } else {
            const float* Ap = A + (long)k0 * lda + m0 + tid;
#pragma unroll
            for (int k = 0; k < 16; k++) pa[k] = Ap[(long)k * lda];
        }
        if (BN == 128) {
            const float* Bp = B + (long)k0 * ldb + n0 + tid;
#pragma unroll
            for (int k = 0; k < 16; k++) pb[k] = Bp[(long)k * ldb];
        } else {
            const float* Bp = B + (long)(k0 + (tid >> 6) * 8) * ldb + n0 + (tid & 63);
#pragma unroll
            for (int k = 0; k < 8; k++) pb[k] = Bp[(long)k * ldb];
        }
    };

    auto storeTile = [&](int buf) {
#pragma unroll
        for (int g = 0; g < 4; g++) {
            uint4 u;
            u.x = f2tf32(pa[g * 4 + 0]); u.y = f2tf32(pa[g * 4 + 1]);
            u.z = f2tf32(pa[g * 4 + 2]); u.w = f2tf32(pa[g * 4 + 3]);
            *(uint4*)&As[buf][tid][g * 4] = u;
        }
        if (BN == 128) {
#pragma unroll
            for (int g = 0; g < 4; g++) {
                uint4 u;
                u.x = f2tf32(pb[g * 4 + 0]); u.y = f2tf32(pb[g * 4 + 1]);
                u.z = f2tf32(pb[g * 4 + 2]); u.w = f2tf32(pb[g * 4 + 3]);
                *(uint4*)&Bs[buf][tid][g * 4] = u;
            }
        } else {
            const int n = tid & 63, kg = (tid >> 6) * 8;
#pragma unroll
            for (int g = 0; g < 2; g++) {
                uint4 u;
                u.x = f2tf32(pb[g * 4 + 0]); u.y = f2tf32(pb[g * 4 + 1]);
                u.z = f2tf32(pb[g * 4 + 2]); u.w = f2tf32(pb[g * 4 + 3]);
                *(uint4*)&Bs[buf][n][kg + g * 4] = u;
            }
        }
    };

    auto computeTile = [&](int buf) {
#pragma unroll
        for (int ks = 0; ks < 16; ks += 8) {
            uint32_t af[4][4];
            uint32_t bf[NJ][2];
#pragma unroll
            for (int i = 0; i < 4; i++) {
                unsigned addr = asU + (unsigned)((buf * 128 * 20 +
                    (warpM * 64 + i * 16 + ldsmRow) * 20 + ks + ldsmK) * 4);
                LDSM4(af[i][0], af[i][1], af[i][2], af[i][3], addr);
            }
#pragma unroll
            for (int jj = 0; jj < NJJ; jj++) {
                unsigned addr = bsU + (unsigned)((buf * BN * 20 +
                    (warpN * WN + jj * 16 + ldsmRow) * 20 + ks + ldsmK) * 4);
                uint32_t r0, r1, r2, r3;
                LDSM4(r0, r1, r2, r3, addr);
                bf[jj * 2][0] = r0; bf[jj * 2 + 1][0] = r1;
                bf[jj * 2][1] = r2; bf[jj * 2 + 1][1] = r3;
            }
#pragma unroll
            for (int i = 0; i < 4; i++)
#pragma unroll
                for (int j = 0; j < NJ; j++)
                    MMA_TF32(acc[i][j], af[i], bf[j]);
        }
    };

    loadTile(0);
    storeTile(0);
    __syncthreads();
    for (int kt = 0; kt < ntiles; kt++) {
        const int buf = kt & 1;
        const bool more = (kt + 1) < ntiles;
        if (more) loadTile((kt + 1) << 4);
        computeTile(buf);
        if (more) storeTile(buf ^ 1);
        __syncthreads();
    }

    float vmax = -1e30f;
#pragma unroll
    for (int i = 0; i < 4; i++) {
        const int rL = m0 + warpM * 64 + i * 16 + gid;
        float dv0 = 1.f, dv1 = 1.f;
        if (rowdiv) { dv0 = 1.0f / rowdiv[rL]; dv1 = 1.0f / rowdiv[rL + 8]; }
#pragma unroll
        for (int j = 0; j < NJ; j++) {
            const int col = n0 + warpN * WN + (j >> 1) * 16 + (j & 1) * 8 + tig * 2;
            float v0 = alpha * acc[i][j][0], v1 = alpha * acc[i][j][1];
            float v2 = alpha * acc[i][j][2], v3 = alpha * acc[i][j][3];
            if (maxOut)
                vmax = fmaxf(vmax, fmaxf(fmaxf(v0, v1), fmaxf(v2, v3)));
            if (bias) {
                float2 bv = *(const float2*)(bias + col);
                v0 += bv.x; v1 += bv.y; v2 += bv.x; v3 += bv.y;
            }
            v0 *= dv0; v1 *= dv0; v2 *= dv1; v3 *= dv1;
            *(float2*)(C + (long)rL * ldc + col) = make_float2(v0, v1);
            *(float2*)(C + (long)(rL + 8) * ldc + col) = make_float2(v2, v3);
        }
    }

    if (maxOut) {
        vmax = warpRedMax(vmax);
        if (lane == 0) redMax[warp] = vmax;
        __syncthreads();
        if (tid == 0) {
            float m = fmaxf(fmaxf(redMax[0], redMax[1]), fmaxf(redMax[2], redMax[3]));
            atomicMax(maxOut + blockIdx.z, encodeF(m));
        }
    }
}

// ---------------------------------------------------------------------------
// ctx_fused (R5, proven): dash -> phi -> kc partial -> phi^T @ V, per chunk.
// ---------------------------------------------------------------------------
#define CF_AP 264
#define CF_BP 72
__global__ __launch_bounds__(256) void ctx_fused(
    const float* __restrict__ kpDash, const float* __restrict__ Km,
    const float* __restrict__ V, const unsigned* __restrict__ stabEnc,
    float* __restrict__ ctxPart, float* __restrict__ kcPart)
{
    extern __shared__ float sm[];
    float* As = sm;                       // 64 * 264
    float* Bs = As + 64 * CF_AP;          // 64 * 72
    float* diag = Bs + 64 * CF_BP;        // 64
    const uint32_t* AsU = (const uint32_t*)As;
    const uint32_t* BsU = (const uint32_t*)Bs;

    const int split = blockIdx.x, bh = blockIdx.y;
    const int b = bh >> 3, h = bh & 7;
    const int t = threadIdx.x;
    const int lane = t & 31, warp = t >> 5;
    const int warpM = warp >> 1;          // 0..3
    const int warpN = warp & 1;           // 0..1
    const int gid = lane >> 2, tig = lane & 3;
    const float stab = decodeF(stabEnc[bh]);
    const int sBase = split * 512;

    float acc[4][4][4];
#pragma unroll
    for (int i = 0; i < 4; i++)
#pragma unroll
        for (int j = 0; j < 4; j++)
#pragma unroll
            for (int r = 0; r < 4; r++) acc[i][j][r] = 0.f;
    float kcLoc = 0.f;

    for (int chunk = 0; chunk < 8; chunk++) {
        const int s0 = sBase + chunk * 64;
        __syncthreads();

        const float* dsrc = kpDash + ((long)bh * NK + s0) * MF;
#pragma unroll
        for (int i = 0; i < 16; i++) {
            int linear = i * 256 + t;
            int s = linear >> 6, c4 = linear & 63;
            float4 v = *(const float4*)(dsrc + (long)s * MF + c4 * 4);
            *(float4*)(As + s * CF_AP + c4 * 4) = v;
        }
        {
            int r = t >> 2, p = t & 3;
            const float* kr = Km + ((long)(b * NK + s0 + r)) * DMODEL + h * DHD + p * 16;
            float ss = 0.f;
#pragma unroll
            for (int i = 0; i < 4; i++) {
                float4 v = *(const float4*)(kr + i * 4);
                ss += v.x * v.x + v.y * v.y + v.z * v.z + v.w * v.w;
            }
            ss += __shfl_xor_sync(0xffffffffu, ss, 1);
            ss += __shfl_xor_sync(0xffffffffu, ss, 2);
            if (p == 0) diag[r] = ss * 0.0625f;
        }
        const float* vsrc = V + ((long)(b * NK + s0)) * DMODEL + h * DHD;
#pragma unroll
        for (int i = 0; i < 4; i++) {
            int linear = i * 256 + t;
            int s = linear >> 4, c4 = linear & 15;
            float4 v = *(const float4*)(vsrc + (long)s * DMODEL + c4 * 4);
            v.x = f2tf32f(v.x); v.y = f2tf32f(v.y);
            v.z = f2tf32f(v.z); v.w = f2tf32f(v.w);
            *(float4*)(Bs + s * CF_BP + c4 * 4) = v;
        }
        __syncthreads();

        {
            float csum = 0.f;
#pragma unroll 8
            for (int s = 0; s < 64; s++) {
                float val = As[s * CF_AP + t];
                val = RATIO * (__expf(val - diag[s] - stab) + EPSF);
                csum += val;
                As[s * CF_AP + t] = f2tf32f(val);
            }
            kcLoc += csum;
        }
        __syncthreads();

#pragma unroll
        for (int ks = 0; ks < 64; ks += 8) {
            uint32_t af[4][4], bf[4][2];
#pragma unroll
            for (int i = 0; i < 4; i++) {
                const int mB = warpM * 64 + i * 16;
                af[i][0] = AsU[(ks + tig) * CF_AP + mB + gid];
                af[i][1] = AsU[(ks + tig) * CF_AP + mB + gid + 8];
                af[i][2] = AsU[(ks + tig + 4) * CF_AP + mB + gid];
                af[i][3] = AsU[(ks + tig + 4) * CF_AP + mB + gid + 8];
            }
#pragma unroll
            for (int j = 0; j < 4; j++) {
                const int nB = warpN * 32 + j * 8;
                bf[j][0] = BsU[(ks + tig) * CF_BP + nB + gid];
                bf[j][1] = BsU[(ks + tig + 4) * CF_BP + nB + gid];
            }
#pragma unroll
            for (int i = 0; i < 4; i++)
#pragma unroll
                for (int j = 0; j < 4; j++)
                    MMA_TF32(acc[i][j], af[i], bf[j]);
        }
    }

    float* cp = ctxPart + ((long)(split * BHN + bh)) * MF * DHD;
#pragma unroll
    for (int i = 0; i < 4; i++) {
        const int m = warpM * 64 + i * 16 + gid;
#pragma unroll
        for (int j = 0; j < 4; j++) {
            const int d = warpN * 32 + j * 8 + tig * 2;
            *(float2*)(cp + (long)m * DHD + d) = make_float2(acc[i][j][0], acc[i][j][1]);
            *(float2*)(cp + (long)(m + 8) * DHD + d) = make_float2(acc[i][j][2], acc[i][j][3]);
        }
    }
    kcPart[((long)(split * BHN + bh)) * MF + t] = kcLoc;
}

// ---------------------------------------------------------------------------
// dashq_phi (R5, proven): dashQ GEMM + rowmax + phi + denominator.
// ---------------------------------------------------------------------------
#define DQ_P 68
__global__ __launch_bounds__(256) void dashq_phi(
    const float* __restrict__ Q, const float* __restrict__ proj,
    const float* __restrict__ kc, float* __restrict__ qp,
    float* __restrict__ denom)
{
    extern __shared__ float sm[];
    float* As = sm;                        // 128 * 68
    float* Bs = As + 128 * DQ_P;           // 256 * 68
    float* diag = Bs + 256 * DQ_P;         // 128
    float* kcS = diag + 128;               // 256
    float* redA = kcS + 256;               // 128 * 4
    float* redB = redA + 512;              // 128 * 4

    const int rt = blockIdx.x, bh = blockIdx.y;
    const int b = bh >> 3, h = bh & 7;
    const int n0 = rt * 128;
    const int t = threadIdx.x;
    const int lane = t & 31, warp = t >> 5;
    const int warpM = warp >> 2;          // 0..1
    const int warpN = warp & 3;           // 0..3
    const int gid = lane >> 2, tig = lane & 3;
    const unsigned asU = (unsigned)__cvta_generic_to_shared(As);
    const unsigned bsU = (unsigned)__cvta_generic_to_shared(Bs);
    const int ldsmRow = (lane & 7) + ((lane >> 3) & 1) * 8;
    const int ldsmK   = (lane >> 4) * 4;

#pragma unroll
    for (int i = 0; i < 8; i++) {
        int linear = i * 256 + t;
        int n = linear >> 4, c4 = linear & 15;
        float4 v = *(const float4*)(Q + ((long)(b * NQ + n0 + n)) * DMODEL + h * DHD + c4 * 4);
        v.x = f2tf32f(v.x); v.y = f2tf32f(v.y);
        v.z = f2tf32f(v.z); v.w = f2tf32f(v.w);
        *(float4*)(As + n * DQ_P + c4 * 4) = v;
    }
#pragma unroll
    for (int i = 0; i < 16; i++) {
        int linear = i * 256 + t;
        int r = linear >> 4, c4 = linear & 15;
        float4 v = *(const float4*)(proj + (long)r * DHD + c4 * 4);
        v.x = f2tf32f(v.x); v.y = f2tf32f(v.y);
        v.z = f2tf32f(v.z); v.w = f2tf32f(v.w);
        *(float4*)(Bs + r * DQ_P + c4 * 4) = v;
    }
    {
        int r = t >> 1, half = t & 1;
        const float* qr = Q + ((long)(b * NQ + n0 + r)) * DMODEL + h * DHD + half * 32;
        float ss = 0.f;
#pragma unroll
        for (int i = 0; i < 8; i++) {
            float4 v = *(const float4*)(qr + i * 4);
            ss += v.x * v.x + v.y * v.y + v.z * v.z + v.w * v.w;
        }
        ss += __shfl_xor_sync(0xffffffffu, ss, 1);
        if (half == 0) diag[r] = ss * 0.0625f;
    }
    kcS[t] = kc[bh * MF + t];
    __syncthreads();

    float acc[4][8][4];
#pragma unroll
    for (int i = 0; i < 4; i++)
#pragma unroll
        for (int j = 0; j < 8; j++)
#pragma unroll
            for (int r = 0; r < 4; r++) acc[i][j][r] = 0.f;

#pragma unroll
    for (int ks = 0; ks < 64; ks += 8) {
        uint32_t af[4][4], bf[8][2];
#pragma unroll
        for (int i = 0; i < 4; i++) {
            unsigned addr = asU + (unsigned)(((warpM * 64 + i * 16 + ldsmRow) * DQ_P
                                              + ks + ldsmK) * 4);
            LDSM4(af[i][0], af[i][1], af[i][2], af[i][3], addr);
        }
#pragma unroll
        for (int jj = 0; jj < 4; jj++) {
            unsigned addr = bsU + (unsigned)(((warpN * 64 + jj * 16 + ldsmRow) * DQ_P
                                              + ks + ldsmK) * 4);
            uint32_t r0, r1, r2, r3;
            LDSM4(r0, r1, r2, r3, addr);
            bf[jj * 2][0] = r0; bf[jj * 2 + 1][0] = r1;
            bf[jj * 2][1] = r2; bf[jj * 2 + 1][1] = r3;
        }
#pragma unroll
        for (int i = 0; i < 4; i++)
#pragma unroll
            for (int j = 0; j < 8; j++)
                MMA_TF32(acc[i][j], af[i], bf[j]);
    }

#pragma unroll
    for (int i = 0; i < 4; i++)
#pragma unroll
        for (int j = 0; j < 8; j++)
#pragma unroll
            for (int r = 0; r < 4; r++) acc[i][j][r] *= DN_SCALE;

#pragma unroll
    for (int i = 0; i < 4; i++) {
        const int rA = warpM * 64 + i * 16 + gid;
        float mA = -1e30f, mB = -1e30f;
#pragma unroll
        for (int j = 0; j < 8; j++) {
            mA = fmaxf(mA, fmaxf(acc[i][j][0], acc[i][j][1]));
            mB = fmaxf(mB, fmaxf(acc[i][j][2], acc[i][j][3]));
        }
        mA = fmaxf(mA, __shfl_xor_sync(0xffffffffu, mA, 1));
        mA = fmaxf(mA, __shfl_xor_sync(0xffffffffu, mA, 2));
        mB = fmaxf(mB, __shfl_xor_sync(0xffffffffu, mB, 1));
        mB = fmaxf(mB, __shfl_xor_sync(0xffffffffu, mB, 2));
        if (tig == 0) {
            redA[rA * 4 + warpN] = mA;
            redA[(rA + 8) * 4 + warpN] = mB;
        }
    }
    __syncthreads();

#pragma unroll
    for (int i = 0; i < 4; i++) {
        const int rA = warpM * 64 + i * 16 + gid;
        const int rB = rA + 8;
        const float rmA = fmaxf(fmaxf(redA[rA * 4], redA[rA * 4 + 1]),
                                fmaxf(redA[rA * 4 + 2], redA[rA * 4 + 3]));
        const float rmB = fmaxf(fmaxf(redA[rB * 4], redA[rB * 4 + 1]),
                                fmaxf(redA[rB * 4 + 2], redA[rB * 4 + 3]));
        const float shA = diag[rA] + rmA;
        const float shB = diag[rB] + rmB;
        float dA = 0.f, dB = 0.f;
#pragma unroll
        for (int j = 0; j < 8; j++) {
            const int col = warpN * 64 + (j >> 1) * 16 + (j & 1) * 8 + tig * 2;
            float p0 = RATIO * (__expf(acc[i][j][0] - shA) + EPSF);
            float p1 = RATIO * (__expf(acc[i][j][1] - shA) + EPSF);
            float p2 = RATIO * (__expf(acc[i][j][2] - shB) + EPSF);
            float p3 = RATIO * (__expf(acc[i][j][3] - shB) + EPSF);
            float2 kv = *(const float2*)(kcS + col);
            dA += p0 * kv.x + p1 * kv.y;
            dB += p2 * kv.x + p3 * kv.y;
            *(float2*)(qp + ((long)bh * NQ + n0 + rA) * MF + col) = make_float2(p0, p1);
            *(float2*)(qp + ((long)bh * NQ + n0 + rB) * MF + col) = make_float2(p2, p3);
        }
        dA += __shfl_xor_sync(0xffffffffu, dA, 1);
        dA += __shfl_xor_sync(0xffffffffu, dA, 2);
        dB += __shfl_xor_sync(0xffffffffu, dB, 1);
        dB += __shfl_xor_sync(0xffffffffu, dB, 2);
        if (tig == 0) {
            redB[rA * 4 + warpN] = dA;
            redB[rB * 4 + warpN] = dB;
        }
    }
    __syncthreads();
    if (warpN == 0 && tig == 0) {
#pragma unroll
        for (int i = 0; i < 4; i++) {
            const int rA = warpM * 64 + i * 16 + gid;
            const int rB = rA + 8;
            denom[(long)bh * NQ + n0 + rA] =
                (redB[rA * 4] + redB[rA * 4 + 1]) + (redB[rA * 4 + 2] + redB[rA * 4 + 3]);
            denom[(long)bh * NQ + n0 + rB] =
                (redB[rB * 4] + redB[rB * 4 + 1]) + (redB[rB * 4 + 2] + redB[rB * 4 + 3]);
        }
    }
}

// -------------------- small kernels ----------------------------------------
__global__ void transpose_proj(const float* __restrict__ proj, float* __restrict__ projT) {
    int i = blockIdx.x * 256 + threadIdx.x;
    int m = i >> 6, d = i & 63;
    projT[d * MF + m] = proj[i];
}

__global__ void init_stab(unsigned* __restrict__ s) {
    s[threadIdx.x] = 0u;
}

__global__ void kc_final8(const float* __restrict__ part, float* __restrict__ kc) {
    int bh = blockIdx.x, t = threadIdx.x;
    float s = 0.f;
#pragma unroll
    for (int sp = 0; sp < 8; sp++) s += part[((long)(sp * BHN + bh)) * MF + t];
    kc[bh * MF + t] = s;
}

__global__ void reduce_ctx8(const float* __restrict__ p, float* __restrict__ c) {
    int i = blockIdx.x * 256 + threadIdx.x;   // 1048576 total
    float s0 = p[i] + p[i + 1 * 1048576];
    float s1 = p[i + 2 * 1048576] + p[i + 3 * 1048576];
    float s2 = p[i + 4 * 1048576] + p[i + 5 * 1048576];
    float s3 = p[i + 6 * 1048576] + p[i + 7 * 1048576];
    c[i] = (s0 + s1) + (s2 + s3);
}

// ---------------------------------------------------------------------------
extern "C" void kernel_launch(void* const* d_in, const int* in_sizes, int n_in,
                              void* d_out, int out_size)
{
    (void)in_sizes; (void)n_in; (void)out_size;
    const float* x       = (const float*)d_in[0];
    const float* context = (const float*)d_in[1];
    const float* Wq      = (const float*)d_in[2];
    const float* Wk      = (const float*)d_in[3];
    const float* Wv      = (const float*)d_in[4];
    const float* Wo      = (const float*)d_in[5];
    const float* bo      = (const float*)d_in[6];
    const float* proj    = (const float*)d_in[7];
    float* out = (float*)d_out;

    float *Q, *K, *V, *projT, *qp, *kp, *kcPart, *kc, *denom;
    float *ctxPart, *ctx, *attn;
    unsigned* stabEnc;
    cudaGetSymbolAddress((void**)&Q, g_Q);
    cudaGetSymbolAddress((void**)&K, g_K);
    cudaGetSymbolAddress((void**)&V, g_V);
    cudaGetSymbolAddress((void**)&projT, g_projT);
    cudaGetSymbolAddress((void**)&qp, g_qp);
    cudaGetSymbolAddress((void**)&kp, g_kp);
    cudaGetSymbolAddress((void**)&stabEnc, g_stabEnc);
    cudaGetSymbolAddress((void**)&kcPart, g_kcPart);
    cudaGetSymbolAddress((void**)&kc, g_kc);
    cudaGetSymbolAddress((void**)&denom, g_denom);
    cudaGetSymbolAddress((void**)&ctxPart, g_ctxPart);
    cudaGetSymbolAddress((void**)&ctx, g_ctx);
    cudaGetSymbolAddress((void**)&attn, g_attn);

    const int SM_CTX = (64 * CF_AP + 64 * CF_BP + 64) * 4;                // 86272
    const int SM_DQ  = (128 * DQ_P + 256 * DQ_P + 128 + 256 + 1024) * 4;  // 110080
    const int SM_256 = (2 * 256 * 20 + 2 * 128 * 20) * 4;                 // 61440
    cudaFuncSetAttribute(ctx_fused, cudaFuncAttributeMaxDynamicSharedMemorySize, SM_CTX);
    cudaFuncSetAttribute(dashq_phi, cudaFuncAttributeMaxDynamicSharedMemorySize, SM_DQ);
    cudaFuncSetAttribute(tmma256, cudaFuncAttributeMaxDynamicSharedMemorySize, SM_256);

    transpose_proj<<<64, 256>>>(proj, projT);
    init_stab<<<1, BHN>>>(stabEnc);

    // Q/K/V projections (256x128 tiles)
    tmma256<<<dim3(4, 32, 1), 256, SM_256>>>(x, Wq, Q, nullptr, nullptr,
        DMODEL, DMODEL, DMODEL, DMODEL,
        1, 1, 0, 0, 0, 0, 0, 0, 0, 0, 0, 1.f);
    tmma256<<<dim3(4, 128, 1), 256, SM_256>>>(context, Wk, K, nullptr, nullptr,
        DMODEL, DMODEL, DMODEL, DMODEL,
        1, 1, 0, 0, 0, 0, 0, 0, 0, 0, 0, 1.f);
    tmma256<<<dim3(4, 128, 1), 256, SM_256>>>(context, Wv, V, nullptr, nullptr,
        DMODEL, DMODEL, DMODEL, DMODEL,
        1, 1, 0, 0, 0, 0, 0, 0, 0, 0, 0, 1.f);

    // dashK raw + fused global max (z = b*8 + h)
    tmma256<<<dim3(2, 16, BHN), 256, SM_256>>>(K, projT, kp, nullptr, stabEnc,
        DHD, DMODEL, MF, MF,
        8, 8,
        0, (long)NK * DMODEL, DHD,
        0, 0, 0,
        0, (long)NH * NK * MF, (long)NK * MF,
        DN_SCALE);

    // fused phi_k + kc partials + ctx accumulation
    ctx_fused<<<dim3(8, 64), 256, SM_CTX>>>(kp, K, V, stabEnc, ctxPart, kcPart);
    reduce_ctx8<<<4096, 256>>>(ctxPart, ctx);
    kc_final8<<<BHN, 256>>>(kcPart, kc);

    // fused dashQ + phi_q + denominator
    dashq_phi<<<dim3(8, 64), 256, SM_DQ>>>(Q, proj, kc, qp, denom);

    // attn = (qp @ ctx) / denom, merged-head layout (z = b*8 + h)
    tmma2<64, false><<<dim3(1, 8, BHN), 128>>>(qp, ctx, attn, nullptr, denom, nullptr,
        MF, MF, DHD, DMODEL,
        8, 8,
        0, (long)NH * NQ * MF, (long)NQ * MF,
        0, (long)NH * MF * DHD, (long)MF * DHD,
        0, (long)NQ * DMODEL, DHD,
        (long)NH * NQ, NQ, 1.f);

    // final projection + bias (256x128 tiles)
    tmma256<<<dim3(4, 32, 1), 256, SM_256>>>(attn, Wo, out, bo, nullptr,
        DMODEL, DMODEL, DMODEL, DMODEL,
        1, 1, 0, 0, 0, 0, 0, 0, 0, 0, 0, 1.f);
}

// round 9
// speedup vs baseline: 1.2520x; 1.2520x over previous
#include <cuda_runtime.h>
#include <math.h>
#include <stdint.h>

// ---------------------------------------------------------------------------
// Performer FAVOR+ cross-attention forward.
// B=8, Nq=1024, Nk=4096, D=512, H=8, DH=64, M=256
// Round 8: revert tmma256 (R7 regressed). Base = R5 (828us).
// New: eliminate kp (256MB write + 256MB read). dashk_max computes the key
// stabilizer with no dash store; ctx_fused2 recomputes dash in-SM, applies
// phi, accumulates kc, and runs the ctx MMA — all in one pass over K/V.
// ---------------------------------------------------------------------------

#define BATCH 8
#define NQ 1024
#define NK 4096
#define DMODEL 512
#define NH 8
#define DHD 64
#define MF 256
#define BHN 64          // BATCH * NH

#define DN_SCALE 0.35355339059327379f  // 64^-0.25
#define RATIO 0.0625f                  // 256^-0.5
#define EPSF 1e-4f

// -------------------- scratch (static device allocations) ------------------
__device__ float g_Q[BATCH * NQ * DMODEL];          // 16 MB
__device__ float g_K[BATCH * NK * DMODEL];          // 64 MB
__device__ float g_V[BATCH * NK * DMODEL];          // 64 MB
__device__ float g_qp[BHN * NQ * MF];               // phi(dashQ), 64 MB
__device__ unsigned g_stabEnc[BHN];
__device__ float g_kcPart[8 * BHN * MF];
__device__ float g_kc[BHN * MF];
__device__ float g_denom[BHN * NQ];
__device__ float g_ctxPart[8 * BHN * MF * DHD];     // 32 MB
__device__ float g_ctx[BHN * MF * DHD];             // 4 MB
__device__ float g_attn[BATCH * NQ * DMODEL];       // 16 MB

// -------------------- helpers ----------------------------------------------
__device__ __forceinline__ uint32_t f2tf32(float f) {
    uint32_t u;
    asm("cvt.rna.tf32.f32 %0, %1;" : "=r"(u) : "f"(f));
    return u;
}
__device__ __forceinline__ float f2tf32f(float f) {
    return __uint_as_float(f2tf32(f));
}

__device__ __forceinline__ unsigned encodeF(float f) {
    unsigned u = __float_as_uint(f);
    return (u & 0x80000000u) ? ~u : (u | 0x80000000u);
}
__device__ __forceinline__ float decodeF(unsigned e) {
    unsigned u = (e & 0x80000000u) ? (e ^ 0x80000000u) : ~e;
    return __uint_as_float(u);
}

#define MMA_TF32(d, a, b)                                               \
    asm volatile(                                                       \
        "mma.sync.aligned.m16n8k8.row.col.f32.tf32.tf32.f32 "           \
        "{%0,%1,%2,%3}, {%4,%5,%6,%7}, {%8,%9}, {%0,%1,%2,%3};\n"       \
        : "+f"(d[0]), "+f"(d[1]), "+f"(d[2]), "+f"(d[3])                \
        : "r"(a[0]), "r"(a[1]), "r"(a[2]), "r"(a[3]),                   \
          "r"(b[0]), "r"(b[1]))

#define LDSM4(r0, r1, r2, r3, addr)                                     \
    asm volatile(                                                       \
        "ldmatrix.sync.aligned.m8n8.x4.shared.b16 {%0,%1,%2,%3}, [%4];" \
        : "=r"(r0), "=r"(r1), "=r"(r2), "=r"(r3) : "r"(addr))

__device__ __forceinline__ float warpRedMax(float v) {
#pragma unroll
    for (int o = 16; o > 0; o >>= 1) v = fmaxf(v, __shfl_xor_sync(0xffffffffu, v, o));
    return v;
}

// ---------------------------------------------------------------------------
// tmma2 (R3/R5, proven): TF32 GEMM, block 128 x BN x 16, 128 threads, 4 warps.
// ---------------------------------------------------------------------------
template <int BN, bool TRANSA>
__global__ __launch_bounds__(128, 2) void tmma2(
    const float* __restrict__ A, const float* __restrict__ B,
    float* __restrict__ C, const float* __restrict__ bias,
    const float* __restrict__ rowdiv, unsigned* __restrict__ maxOut,
    int K, int lda, int ldb, int ldc,
    int d2, int d3,
    long oA1, long oA2, long oA3,
    long oB1, long oB2, long oB3,
    long oC1, long oC2, long oC3,
    long oD2, long oD3,
    float alpha)
{
    constexpr int WN = BN / 2;
    constexpr int NJ = WN / 8;
    constexpr int NJJ = WN / 16;

    {
        int z = blockIdx.z;
        int z3 = z % d3;
        int zq = z / d3;
        int z2 = zq % d2;
        int z1 = zq / d2;
        A += z1 * oA1 + z2 * oA2 + z3 * oA3;
        B += z1 * oB1 + z2 * oB2 + z3 * oB3;
        C += z1 * oC1 + z2 * oC2 + z3 * oC3;
        if (rowdiv) rowdiv += z2 * oD2 + z3 * oD3;
    }

    __shared__ uint32_t As[2][128][20];
    __shared__ uint32_t Bs[2][BN][20];
    __shared__ float redMax[4];

    const int tid = threadIdx.x;
    const int lane = tid & 31;
    const int warp = tid >> 5;
    const int warpM = warp >> 1;
    const int warpN = warp & 1;
    const int gid = lane >> 2;
    const int tig = lane & 3;

    const int m0 = blockIdx.y * 128;
    const int n0 = blockIdx.x * BN;

    const unsigned asU = (unsigned)__cvta_generic_to_shared(&As[0][0][0]);
    const unsigned bsU = (unsigned)__cvta_generic_to_shared(&Bs[0][0][0]);
    const int ldsmRow = (lane & 7) + ((lane >> 3) & 1) * 8;
    const int ldsmK   = (lane >> 4) * 4;

    float acc[4][NJ][4];
#pragma unroll
    for (int i = 0; i < 4; i++)
#pragma unroll
        for (int j = 0; j < NJ; j++)
#pragma unroll
            for (int r = 0; r < 4; r++) acc[i][j][r] = 0.f;

    const int ntiles = K >> 4;
    float pa[16], pb[16];

    auto loadTile = [&](int k0) {
        if (!TRANSA) {
            const float* Ap = A + (long)(m0 + tid) * lda + k0;
            *(float4*)(pa + 0)  = *(const float4*)(Ap + 0);
            *(float4*)(pa + 4)  = *(const float4*)(Ap + 4);
            *(float4*)(pa + 8)  = *(const float4*)(Ap + 8);
            *(float4*)(pa + 12) = *(const float4*)(Ap + 12);
        } else {
            const float* Ap = A + (long)k0 * lda + m0 + tid;
#pragma unroll
            for (int k = 0; k < 16; k++) pa[k] = Ap[(long)k * lda];
        }
        if (BN == 128) {
            const float* Bp = B + (long)k0 * ldb + n0 + tid;
#pragma unroll
            for (int k = 0; k < 16; k++) pb[k] = Bp[(long)k * ldb];
        } else {
            const float* Bp = B + (long)(k0 + (tid >> 6) * 8) * ldb + n0 + (tid & 63);
#pragma unroll
            for (int k = 0; k < 8; k++) pb[k] = Bp[(long)k * ldb];
        }
    };

    auto storeTile = [&](int buf) {
#pragma unroll
        for (int g = 0; g < 4; g++) {
            uint4 u;
            u.x = f2tf32(pa[g * 4 + 0]); u.y = f2tf32(pa[g * 4 + 1]);
            u.z = f2tf32(pa[g * 4 + 2]); u.w = f2tf32(pa[g * 4 + 3]);
            *(uint4*)&As[buf][tid][g * 4] = u;
        }
        if (BN == 128) {
#pragma unroll
            for (int g = 0; g < 4; g++) {
                uint4 u;
                u.x = f2tf32(pb[g * 4 + 0]); u.y = f2tf32(pb[g * 4 + 1]);
                u.z = f2tf32(pb[g * 4 + 2]); u.w = f2tf32(pb[g * 4 + 3]);
                *(uint4*)&Bs[buf][tid][g * 4] = u;
            }
        } else {
            const int n = tid & 63, kg = (tid >> 6) * 8;
#pragma unroll
            for (int g = 0; g < 2; g++) {
                uint4 u;
                u.x = f2tf32(pb[g * 4 + 0]); u.y = f2tf32(pb[g * 4 + 1]);
                u.z = f2tf32(pb[g * 4 + 2]); u.w = f2tf32(pb[g * 4 + 3]);
                *(uint4*)&Bs[buf][n][kg + g * 4] = u;
            }
        }
    };

    auto computeTile = [&](int buf) {
#pragma unroll
        for (int ks = 0; ks < 16; ks += 8) {
            uint32_t af[4][4];
            uint32_t bf[NJ][2];
#pragma unroll
            for (int i = 0; i < 4; i++) {
                unsigned addr = asU + (unsigned)((buf * 128 * 20 +
                    (warpM * 64 + i * 16 + ldsmRow) * 20 + ks + ldsmK) * 4);
                LDSM4(af[i][0], af[i][1], af[i][2], af[i][3], addr);
            }
#pragma unroll
            for (int jj = 0; jj < NJJ; jj++) {
                unsigned addr = bsU + (unsigned)((buf * BN * 20 +
                    (warpN * WN + jj * 16 + ldsmRow) * 20 + ks + ldsmK) * 4);
                uint32_t r0, r1, r2, r3;
                LDSM4(r0, r1, r2, r3, addr);
                bf[jj * 2][0] = r0; bf[jj * 2 + 1][0] = r1;
                bf[jj * 2][1] = r2; bf[jj * 2 + 1][1] = r3;
            }
#pragma unroll
            for (int i = 0; i < 4; i++)
#pragma unroll
                for (int j = 0; j < NJ; j++)
                    MMA_TF32(acc[i][j], af[i], bf[j]);
        }
    };

    loadTile(0);
    storeTile(0);
    __syncthreads();
    for (int kt = 0; kt < ntiles; kt++) {
        const int buf = kt & 1;
        const bool more = (kt + 1) < ntiles;
        if (more) loadTile((kt + 1) << 4);
        computeTile(buf);
        if (more) storeTile(buf ^ 1);
        __syncthreads();
    }

    float vmax = -1e30f;
#pragma unroll
    for (int i = 0; i < 4; i++) {
        const int rL = m0 + warpM * 64 + i * 16 + gid;
        float dv0 = 1.f, dv1 = 1.f;
        if (rowdiv) { dv0 = 1.0f / rowdiv[rL]; dv1 = 1.0f / rowdiv[rL + 8]; }
#pragma unroll
        for (int j = 0; j < NJ; j++) {
            const int col = n0 + warpN * WN + (j >> 1) * 16 + (j & 1) * 8 + tig * 2;
            float v0 = alpha * acc[i][j][0], v1 = alpha * acc[i][j][1];
            float v2 = alpha * acc[i][j][2], v3 = alpha * acc[i][j][3];
            if (maxOut)
                vmax = fmaxf(vmax, fmaxf(fmaxf(v0, v1), fmaxf(v2, v3)));
            if (bias) {
                float2 bv = *(const float2*)(bias + col);
                v0 += bv.x; v1 += bv.y; v2 += bv.x; v3 += bv.y;
            }
            v0 *= dv0; v1 *= dv0; v2 *= dv1; v3 *= dv1;
            *(float2*)(C + (long)rL * ldc + col) = make_float2(v0, v1);
            *(float2*)(C + (long)(rL + 8) * ldc + col) = make_float2(v2, v3);
        }
    }

    if (maxOut) {
        vmax = warpRedMax(vmax);
        if (lane == 0) redMax[warp] = vmax;
        __syncthreads();
        if (tid == 0) {
            float m = fmaxf(fmaxf(redMax[0], redMax[1]), fmaxf(redMax[2], redMax[3]));
            atomicMax(maxOut + blockIdx.z, encodeF(m));
        }
    }
}

// ---------------------------------------------------------------------------
// dashk_max: per (rowtile, bh): dash 128x256 GEMM (K=64) entirely in
// registers; reduce to global per-(b,h) max via encoded atomicMax. No store.
// Same MMA chain as ctx_fused2's dash -> bitwise-identical values.
// 256 threads, 8 warps: warpM 0..1 (64 rows), warpN 0..3 (64 cols).
// ---------------------------------------------------------------------------
#define DQ_P 68
__global__ __launch_bounds__(256) void dashk_max(
    const float* __restrict__ Km, const float* __restrict__ proj,
    unsigned* __restrict__ stabEnc)
{
    extern __shared__ float sm[];
    float* As = sm;                        // 128 * 68
    float* Bs = As + 128 * DQ_P;           // 256 * 68
    __shared__ float red[8];

    const int rt = blockIdx.x, bh = blockIdx.y;
    const int b = bh >> 3, h = bh & 7;
    const int s0 = rt * 128;
    const int t = threadIdx.x;
    const int lane = t & 31, warp = t >> 5;
    const int warpM = warp >> 2;          // 0..1
    const int warpN = warp & 3;           // 0..3
    const unsigned asU = (unsigned)__cvta_generic_to_shared(As);
    const unsigned bsU = (unsigned)__cvta_generic_to_shared(Bs);
    const int ldsmRow = (lane & 7) + ((lane >> 3) & 1) * 8;
    const int ldsmK   = (lane >> 4) * 4;

    // stage A = K rows [128][64] (tf32-rounded)
#pragma unroll
    for (int i = 0; i < 8; i++) {
        int linear = i * 256 + t;
        int n = linear >> 4, c4 = linear & 15;
        float4 v = *(const float4*)(Km + ((long)(b * NK + s0 + n)) * DMODEL + h * DHD + c4 * 4);
        v.x = f2tf32f(v.x); v.y = f2tf32f(v.y);
        v.z = f2tf32f(v.z); v.w = f2tf32f(v.w);
        *(float4*)(As + n * DQ_P + c4 * 4) = v;
    }
    // stage B = proj [256][64] n-major (tf32-rounded)
#pragma unroll
    for (int i = 0; i < 16; i++) {
        int linear = i * 256 + t;
        int r = linear >> 4, c4 = linear & 15;
        float4 v = *(const float4*)(proj + (long)r * DHD + c4 * 4);
        v.x = f2tf32f(v.x); v.y = f2tf32f(v.y);
        v.z = f2tf32f(v.z); v.w = f2tf32f(v.w);
        *(float4*)(Bs + r * DQ_P + c4 * 4) = v;
    }
    __syncthreads();

    float acc[4][8][4];
#pragma unroll
    for (int i = 0; i < 4; i++)
#pragma unroll
        for (int j = 0; j < 8; j++)
#pragma unroll
            for (int r = 0; r < 4; r++) acc[i][j][r] = 0.f;

#pragma unroll
    for (int ks = 0; ks < 64; ks += 8) {
        uint32_t af[4][4], bf[8][2];
#pragma unroll
        for (int i = 0; i < 4; i++) {
            unsigned addr = asU + (unsigned)(((warpM * 64 + i * 16 + ldsmRow) * DQ_P
                                              + ks + ldsmK) * 4);
            LDSM4(af[i][0], af[i][1], af[i][2], af[i][3], addr);
        }
#pragma unroll
        for (int jj = 0; jj < 4; jj++) {
            unsigned addr = bsU + (unsigned)(((warpN * 64 + jj * 16 + ldsmRow) * DQ_P
                                              + ks + ldsmK) * 4);
            uint32_t r0, r1, r2, r3;
            LDSM4(r0, r1, r2, r3, addr);
            bf[jj * 2][0] = r0; bf[jj * 2 + 1][0] = r1;
            bf[jj * 2][1] = r2; bf[jj * 2 + 1][1] = r3;
        }
#pragma unroll
        for (int i = 0; i < 4; i++)
#pragma unroll
            for (int j = 0; j < 8; j++)
                MMA_TF32(acc[i][j], af[i], bf[j]);
    }

    float vmax = -1e30f;
#pragma unroll
    for (int i = 0; i < 4; i++)
#pragma unroll
        for (int j = 0; j < 8; j++)
#pragma unroll
            for (int r = 0; r < 4; r++) vmax = fmaxf(vmax, acc[i][j][r]);
    vmax *= DN_SCALE;
    vmax = warpRedMax(vmax);
    if (lane == 0) red[warp] = vmax;
    __syncthreads();
    if (t == 0) {
        float m = red[0];
#pragma unroll
        for (int i = 1; i < 8; i++) m = fmaxf(m, red[i]);
        atomicMax(stabEnc + bh, encodeF(m));
    }
}

// ---------------------------------------------------------------------------
// ctx_fused2: per (split, bh), loop 8 chunks of 64 keys:
//   stage K chunk (rounded) + diag (unrounded) + V chunk;
//   recompute dash = K_chunk @ proj^T via MMA (K=64);
//   phi in registers (kc partials per-lane); store phi tile to smem;
//   ctx MMA phi^T @ V (scalar-frag path from R5's ctx_fused).
// 256 threads. Dash phase: warp w owns 32 m-cols. Ctx phase: 4Mx2N warps.
// ---------------------------------------------------------------------------
#define C2_FP 264
#define C2_VP 72
__global__ __launch_bounds__(256) void ctx_fused2(
    const float* __restrict__ Km, const float* __restrict__ V,
    const float* __restrict__ proj, const unsigned* __restrict__ stabEnc,
    float* __restrict__ ctxPart, float* __restrict__ kcPart)
{
    extern __shared__ float sm[];
    float* Bp = sm;                        // proj [256][68]
    float* Ak = Bp + 256 * DQ_P;           // K chunk [64][68]
    float* Ph = Ak + 64 * DQ_P;            // phi [64][264]
    float* Bv = Ph + 64 * C2_FP;           // V chunk [64][72]
    float* diag = Bv + 64 * C2_VP;         // [64]
    const uint32_t* PhU = (const uint32_t*)Ph;
    const uint32_t* BvU = (const uint32_t*)Bv;

    const int split = blockIdx.x, bh = blockIdx.y;
    const int b = bh >> 3, h = bh & 7;
    const int t = threadIdx.x;
    const int lane = t & 31, warp = t >> 5;
    const int gid = lane >> 2, tig = lane & 3;
    const unsigned bpU = (unsigned)__cvta_generic_to_shared(Bp);
    const unsigned akU = (unsigned)__cvta_generic_to_shared(Ak);
    const int ldsmRow = (lane & 7) + ((lane >> 3) & 1) * 8;
    const int ldsmK   = (lane >> 4) * 4;
    const float stab = decodeF(stabEnc[bh]);
    const int sBase = split * 512;

    // ctx-phase warp roles
    const int warpM = warp >> 1;          // 0..3
    const int warpN = warp & 1;           // 0..1

    // stage proj once [256][64] (tf32-rounded)
#pragma unroll
    for (int i = 0; i < 16; i++) {
        int linear = i * 256 + t;
        int r = linear >> 4, c4 = linear & 15;
        float4 v = *(const float4*)(proj + (long)r * DHD + c4 * 4);
        v.x = f2tf32f(v.x); v.y = f2tf32f(v.y);
        v.z = f2tf32f(v.z); v.w = f2tf32f(v.w);
        *(float4*)(Bp + r * DQ_P + c4 * 4) = v;
    }

    float ctxAcc[4][4][4];
#pragma unroll
    for (int i = 0; i < 4; i++)
#pragma unroll
        for (int j = 0; j < 4; j++)
#pragma unroll
            for (int r = 0; r < 4; r++) ctxAcc[i][j][r] = 0.f;
    float kcAcc[4][2];
#pragma unroll
    for (int j = 0; j < 4; j++) { kcAcc[j][0] = 0.f; kcAcc[j][1] = 0.f; }

    for (int chunk = 0; chunk < 8; chunk++) {
        const int s0 = sBase + chunk * 64;
        __syncthreads();   // prior ctx MMA / dash MMA done before restaging

        // K chunk: rounded into Ak, unrounded squares -> diag
        {
            const int r = t >> 2, p = t & 3;
            const float* kr = Km + ((long)(b * NK + s0 + r)) * DMODEL + h * DHD + p * 16;
            float ss = 0.f;
#pragma unroll
            for (int i = 0; i < 4; i++) {
                float4 v = *(const float4*)(kr + i * 4);
                ss += v.x * v.x + v.y * v.y + v.z * v.z + v.w * v.w;
                v.x = f2tf32f(v.x); v.y = f2tf32f(v.y);
                v.z = f2tf32f(v.z); v.w = f2tf32f(v.w);
                *(float4*)(Ak + r * DQ_P + p * 16 + i * 4) = v;
            }
            ss += __shfl_xor_sync(0xffffffffu, ss, 1);
            ss += __shfl_xor_sync(0xffffffffu, ss, 2);
            if (p == 0) diag[r] = ss * 0.0625f;
        }
        // V chunk (rounded)
        {
            const float* vsrc = V + ((long)(b * NK + s0)) * DMODEL + h * DHD;
#pragma unroll
            for (int i = 0; i < 4; i++) {
                int linear = i * 256 + t;
                int s = linear >> 4, c4 = linear & 15;
                float4 v = *(const float4*)(vsrc + (long)s * DMODEL + c4 * 4);
                v.x = f2tf32f(v.x); v.y = f2tf32f(v.y);
                v.z = f2tf32f(v.z); v.w = f2tf32f(v.w);
                *(float4*)(Bv + s * C2_VP + c4 * 4) = v;
            }
        }
        __syncthreads();

        // dash MMA: rows = 64 keys, cols = warp's 32 features, K=64
        float dacc[4][4][4];
#pragma unroll
        for (int i = 0; i < 4; i++)
#pragma unroll
            for (int j = 0; j < 4; j++)
#pragma unroll
                for (int r = 0; r < 4; r++) dacc[i][j][r] = 0.f;

#pragma unroll
        for (int ks = 0; ks < 64; ks += 8) {
            uint32_t af[4][4], bf[4][2];
#pragma unroll
            for (int i = 0; i < 4; i++) {
                unsigned addr = akU + (unsigned)(((i * 16 + ldsmRow) * DQ_P
                                                  + ks + ldsmK) * 4);
                LDSM4(af[i][0], af[i][1], af[i][2], af[i][3], addr);
            }
#pragma unroll
            for (int jj = 0; jj < 2; jj++) {
                unsigned addr = bpU + (unsigned)(((warp * 32 + jj * 16 + ldsmRow) * DQ_P
                                                  + ks + ldsmK) * 4);
                uint32_t r0, r1, r2, r3;
                LDSM4(r0, r1, r2, r3, addr);
                bf[jj * 2][0] = r0; bf[jj * 2 + 1][0] = r1;
                bf[jj * 2][1] = r2; bf[jj * 2 + 1][1] = r3;
            }
#pragma unroll
            for (int i = 0; i < 4; i++)
#pragma unroll
                for (int j = 0; j < 4; j++)
                    MMA_TF32(dacc[i][j], af[i], bf[j]);
        }

        // phi + kc + store phi tile
#pragma unroll
        for (int i = 0; i < 4; i++) {
            const int rA = i * 16 + gid;
            const int rB = rA + 8;
            const float shA = diag[rA] + stab;
            const float shB = diag[rB] + stab;
#pragma unroll
            for (int j = 0; j < 4; j++) {
                const int col = warp * 32 + j * 8 + tig * 2;
                float p0 = RATIO * (__expf(dacc[i][j][0] * DN_SCALE - shA) + EPSF);
                float p1 = RATIO * (__expf(dacc[i][j][1] * DN_SCALE - shA) + EPSF);
                float p2 = RATIO * (__expf(dacc[i][j][2] * DN_SCALE - shB) + EPSF);
                float p3 = RATIO * (__expf(dacc[i][j][3] * DN_SCALE - shB) + EPSF);
                kcAcc[j][0] += p0 + p2;
                kcAcc[j][1] += p1 + p3;
                *(float2*)(Ph + rA * C2_FP + col) = make_float2(f2tf32f(p0), f2tf32f(p1));
                *(float2*)(Ph + rB * C2_FP + col) = make_float2(f2tf32f(p2), f2tf32f(p3));
            }
        }
        __syncthreads();

        // ctx MMA: C[m][d] += sum_s phi[s][m] * V[s][d]  (scalar frags)
#pragma unroll
        for (int ks = 0; ks < 64; ks += 8) {
            uint32_t af[4][4], bf[4][2];
#pragma unroll
            for (int i = 0; i < 4; i++) {
                const int mB = warpM * 64 + i * 16;
                af[i][0] = PhU[(ks + tig) * C2_FP + mB + gid];
                af[i][1] = PhU[(ks + tig) * C2_FP + mB + gid + 8];
                af[i][2] = PhU[(ks + tig + 4) * C2_FP + mB + gid];
                af[i][3] = PhU[(ks + tig + 4) * C2_FP + mB + gid + 8];
            }
#pragma unroll
            for (int j = 0; j < 4; j++) {
                const int nB = warpN * 32 + j * 8;
                bf[j][0] = BvU[(ks + tig) * C2_VP + nB + gid];
                bf[j][1] = BvU[(ks + tig + 4) * C2_VP + nB + gid];
            }
#pragma unroll
            for (int i = 0; i < 4; i++)
#pragma unroll
                for (int j = 0; j < 4; j++)
                    MMA_TF32(ctxAcc[i][j], af[i], bf[j]);
        }
    }

    // epilogue: ctxPart + kcPart
    float* cp = ctxPart + ((long)(split * BHN + bh)) * MF * DHD;
#pragma unroll
    for (int i = 0; i < 4; i++) {
        const int m = warpM * 64 + i * 16 + gid;
#pragma unroll
        for (int j = 0; j < 4; j++) {
            const int d = warpN * 32 + j * 8 + tig * 2;
            *(float2*)(cp + (long)m * DHD + d) = make_float2(ctxAcc[i][j][0], ctxAcc[i][j][1]);
            *(float2*)(cp + (long)(m + 8) * DHD + d) = make_float2(ctxAcc[i][j][2], ctxAcc[i][j][3]);
        }
    }
    // kc: reduce over gid (rows) -> lane gid==0 owns column (j, tig, parity)
#pragma unroll
    for (int j = 0; j < 4; j++) {
#pragma unroll
        for (int p = 0; p < 2; p++) {
            float v = kcAcc[j][p];
            v += __shfl_xor_sync(0xffffffffu, v, 4);
            v += __shfl_xor_sync(0xffffffffu, v, 8);
            v += __shfl_xor_sync(0xffffffffu, v, 16);
            if (gid == 0) {
                const int col = warp * 32 + j * 8 + tig * 2 + p;
                kcPart[((long)(split * BHN + bh)) * MF + col] = v;
            }
        }
    }
}

// ---------------------------------------------------------------------------
// dashq_phi (R5, proven): dashQ GEMM + rowmax + phi + denominator.
// ---------------------------------------------------------------------------
__global__ __launch_bounds__(256) void dashq_phi(
    const float* __restrict__ Q, const float* __restrict__ proj,
    const float* __restrict__ kc, float* __restrict__ qp,
    float* __restrict__ denom)
{
    extern __shared__ float sm[];
    float* As = sm;                        // 128 * 68
    float* Bs = As + 128 * DQ_P;           // 256 * 68
    float* diag = Bs + 256 * DQ_P;         // 128
    float* kcS = diag + 128;               // 256
    float* redA = kcS + 256;               // 128 * 4
    float* redB = redA + 512;              // 128 * 4

    const int rt = blockIdx.x, bh = blockIdx.y;
    const int b = bh >> 3, h = bh & 7;
    const int n0 = rt * 128;
    const int t = threadIdx.x;
    const int lane = t & 31, warp = t >> 5;
    const int warpM = warp >> 2;          // 0..1
    const int warpN = warp & 3;           // 0..3
    const int gid = lane >> 2, tig = lane & 3;
    const unsigned asU = (unsigned)__cvta_generic_to_shared(As);
    const unsigned bsU = (unsigned)__cvta_generic_to_shared(Bs);
    const int ldsmRow = (lane & 7) + ((lane >> 3) & 1) * 8;
    const int ldsmK   = (lane >> 4) * 4;

#pragma unroll
    for (int i = 0; i < 8; i++) {
        int linear = i * 256 + t;
        int n = linear >> 4, c4 = linear & 15;
        float4 v = *(const float4*)(Q + ((long)(b * NQ + n0 + n)) * DMODEL + h * DHD + c4 * 4);
        v.x = f2tf32f(v.x); v.y = f2tf32f(v.y);
        v.z = f2tf32f(v.z); v.w = f2tf32f(v.w);
        *(float4*)(As + n * DQ_P + c4 * 4) = v;
    }
#pragma unroll
    for (int i = 0; i < 16; i++) {
        int linear = i * 256 + t;
        int r = linear >> 4, c4 = linear & 15;
        float4 v = *(const float4*)(proj + (long)r * DHD + c4 * 4);
        v.x = f2tf32f(v.x); v.y = f2tf32f(v.y);
        v.z = f2tf32f(v.z); v.w = f2tf32f(v.w);
        *(float4*)(Bs + r * DQ_P + c4 * 4) = v;
    }
    {
        int r = t >> 1, half = t & 1;
        const float* qr = Q + ((long)(b * NQ + n0 + r)) * DMODEL + h * DHD + half * 32;
        float ss = 0.f;
#pragma unroll
        for (int i = 0; i < 8; i++) {
            float4 v = *(const float4*)(qr + i * 4);
            ss += v.x * v.x + v.y * v.y + v.z * v.z + v.w * v.w;
        }
        ss += __shfl_xor_sync(0xffffffffu, ss, 1);
        if (half == 0) diag[r] = ss * 0.0625f;
    }
    kcS[t] = kc[bh * MF + t];
    __syncthreads();

    float acc[4][8][4];
#pragma unroll
    for (int i = 0; i < 4; i++)
#pragma unroll
        for (int j = 0; j < 8; j++)
#pragma unroll
            for (int r = 0; r < 4; r++) acc[i][j][r] = 0.f;

#pragma unroll
    for (int ks = 0; ks < 64; ks += 8) {
        uint32_t af[4][4], bf[8][2];
#pragma unroll
        for (int i = 0; i < 4; i++) {
            unsigned addr = asU + (unsigned)(((warpM * 64 + i * 16 + ldsmRow) * DQ_P
                                              + ks + ldsmK) * 4);
            LDSM4(af[i][0], af[i][1], af[i][2], af[i][3], addr);
        }
#pragma unroll
        for (int jj = 0; jj < 4; jj++) {
            unsigned addr = bsU + (unsigned)(((warpN * 64 + jj * 16 + ldsmRow) * DQ_P
                                              + ks + ldsmK) * 4);
            uint32_t r0, r1, r2, r3;
            LDSM4(r0, r1, r2, r3, addr);
            bf[jj * 2][0] = r0; bf[jj * 2 + 1][0] = r1;
            bf[jj * 2][1] = r2; bf[jj * 2 + 1][1] = r3;
        }
#pragma unroll
        for (int i = 0; i < 4; i++)
#pragma unroll
            for (int j = 0; j < 8; j++)
                MMA_TF32(acc[i][j], af[i], bf[j]);
    }

#pragma unroll
    for (int i = 0; i < 4; i++)
#pragma unroll
        for (int j = 0; j < 8; j++)
#pragma unroll
            for (int r = 0; r < 4; r++) acc[i][j][r] *= DN_SCALE;

#pragma unroll
    for (int i = 0; i < 4; i++) {
        const int rA = warpM * 64 + i * 16 + gid;
        float mA = -1e30f, mB = -1e30f;
#pragma unroll
        for (int j = 0; j < 8; j++) {
            mA = fmaxf(mA, fmaxf(acc[i][j][0], acc[i][j][1]));
            mB = fmaxf(mB, fmaxf(acc[i][j][2], acc[i][j][3]));
        }
        mA = fmaxf(mA, __shfl_xor_sync(0xffffffffu, mA, 1));
        mA = fmaxf(mA, __shfl_xor_sync(0xffffffffu, mA, 2));
        mB = fmaxf(mB, __shfl_xor_sync(0xffffffffu, mB, 1));
        mB = fmaxf(mB, __shfl_xor_sync(0xffffffffu, mB, 2));
        if (tig == 0) {
            redA[rA * 4 + warpN] = mA;
            redA[(rA + 8) * 4 + warpN] = mB;
        }
    }
    __syncthreads();

#pragma unroll
    for (int i = 0; i < 4; i++) {
        const int rA = warpM * 64 + i * 16 + gid;
        const int rB = rA + 8;
        const float rmA = fmaxf(fmaxf(redA[rA * 4], redA[rA * 4 + 1]),
                                fmaxf(redA[rA * 4 + 2], redA[rA * 4 + 3]));
        const float rmB = fmaxf(fmaxf(redA[rB * 4], redA[rB * 4 + 1]),
                                fmaxf(redA[rB * 4 + 2], redA[rB * 4 + 3]));
        const float shA = diag[rA] + rmA;
        const float shB = diag[rB] + rmB;
        float dA = 0.f, dB = 0.f;
#pragma unroll
        for (int j = 0; j < 8; j++) {
            const int col = warpN * 64 + (j >> 1) * 16 + (j & 1) * 8 + tig * 2;
            float p0 = RATIO * (__expf(acc[i][j][0] - shA) + EPSF);
            float p1 = RATIO * (__expf(acc[i][j][1] - shA) + EPSF);
            float p2 = RATIO * (__expf(acc[i][j][2] - shB) + EPSF);
            float p3 = RATIO * (__expf(acc[i][j][3] - shB) + EPSF);
            float2 kv = *(const float2*)(kcS + col);
            dA += p0 * kv.x + p1 * kv.y;
            dB += p2 * kv.x + p3 * kv.y;
            *(float2*)(qp + ((long)bh * NQ + n0 + rA) * MF + col) = make_float2(p0, p1);
            *(float2*)(qp + ((long)bh * NQ + n0 + rB) * MF + col) = make_float2(p2, p3);
        }
        dA += __shfl_xor_sync(0xffffffffu, dA, 1);
        dA += __shfl_xor_sync(0xffffffffu, dA, 2);
        dB += __shfl_xor_sync(0xffffffffu, dB, 1);
        dB += __shfl_xor_sync(0xffffffffu, dB, 2);
        if (tig == 0) {
            redB[rA * 4 + warpN] = dA;
            redB[rB * 4 + warpN] = dB;
        }
    }
    __syncthreads();
    if (warpN == 0 && tig == 0) {
#pragma unroll
        for (int i = 0; i < 4; i++) {
            const int rA = warpM * 64 + i * 16 + gid;
            const int rB = rA + 8;
            denom[(long)bh * NQ + n0 + rA] =
                (redB[rA * 4] + redB[rA * 4 + 1]) + (redB[rA * 4 + 2] + redB[rA * 4 + 3]);
            denom[(long)bh * NQ + n0 + rB] =
                (redB[rB * 4] + redB[rB * 4 + 1]) + (redB[rB * 4 + 2] + redB[rB * 4 + 3]);
        }
    }
}

// -------------------- small kernels ----------------------------------------
__global__ void init_stab(unsigned* __restrict__ s) {
    s[threadIdx.x] = 0u;
}

__global__ void kc_final8(const float* __restrict__ part, float* __restrict__ kc) {
    int bh = blockIdx.x, t = threadIdx.x;
    float s = 0.f;
#pragma unroll
    for (int sp = 0; sp < 8; sp++) s += part[((long)(sp * BHN + bh)) * MF + t];
    kc[bh * MF + t] = s;
}

__global__ void reduce_ctx8(const float* __restrict__ p, float* __restrict__ c) {
    int i = blockIdx.x * 256 + threadIdx.x;   // 1048576 total
    float s0 = p[i] + p[i + 1 * 1048576];
    float s1 = p[i + 2 * 1048576] + p[i + 3 * 1048576];
    float s2 = p[i + 4 * 1048576] + p[i + 5 * 1048576];
    float s3 = p[i + 6 * 1048576] + p[i + 7 * 1048576];
    c[i] = (s0 + s1) + (s2 + s3);
}

// ---------------------------------------------------------------------------
extern "C" void kernel_launch(void* const* d_in, const int* in_sizes, int n_in,
                              void* d_out, int out_size)
{
    (void)in_sizes; (void)n_in; (void)out_size;
    const float* x       = (const float*)d_in[0];
    const float* context = (const float*)d_in[1];
    const float* Wq      = (const float*)d_in[2];
    const float* Wk      = (const float*)d_in[3];
    const float* Wv      = (const float*)d_in[4];
    const float* Wo      = (const float*)d_in[5];
    const float* bo      = (const float*)d_in[6];
    const float* proj    = (const float*)d_in[7];
    float* out = (float*)d_out;

    float *Q, *K, *V, *qp, *kcPart, *kc, *denom;
    float *ctxPart, *ctx, *attn;
    unsigned* stabEnc;
    cudaGetSymbolAddress((void**)&Q, g_Q);
    cudaGetSymbolAddress((void**)&K, g_K);
    cudaGetSymbolAddress((void**)&V, g_V);
    cudaGetSymbolAddress((void**)&qp, g_qp);
    cudaGetSymbolAddress((void**)&stabEnc, g_stabEnc);
    cudaGetSymbolAddress((void**)&kcPart, g_kcPart);
    cudaGetSymbolAddress((void**)&kc, g_kc);
    cudaGetSymbolAddress((void**)&denom, g_denom);
    cudaGetSymbolAddress((void**)&ctxPart, g_ctxPart);
    cudaGetSymbolAddress((void**)&ctx, g_ctx);
    cudaGetSymbolAddress((void**)&attn, g_attn);

    const int SM_DK = (128 * DQ_P + 256 * DQ_P) * 4;                      // 104448
    const int SM_C2 = (256 * DQ_P + 64 * DQ_P + 64 * C2_FP + 64 * C2_VP + 64) * 4; // 173312
    const int SM_DQ = (128 * DQ_P + 256 * DQ_P + 128 + 256 + 1024) * 4;   // 110080
    cudaFuncSetAttribute(dashk_max, cudaFuncAttributeMaxDynamicSharedMemorySize, SM_DK);
    cudaFuncSetAttribute(ctx_fused2, cudaFuncAttributeMaxDynamicSharedMemorySize, SM_C2);
    cudaFuncSetAttribute(dashq_phi, cudaFuncAttributeMaxDynamicSharedMemorySize, SM_DQ);

    init_stab<<<1, BHN>>>(stabEnc);

    // Q/K/V projections (R5 config)
    tmma2<128, false><<<dim3(4, 64, 1), 128>>>(x, Wq, Q, nullptr, nullptr, nullptr,
        DMODEL, DMODEL, DMODEL, DMODEL,
        1, 1, 0, 0, 0, 0, 0, 0, 0, 0, 0, 0, 0, 1.f);
    tmma2<128, false><<<dim3(4, 256, 1), 128>>>(context, Wk, K, nullptr, nullptr, nullptr,
        DMODEL, DMODEL, DMODEL, DMODEL,
        1, 1, 0, 0, 0, 0, 0, 0, 0, 0, 0, 0, 0, 1.f);
    tmma2<128, false><<<dim3(4, 256, 1), 128>>>(context, Wv, V, nullptr, nullptr, nullptr,
        DMODEL, DMODEL, DMODEL, DMODEL,
        1, 1, 0, 0, 0, 0, 0, 0, 0, 0, 0, 0, 0, 1.f);

    // key stabilizer max (no dash store)
    dashk_max<<<dim3(32, 64), 256, SM_DK>>>(K, proj, stabEnc);

    // fused dash-recompute + phi + kc + ctx
    ctx_fused2<<<dim3(8, 64), 256, SM_C2>>>(K, V, proj, stabEnc, ctxPart, kcPart);
    reduce_ctx8<<<4096, 256>>>(ctxPart, ctx);
    kc_final8<<<BHN, 256>>>(kcPart, kc);

    // fused dashQ + phi_q + denominator
    dashq_phi<<<dim3(8, 64), 256, SM_DQ>>>(Q, proj, kc, qp, denom);

    // attn = (qp @ ctx) / denom, merged-head layout (z = b*8 + h)
    tmma2<64, false><<<dim3(1, 8, BHN), 128>>>(qp, ctx, attn, nullptr, denom, nullptr,
        MF, MF, DHD, DMODEL,
        8, 8,
        0, (long)NH * NQ * MF, (long)NQ * MF,
        0, (long)NH * MF * DHD, (long)MF * DHD,
        0, (long)NQ * DMODEL, DHD,
        (long)NH * NQ, NQ, 1.f);

    // final projection + bias
    tmma2<128, false><<<dim3(4, 64, 1), 128>>>(attn, Wo, out, bo, nullptr, nullptr,
        DMODEL, DMODEL, DMODEL, DMODEL,
        1, 1, 0, 0, 0, 0, 0, 0, 0, 0, 0, 0, 0, 1.f);
}

// round 14
// speedup vs baseline: 1.3776x; 1.1003x over previous
#include <cuda_runtime.h>
#include <cuda_fp16.h>
#include <math.h>
#include <stdint.h>

// ---------------------------------------------------------------------------
// Performer FAVOR+ cross-attention forward.
// B=8, Nq=1024, Nk=4096, D=512, H=8, DH=64, M=256
// Round 13: byte-identical resubmit of R12 (never executed; R12 hit a broker
// infra failure). tmma2h smem pitch = 12 u32 (48 B, 16-aligned) fixes the
// R11 misaligned STS.128. fp16 m16n8k16 projections; tf32 everywhere else.
// ---------------------------------------------------------------------------

#define BATCH 8
#define NQ 1024
#define NK 4096
#define DMODEL 512
#define NH 8
#define DHD 64
#define MF 256
#define BHN 64          // BATCH * NH

#define DN_SCALE 0.35355339059327379f  // 64^-0.25
#define RATIO 0.0625f                  // 256^-0.5
#define EPSF 1e-4f

// -------------------- scratch (static device allocations) ------------------
__device__ float g_Q[BATCH * NQ * DMODEL];          // 16 MB
__device__ float g_K[BATCH * NK * DMODEL];          // 64 MB
__device__ float g_V[BATCH * NK * DMODEL];          // 64 MB
__device__ float g_qp[BHN * NQ * MF];               // phi(dashQ), 64 MB
__device__ unsigned g_stabEnc[BHN];
__device__ float g_kcPart[8 * BHN * MF];
__device__ float g_kc[BHN * MF];
__device__ float g_denom[BHN * NQ];
__device__ float g_ctxPart[8 * BHN * MF * DHD];     // 32 MB
__device__ float g_ctx[BHN * MF * DHD];             // 4 MB
__device__ float g_attn[BATCH * NQ * DMODEL];       // 16 MB

// -------------------- helpers ----------------------------------------------
__device__ __forceinline__ uint32_t f2tf32(float f) {
    uint32_t u;
    asm("cvt.rna.tf32.f32 %0, %1;" : "=r"(u) : "f"(f));
    return u;
}
__device__ __forceinline__ float f2tf32f(float f) {
    return __uint_as_float(f2tf32(f));
}
__device__ __forceinline__ uint32_t packh2(float a, float b) {
    __half2 h = __floats2half2_rn(a, b);
    return *(uint32_t*)&h;
}

__device__ __forceinline__ unsigned encodeF(float f) {
    unsigned u = __float_as_uint(f);
    return (u & 0x80000000u) ? ~u : (u | 0x80000000u);
}
__device__ __forceinline__ float decodeF(unsigned e) {
    unsigned u = (e & 0x80000000u) ? (e ^ 0x80000000u) : ~e;
    return __uint_as_float(u);
}

#define MMA_TF32(d, a, b)                                               \
    asm volatile(                                                       \
        "mma.sync.aligned.m16n8k8.row.col.f32.tf32.tf32.f32 "           \
        "{%0,%1,%2,%3}, {%4,%5,%6,%7}, {%8,%9}, {%0,%1,%2,%3};\n"       \
        : "+f"(d[0]), "+f"(d[1]), "+f"(d[2]), "+f"(d[3])                \
        : "r"(a[0]), "r"(a[1]), "r"(a[2]), "r"(a[3]),                   \
          "r"(b[0]), "r"(b[1]))

#define MMA_F16(d, a, b)                                                \
    asm volatile(                                                       \
        "mma.sync.aligned.m16n8k16.row.col.f32.f16.f16.f32 "            \
        "{%0,%1,%2,%3}, {%4,%5,%6,%7}, {%8,%9}, {%0,%1,%2,%3};\n"       \
        : "+f"(d[0]), "+f"(d[1]), "+f"(d[2]), "+f"(d[3])                \
        : "r"(a[0]), "r"(a[1]), "r"(a[2]), "r"(a[3]),                   \
          "r"(b[0]), "r"(b[1]))

#define LDSM4(r0, r1, r2, r3, addr)                                     \
    asm volatile(                                                       \
        "ldmatrix.sync.aligned.m8n8.x4.shared.b16 {%0,%1,%2,%3}, [%4];" \
        : "=r"(r0), "=r"(r1), "=r"(r2), "=r"(r3) : "r"(addr))

__device__ __forceinline__ float warpRedMax(float v) {
#pragma unroll
    for (int o = 16; o > 0; o >>= 1) v = fmaxf(v, __shfl_xor_sync(0xffffffffu, v, o));
    return v;
}

// ---------------------------------------------------------------------------
// tmma2h: fp16 GEMM for projections. C = A[M,K] @ B[K,N] (+ bias), row-major.
// Block 128x128x16, 128 threads, 4 warps (2x2), warp tile 64x64.
// A smem [128 m][16 k] fp16 (8 u32 payload), pitch 12 u32 (48 B: 16-aligned,
// STS.128 and LDSM conflict-free). B smem n-major [128 n][16 k], same pitch.
// M%128==0, N%128==0, K%16==0.
// ---------------------------------------------------------------------------
#define HP 12                 // fp16 smem row pitch in u32
#define HBUF (128 * HP)       // per-buffer u32 stride
__global__ __launch_bounds__(128, 2) void tmma2h(
    const float* __restrict__ A, const float* __restrict__ B,
    float* __restrict__ C, const float* __restrict__ bias,
    int K, int lda, int ldb, int ldc)
{
    __shared__ uint32_t As[2][128][HP];
    __shared__ uint32_t Bs[2][128][HP];

    const int tid = threadIdx.x;
    const int lane = tid & 31;
    const int warp = tid >> 5;
    const int warpM = warp >> 1;          // 0..1
    const int warpN = warp & 1;           // 0..1
    const int gid = lane >> 2;
    const int tig = lane & 3;

    const int m0 = blockIdx.y * 128;
    const int n0 = blockIdx.x * 128;

    const unsigned asU = (unsigned)__cvta_generic_to_shared(&As[0][0][0]);
    const unsigned bsU = (unsigned)__cvta_generic_to_shared(&Bs[0][0][0]);
    const int lr = lane & 15;             // ldsm row within 16-row group
    const int lc = (lane >> 4) * 4;       // ldsm u32 col: 0 or 4

    float acc[4][8][4];
#pragma unroll
    for (int i = 0; i < 4; i++)
#pragma unroll
        for (int j = 0; j < 8; j++)
#pragma unroll
            for (int r = 0; r < 4; r++) acc[i][j][r] = 0.f;

    const int ntiles = K >> 4;
    float pa[16], pb[16];

    auto loadTile = [&](int k0) {
        const float* Ap = A + (long)(m0 + tid) * lda + k0;
        *(float4*)(pa + 0)  = *(const float4*)(Ap + 0);
        *(float4*)(pa + 4)  = *(const float4*)(Ap + 4);
        *(float4*)(pa + 8)  = *(const float4*)(Ap + 8);
        *(float4*)(pa + 12) = *(const float4*)(Ap + 12);
        const float* Bp = B + (long)k0 * ldb + n0 + tid;
#pragma unroll
        for (int k = 0; k < 16; k++) pb[k] = Bp[(long)k * ldb];
    };

    auto storeTile = [&](int buf) {
        uint4 u;
        u.x = packh2(pa[0], pa[1]);   u.y = packh2(pa[2], pa[3]);
        u.z = packh2(pa[4], pa[5]);   u.w = packh2(pa[6], pa[7]);
        *(uint4*)&As[buf][tid][0] = u;
        u.x = packh2(pa[8], pa[9]);   u.y = packh2(pa[10], pa[11]);
        u.z = packh2(pa[12], pa[13]); u.w = packh2(pa[14], pa[15]);
        *(uint4*)&As[buf][tid][4] = u;
        u.x = packh2(pb[0], pb[1]);   u.y = packh2(pb[2], pb[3]);
        u.z = packh2(pb[4], pb[5]);   u.w = packh2(pb[6], pb[7]);
        *(uint4*)&Bs[buf][tid][0] = u;
        u.x = packh2(pb[8], pb[9]);   u.y = packh2(pb[10], pb[11]);
        u.z = packh2(pb[12], pb[13]); u.w = packh2(pb[14], pb[15]);
        *(uint4*)&Bs[buf][tid][4] = u;
    };

    auto computeTile = [&](int buf) {
        uint32_t af[4][4];
        uint32_t bf[8][2];
#pragma unroll
        for (int i = 0; i < 4; i++) {
            unsigned addr = asU + (unsigned)((buf * HBUF +
                (warpM * 64 + i * 16 + lr) * HP + lc) * 4);
            LDSM4(af[i][0], af[i][1], af[i][2], af[i][3], addr);
        }
#pragma unroll
        for (int jj = 0; jj < 4; jj++) {
            unsigned addr = bsU + (unsigned)((buf * HBUF +
                (warpN * 64 + jj * 16 + lr) * HP + lc) * 4);
            uint32_t r0, r1, r2, r3;
            LDSM4(r0, r1, r2, r3, addr);
            bf[jj * 2][0] = r0; bf[jj * 2 + 1][0] = r1;
            bf[jj * 2][1] = r2; bf[jj * 2 + 1][1] = r3;
        }
#pragma unroll
        for (int i = 0; i < 4; i++)
#pragma unroll
            for (int j = 0; j < 8; j++)
                MMA_F16(acc[i][j], af[i], bf[j]);
    };

    loadTile(0);
    storeTile(0);
    __syncthreads();
    for (int kt = 0; kt < ntiles; kt++) {
        const int buf = kt & 1;
        const bool more = (kt + 1) < ntiles;
        if (more) loadTile((kt + 1) << 4);
        computeTile(buf);
        if (more) storeTile(buf ^ 1);
        __syncthreads();
    }

#pragma unroll
    for (int i = 0; i < 4; i++) {
        const int rL = m0 + warpM * 64 + i * 16 + gid;
#pragma unroll
        for (int j = 0; j < 8; j++) {
            const int col = n0 + warpN * 64 + (j >> 1) * 16 + (j & 1) * 8 + tig * 2;
            float v0 = acc[i][j][0], v1 = acc[i][j][1];
            float v2 = acc[i][j][2], v3 = acc[i][j][3];
            if (bias) {
                float2 bv = *(const float2*)(bias + col);
                v0 += bv.x; v1 += bv.y; v2 += bv.x; v3 += bv.y;
            }
            *(float2*)(C + (long)rL * ldc + col) = make_float2(v0, v1);
            *(float2*)(C + (long)(rL + 8) * ldc + col) = make_float2(v2, v3);
        }
    }
}

// ---------------------------------------------------------------------------
// tmma2 (proven): TF32 GEMM, block 128 x BN x 16, 128 threads, 4 warps.
// Used only (BN=64) for the attn = (qp @ ctx)/denom GEMM.
// ---------------------------------------------------------------------------
template <int BN, bool TRANSA>
__global__ __launch_bounds__(128, 2) void tmma2(
    const float* __restrict__ A, const float* __restrict__ B,
    float* __restrict__ C, const float* __restrict__ bias,
    const float* __restrict__ rowdiv, unsigned* __restrict__ maxOut,
    int K, int lda, int ldb, int ldc,
    int d2, int d3,
    long oA1, long oA2, long oA3,
    long oB1, long oB2, long oB3,
    long oC1, long oC2, long oC3,
    long oD2, long oD3,
    float alpha)
{
    constexpr int WN = BN / 2;
    constexpr int NJ = WN / 8;
    constexpr int NJJ = WN / 16;

    {
        int z = blockIdx.z;
        int z3 = z % d3;
        int zq = z / d3;
        int z2 = zq % d2;
        int z1 = zq / d2;
        A += z1 * oA1 + z2 * oA2 + z3 * oA3;
        B += z1 * oB1 + z2 * oB2 + z3 * oB3;
        C += z1 * oC1 + z2 * oC2 + z3 * oC3;
        if (rowdiv) rowdiv += z2 * oD2 + z3 * oD3;
    }

    __shared__ uint32_t As[2][128][20];
    __shared__ uint32_t Bs[2][BN][20];
    __shared__ float redMax[4];

    const int tid = threadIdx.x;
    const int lane = tid & 31;
    const int warp = tid >> 5;
    const int warpM = warp >> 1;
    const int warpN = warp & 1;
    const int gid = lane >> 2;
    const int tig = lane & 3;

    const int m0 = blockIdx.y * 128;
    const int n0 = blockIdx.x * BN;

    const unsigned asU = (unsigned)__cvta_generic_to_shared(&As[0][0][0]);
    const unsigned bsU = (unsigned)__cvta_generic_to_shared(&Bs[0][0][0]);
    const int ldsmRow = (lane & 7) + ((lane >> 3) & 1) * 8;
    const int ldsmK   = (lane >> 4) * 4;

    float acc[4][NJ][4];
#pragma unroll
    for (int i = 0; i < 4; i++)
#pragma unroll
        for (int j = 0; j < NJ; j++)
#pragma unroll
            for (int r = 0; r < 4; r++) acc[i][j][r] = 0.f;

    const int ntiles = K >> 4;
    float pa[16], pb[16];

    auto loadTile = [&](int k0) {
        if (!TRANSA) {
            const float* Ap = A + (long)(m0 + tid) * lda + k0;
            *(float4*)(pa + 0)  = *(const float4*)(Ap + 0);
            *(float4*)(pa + 4)  = *(const float4*)(Ap + 4);
            *(float4*)(pa + 8)  = *(const float4*)(Ap + 8);
            *(float4*)(pa + 12) = *(const float4*)(Ap + 12);
        } else {
            const float* Ap = A + (long)k0 * lda + m0 + tid;
#pragma unroll
            for (int k = 0; k < 16; k++) pa[k] = Ap[(long)k * lda];
        }
        if (BN == 128) {
            const float* Bp = B + (long)k0 * ldb + n0 + tid;
#pragma unroll
            for (int k = 0; k < 16; k++) pb[k] = Bp[(long)k * ldb];
        } else {
            const float* Bp = B + (long)(k0 + (tid >> 6) * 8) * ldb + n0 + (tid & 63);
#pragma unroll
            for (int k = 0; k < 8; k++) pb[k] = Bp[(long)k * ldb];
        }
    };

    auto storeTile = [&](int buf) {
#pragma unroll
        for (int g = 0; g < 4; g++) {
            uint4 u;
            u.x = f2tf32(pa[g * 4 + 0]); u.y = f2tf32(pa[g * 4 + 1]);
            u.z = f2tf32(pa[g * 4 + 2]); u.w = f2tf32(pa[g * 4 + 3]);
            *(uint4*)&As[buf][tid][g * 4] = u;
        }
        if (BN == 128) {
#pragma unroll
            for (int g = 0; g < 4; g++) {
                uint4 u;
                u.x = f2tf32(pb[g * 4 + 0]); u.y = f2tf32(pb[g * 4 + 1]);
                u.z = f2tf32(pb[g * 4 + 2]); u.w = f2tf32(pb[g * 4 + 3]);
                *(uint4*)&Bs[buf][tid][g * 4] = u;
            }
        } else {
            const int n = tid & 63, kg = (tid >> 6) * 8;
#pragma unroll
            for (int g = 0; g < 2; g++) {
                uint4 u;
                u.x = f2tf32(pb[g * 4 + 0]); u.y = f2tf32(pb[g * 4 + 1]);
                u.z = f2tf32(pb[g * 4 + 2]); u.w = f2tf32(pb[g * 4 + 3]);
                *(uint4*)&Bs[buf][n][kg + g * 4] = u;
            }
        }
    };

    auto computeTile = [&](int buf) {
#pragma unroll
        for (int ks = 0; ks < 16; ks += 8) {
            uint32_t af[4][4];
            uint32_t bf[NJ][2];
#pragma unroll
            for (int i = 0; i < 4; i++) {
                unsigned addr = asU + (unsigned)((buf * 128 * 20 +
                    (warpM * 64 + i * 16 + ldsmRow) * 20 + ks + ldsmK) * 4);
                LDSM4(af[i][0], af[i][1], af[i][2], af[i][3], addr);
            }
#pragma unroll
            for (int jj = 0; jj < NJJ; jj++) {
                unsigned addr = bsU + (unsigned)((buf * BN * 20 +
                    (warpN * WN + jj * 16 + ldsmRow) * 20 + ks + ldsmK) * 4);
                uint32_t r0, r1, r2, r3;
                LDSM4(r0, r1, r2, r3, addr);
                bf[jj * 2][0] = r0; bf[jj * 2 + 1][0] = r1;
                bf[jj * 2][1] = r2; bf[jj * 2 + 1][1] = r3;
            }
#pragma unroll
            for (int i = 0; i < 4; i++)
#pragma unroll
                for (int j = 0; j < NJ; j++)
                    MMA_TF32(acc[i][j], af[i], bf[j]);
        }
    };

    loadTile(0);
    storeTile(0);
    __syncthreads();
    for (int kt = 0; kt < ntiles; kt++) {
        const int buf = kt & 1;
        const bool more = (kt + 1) < ntiles;
        if (more) loadTile((kt + 1) << 4);
        computeTile(buf);
        if (more) storeTile(buf ^ 1);
        __syncthreads();
    }

    float vmax = -1e30f;
#pragma unroll
    for (int i = 0; i < 4; i++) {
        const int rL = m0 + warpM * 64 + i * 16 + gid;
        float dv0 = 1.f, dv1 = 1.f;
        if (rowdiv) { dv0 = 1.0f / rowdiv[rL]; dv1 = 1.0f / rowdiv[rL + 8]; }
#pragma unroll
        for (int j = 0; j < NJ; j++) {
            const int col = n0 + warpN * WN + (j >> 1) * 16 + (j & 1) * 8 + tig * 2;
            float v0 = alpha * acc[i][j][0], v1 = alpha * acc[i][j][1];
            float v2 = alpha * acc[i][j][2], v3 = alpha * acc[i][j][3];
            if (maxOut)
                vmax = fmaxf(vmax, fmaxf(fmaxf(v0, v1), fmaxf(v2, v3)));
            if (bias) {
                float2 bv = *(const float2*)(bias + col);
                v0 += bv.x; v1 += bv.y; v2 += bv.x; v3 += bv.y;
            }
            v0 *= dv0; v1 *= dv0; v2 *= dv1; v3 *= dv1;
            *(float2*)(C + (long)rL * ldc + col) = make_float2(v0, v1);
            *(float2*)(C + (long)(rL + 8) * ldc + col) = make_float2(v2, v3);
        }
    }

    if (maxOut) {
        vmax = warpRedMax(vmax);
        if (lane == 0) redMax[warp] = vmax;
        __syncthreads();
        if (tid == 0) {
            float m = fmaxf(fmaxf(redMax[0], redMax[1]), fmaxf(redMax[2], redMax[3]));
            atomicMax(maxOut + blockIdx.z, encodeF(m));
        }
    }
}

// ---------------------------------------------------------------------------
// dashk_max (proven): dash GEMM in registers; global max only, no store.
// ---------------------------------------------------------------------------
#define DQ_P 68
__global__ __launch_bounds__(256) void dashk_max(
    const float* __restrict__ Km, const float* __restrict__ proj,
    unsigned* __restrict__ stabEnc)
{
    extern __shared__ float sm[];
    float* As = sm;                        // 128 * 68
    float* Bs = As + 128 * DQ_P;           // 256 * 68
    __shared__ float red[8];

    const int rt = blockIdx.x, bh = blockIdx.y;
    const int b = bh >> 3, h = bh & 7;
    const int s0 = rt * 128;
    const int t = threadIdx.x;
    const int lane = t & 31, warp = t >> 5;
    const int warpM = warp >> 2;          // 0..1
    const int warpN = warp & 3;           // 0..3
    const unsigned asU = (unsigned)__cvta_generic_to_shared(As);
    const unsigned bsU = (unsigned)__cvta_generic_to_shared(Bs);
    const int ldsmRow = (lane & 7) + ((lane >> 3) & 1) * 8;
    const int ldsmK   = (lane >> 4) * 4;

#pragma unroll
    for (int i = 0; i < 8; i++) {
        int linear = i * 256 + t;
        int n = linear >> 4, c4 = linear & 15;
        float4 v = *(const float4*)(Km + ((long)(b * NK + s0 + n)) * DMODEL + h * DHD + c4 * 4);
        v.x = f2tf32f(v.x); v.y = f2tf32f(v.y);
        v.z = f2tf32f(v.z); v.w = f2tf32f(v.w);
        *(float4*)(As + n * DQ_P + c4 * 4) = v;
    }
#pragma unroll
    for (int i = 0; i < 16; i++) {
        int linear = i * 256 + t;
        int r = linear >> 4, c4 = linear & 15;
        float4 v = *(const float4*)(proj + (long)r * DHD + c4 * 4);
        v.x = f2tf32f(v.x); v.y = f2tf32f(v.y);
        v.z = f2tf32f(v.z); v.w = f2tf32f(v.w);
        *(float4*)(Bs + r * DQ_P + c4 * 4) = v;
    }
    __syncthreads();

    float acc[4][8][4];
#pragma unroll
    for (int i = 0; i < 4; i++)
#pragma unroll
        for (int j = 0; j < 8; j++)
#pragma unroll
            for (int r = 0; r < 4; r++) acc[i][j][r] = 0.f;

#pragma unroll
    for (int ks = 0; ks < 64; ks += 8) {
        uint32_t af[4][4], bf[8][2];
#pragma unroll
        for (int i = 0; i < 4; i++) {
            unsigned addr = asU + (unsigned)(((warpM * 64 + i * 16 + ldsmRow) * DQ_P
                                              + ks + ldsmK) * 4);
            LDSM4(af[i][0], af[i][1], af[i][2], af[i][3], addr);
        }
#pragma unroll
        for (int jj = 0; jj < 4; jj++) {
            unsigned addr = bsU + (unsigned)(((warpN * 64 + jj * 16 + ldsmRow) * DQ_P
                                              + ks + ldsmK) * 4);
            uint32_t r0, r1, r2, r3;
            LDSM4(r0, r1, r2, r3, addr);
            bf[jj * 2][0] = r0; bf[jj * 2 + 1][0] = r1;
            bf[jj * 2][1] = r2; bf[jj * 2 + 1][1] = r3;
        }
#pragma unroll
        for (int i = 0; i < 4; i++)
#pragma unroll
            for (int j = 0; j < 8; j++)
                MMA_TF32(acc[i][j], af[i], bf[j]);
    }

    float vmax = -1e30f;
#pragma unroll
    for (int i = 0; i < 4; i++)
#pragma unroll
        for (int j = 0; j < 8; j++)
#pragma unroll
            for (int r = 0; r < 4; r++) vmax = fmaxf(vmax, acc[i][j][r]);
    vmax *= DN_SCALE;
    vmax = warpRedMax(vmax);
    if (lane == 0) red[warp] = vmax;
    __syncthreads();
    if (t == 0) {
        float m = red[0];
#pragma unroll
        for (int i = 1; i < 8; i++) m = fmaxf(m, red[i]);
        atomicMax(stabEnc + bh, encodeF(m));
    }
}

// ---------------------------------------------------------------------------
// ctx_fused2 (proven): recompute dash in-SM, phi, kc, ctx MMA per chunk.
// ---------------------------------------------------------------------------
#define C2_FP 264
#define C2_VP 72
__global__ __launch_bounds__(256) void ctx_fused2(
    const float* __restrict__ Km, const float* __restrict__ V,
    const float* __restrict__ proj, const unsigned* __restrict__ stabEnc,
    float* __restrict__ ctxPart, float* __restrict__ kcPart)
{
    extern __shared__ float sm[];
    float* Bp = sm;                        // proj [256][68]
    float* Ak = Bp + 256 * DQ_P;           // K chunk [64][68]
    float* Ph = Ak + 64 * DQ_P;            // phi [64][264]
    float* Bv = Ph + 64 * C2_FP;           // V chunk [64][72]
    float* diag = Bv + 64 * C2_VP;         // [64]
    const uint32_t* PhU = (const uint32_t*)Ph;
    const uint32_t* BvU = (const uint32_t*)Bv;

    const int split = blockIdx.x, bh = blockIdx.y;
    const int b = bh >> 3, h = bh & 7;
    const int t = threadIdx.x;
    const int lane = t & 31, warp = t >> 5;
    const int gid = lane >> 2, tig = lane & 3;
    const unsigned bpU = (unsigned)__cvta_generic_to_shared(Bp);
    const unsigned akU = (unsigned)__cvta_generic_to_shared(Ak);
    const int ldsmRow = (lane & 7) + ((lane >> 3) & 1) * 8;
    const int ldsmK   = (lane >> 4) * 4;
    const float stab = decodeF(stabEnc[bh]);
    const int sBase = split * 512;

    const int warpM = warp >> 1;          // 0..3
    const int warpN = warp & 1;           // 0..1

#pragma unroll
    for (int i = 0; i < 16; i++) {
        int linear = i * 256 + t;
        int r = linear >> 4, c4 = linear & 15;
        float4 v = *(const float4*)(proj + (long)r * DHD + c4 * 4);
        v.x = f2tf32f(v.x); v.y = f2tf32f(v.y);
        v.z = f2tf32f(v.z); v.w = f2tf32f(v.w);
        *(float4*)(Bp + r * DQ_P + c4 * 4) = v;
    }

    float ctxAcc[4][4][4];
#pragma unroll
    for (int i = 0; i < 4; i++)
#pragma unroll
        for (int j = 0; j < 4; j++)
#pragma unroll
            for (int r = 0; r < 4; r++) ctxAcc[i][j][r] = 0.f;
    float kcAcc[4][2];
#pragma unroll
    for (int j = 0; j < 4; j++) { kcAcc[j][0] = 0.f; kcAcc[j][1] = 0.f; }

    for (int chunk = 0; chunk < 8; chunk++) {
        const int s0 = sBase + chunk * 64;
        __syncthreads();

        {
            const int r = t >> 2, p = t & 3;
            const float* kr = Km + ((long)(b * NK + s0 + r)) * DMODEL + h * DHD + p * 16;
            float ss = 0.f;
#pragma unroll
            for (int i = 0; i < 4; i++) {
                float4 v = *(const float4*)(kr + i * 4);
                ss += v.x * v.x + v.y * v.y + v.z * v.z + v.w * v.w;
                v.x = f2tf32f(v.x); v.y = f2tf32f(v.y);
                v.z = f2tf32f(v.z); v.w = f2tf32f(v.w);
                *(float4*)(Ak + r * DQ_P + p * 16 + i * 4) = v;
            }
            ss += __shfl_xor_sync(0xffffffffu, ss, 1);
            ss += __shfl_xor_sync(0xffffffffu, ss, 2);
            if (p == 0) diag[r] = ss * 0.0625f;
        }
        {
            const float* vsrc = V + ((long)(b * NK + s0)) * DMODEL + h * DHD;
#pragma unroll
            for (int i = 0; i < 4; i++) {
                int linear = i * 256 + t;
                int s = linear >> 4, c4 = linear & 15;
                float4 v = *(const float4*)(vsrc + (long)s * DMODEL + c4 * 4);
                v.x = f2tf32f(v.x); v.y = f2tf32f(v.y);
                v.z = f2tf32f(v.z); v.w = f2tf32f(v.w);
                *(float4*)(Bv + s * C2_VP + c4 * 4) = v;
            }
        }
        __syncthreads();

        float dacc[4][4][4];
#pragma unroll
        for (int i = 0; i < 4; i++)
#pragma unroll
            for (int j = 0; j < 4; j++)
#pragma unroll
                for (int r = 0; r < 4; r++) dacc[i][j][r] = 0.f;

#pragma unroll
        for (int ks = 0; ks < 64; ks += 8) {
            uint32_t af[4][4], bf[4][2];
#pragma unroll
            for (int i = 0; i < 4; i++) {
                unsigned addr = akU + (unsigned)(((i * 16 + ldsmRow) * DQ_P
                                                  + ks + ldsmK) * 4);
                LDSM4(af[i][0], af[i][1], af[i][2], af[i][3], addr);
            }
#pragma unroll
            for (int jj = 0; jj < 2; jj++) {
                unsigned addr = bpU + (unsigned)(((warp * 32 + jj * 16 + ldsmRow) * DQ_P
                                                  + ks + ldsmK) * 4);
                uint32_t r0, r1, r2, r3;
                LDSM4(r0, r1, r2, r3, addr);
                bf[jj * 2][0] = r0; bf[jj * 2 + 1][0] = r1;
                bf[jj * 2][1] = r2; bf[jj * 2 + 1][1] = r3;
            }
#pragma unroll
            for (int i = 0; i < 4; i++)
#pragma unroll
                for (int j = 0; j < 4; j++)
                    MMA_TF32(dacc[i][j], af[i], bf[j]);
        }

#pragma unroll
        for (int i = 0; i < 4; i++) {
            const int rA = i * 16 + gid;
            const int rB = rA + 8;
            const float shA = diag[rA] + stab;
            const float shB = diag[rB] + stab;
#pragma unroll
            for (int j = 0; j < 4; j++) {
                const int col = warp * 32 + j * 8 + tig * 2;
                float p0 = RATIO * (__expf(dacc[i][j][0] * DN_SCALE - shA) + EPSF);
                float p1 = RATIO * (__expf(dacc[i][j][1] * DN_SCALE - shA) + EPSF);
                float p2 = RATIO * (__expf(dacc[i][j][2] * DN_SCALE - shB) + EPSF);
                float p3 = RATIO * (__expf(dacc[i][j][3] * DN_SCALE - shB) + EPSF);
                kcAcc[j][0] += p0 + p2;
                kcAcc[j][1] += p1 + p3;
                *(float2*)(Ph + rA * C2_FP + col) = make_float2(f2tf32f(p0), f2tf32f(p1));
                *(float2*)(Ph + rB * C2_FP + col) = make_float2(f2tf32f(p2), f2tf32f(p3));
            }
        }
        __syncthreads();

#pragma unroll
        for (int ks = 0; ks < 64; ks += 8) {
            uint32_t af[4][4], bf[4][2];
#pragma unroll
            for (int i = 0; i < 4; i++) {
                const int mB = warpM * 64 + i * 16;
                af[i][0] = PhU[(ks + tig) * C2_FP + mB + gid];
                af[i][1] = PhU[(ks + tig) * C2_FP + mB + gid + 8];
                af[i][2] = PhU[(ks + tig + 4) * C2_FP + mB + gid];
                af[i][3] = PhU[(ks + tig + 4) * C2_FP + mB + gid + 8];
            }
#pragma unroll
            for (int j = 0; j < 4; j++) {
                const int nB = warpN * 32 + j * 8;
                bf[j][0] = BvU[(ks + tig) * C2_VP + nB + gid];
                bf[j][1] = BvU[(ks + tig + 4) * C2_VP + nB + gid];
            }
#pragma unroll
            for (int i = 0; i < 4; i++)
#pragma unroll
                for (int j = 0; j < 4; j++)
                    MMA_TF32(ctxAcc[i][j], af[i], bf[j]);
        }
    }

    float* cp = ctxPart + ((long)(split * BHN + bh)) * MF * DHD;
#pragma unroll
    for (int i = 0; i < 4; i++) {
        const int m = warpM * 64 + i * 16 + gid;
#pragma unroll
        for (int j = 0; j < 4; j++) {
            const int d = warpN * 32 + j * 8 + tig * 2;
            *(float2*)(cp + (long)m * DHD + d) = make_float2(ctxAcc[i][j][0], ctxAcc[i][j][1]);
            *(float2*)(cp + (long)(m + 8) * DHD + d) = make_float2(ctxAcc[i][j][2], ctxAcc[i][j][3]);
        }
    }
#pragma unroll
    for (int j = 0; j < 4; j++) {
#pragma unroll
        for (int p = 0; p < 2; p++) {
            float v = kcAcc[j][p];
            v += __shfl_xor_sync(0xffffffffu, v, 4);
            v += __shfl_xor_sync(0xffffffffu, v, 8);
            v += __shfl_xor_sync(0xffffffffu, v, 16);
            if (gid == 0) {
                const int col = warp * 32 + j * 8 + tig * 2 + p;
                kcPart[((long)(split * BHN + bh)) * MF + col] = v;
            }
        }
    }
}

// ---------------------------------------------------------------------------
// dashq_phi (proven): dashQ GEMM + rowmax + phi + denominator.
// ---------------------------------------------------------------------------
__global__ __launch_bounds__(256) void dashq_phi(
    const float* __restrict__ Q, const float* __restrict__ proj,
    const float* __restrict__ kc, float* __restrict__ qp,
    float* __restrict__ denom)
{
    extern __shared__ float sm[];
    float* As = sm;                        // 128 * 68
    float* Bs = As + 128 * DQ_P;           // 256 * 68
    float* diag = Bs + 256 * DQ_P;         // 128
    float* kcS = diag + 128;               // 256
    float* redA = kcS + 256;               // 128 * 4
    float* redB = redA + 512;              // 128 * 4

    const int rt = blockIdx.x, bh = blockIdx.y;
    const int b = bh >> 3, h = bh & 7;
    const int n0 = rt * 128;
    const int t = threadIdx.x;
    const int lane = t & 31, warp = t >> 5;
    const int warpM = warp >> 2;          // 0..1
    const int warpN = warp & 3;           // 0..3
    const int gid = lane >> 2, tig = lane & 3;
    const unsigned asU = (unsigned)__cvta_generic_to_shared(As);
    const unsigned bsU = (unsigned)__cvta_generic_to_shared(Bs);
    const int ldsmRow = (lane & 7) + ((lane >> 3) & 1) * 8;
    const int ldsmK   = (lane >> 4) * 4;

#pragma unroll
    for (int i = 0; i < 8; i++) {
        int linear = i * 256 + t;
        int n = linear >> 4, c4 = linear & 15;
        float4 v = *(const float4*)(Q + ((long)(b * NQ + n0 + n)) * DMODEL + h * DHD + c4 * 4);
        v.x = f2tf32f(v.x); v.y = f2tf32f(v.y);
        v.z = f2tf32f(v.z); v.w = f2tf32f(v.w);
        *(float4*)(As + n * DQ_P + c4 * 4) = v;
    }
#pragma unroll
    for (int i = 0; i < 16; i++) {
        int linear = i * 256 + t;
        int r = linear >> 4, c4 = linear & 15;
        float4 v = *(const float4*)(proj + (long)r * DHD + c4 * 4);
        v.x = f2tf32f(v.x); v.y = f2tf32f(v.y);
        v.z = f2tf32f(v.z); v.w = f2tf32f(v.w);
        *(float4*)(Bs + r * DQ_P + c4 * 4) = v;
    }
    {
        int r = t >> 1, half = t & 1;
        const float* qr = Q + ((long)(b * NQ + n0 + r)) * DMODEL + h * DHD + half * 32;
        float ss = 0.f;
#pragma unroll
        for (int i = 0; i < 8; i++) {
            float4 v = *(const float4*)(qr + i * 4);
            ss += v.x * v.x + v.y * v.y + v.z * v.z + v.w * v.w;
        }
        ss += __shfl_xor_sync(0xffffffffu, ss, 1);
        if (half == 0) diag[r] = ss * 0.0625f;
    }
    kcS[t] = kc[bh * MF + t];
    __syncthreads();

    float acc[4][8][4];
#pragma unroll
    for (int i = 0; i < 4; i++)
#pragma unroll
        for (int j = 0; j < 8; j++)
#pragma unroll
            for (int r = 0; r < 4; r++) acc[i][j][r] = 0.f;

#pragma unroll
    for (int ks = 0; ks < 64; ks += 8) {
        uint32_t af[4][4], bf[8][2];
#pragma unroll
        for (int i = 0; i < 4; i++) {
            unsigned addr = asU + (unsigned)(((warpM * 64 + i * 16 + ldsmRow) * DQ_P
                                              + ks + ldsmK) * 4);
            LDSM4(af[i][0], af[i][1], af[i][2], af[i][3], addr);
        }
#pragma unroll
        for (int jj = 0; jj < 4; jj++) {
            unsigned addr = bsU + (unsigned)(((warpN * 64 + jj * 16 + ldsmRow) * DQ_P
                                              + ks + ldsmK) * 4);
            uint32_t r0, r1, r2, r3;
            LDSM4(r0, r1, r2, r3, addr);
            bf[jj * 2][0] = r0; bf[jj * 2 + 1][0] = r1;
            bf[jj * 2][1] = r2; bf[jj * 2 + 1][1] = r3;
        }
#pragma unroll
        for (int i = 0; i < 4; i++)
#pragma unroll
            for (int j = 0; j < 8; j++)
                MMA_TF32(acc[i][j], af[i], bf[j]);
    }

#pragma unroll
    for (int i = 0; i < 4; i++)
#pragma unroll
        for (int j = 0; j < 8; j++)
#pragma unroll
            for (int r = 0; r < 4; r++) acc[i][j][r] *= DN_SCALE;

#pragma unroll
    for (int i = 0; i < 4; i++) {
        const int rA = warpM * 64 + i * 16 + gid;
        float mA = -1e30f, mB = -1e30f;
#pragma unroll
        for (int j = 0; j < 8; j++) {
            mA = fmaxf(mA, fmaxf(acc[i][j][0], acc[i][j][1]));
            mB = fmaxf(mB, fmaxf(acc[i][j][2], acc[i][j][3]));
        }
        mA = fmaxf(mA, __shfl_xor_sync(0xffffffffu, mA, 1));
        mA = fmaxf(mA, __shfl_xor_sync(0xffffffffu, mA, 2));
        mB = fmaxf(mB, __shfl_xor_sync(0xffffffffu, mB, 1));
        mB = fmaxf(mB, __shfl_xor_sync(0xffffffffu, mB, 2));
        if (tig == 0) {
            redA[rA * 4 + warpN] = mA;
            redA[(rA + 8) * 4 + warpN] = mB;
        }
    }
    __syncthreads();

#pragma unroll
    for (int i = 0; i < 4; i++) {
        const int rA = warpM * 64 + i * 16 + gid;
        const int rB = rA + 8;
        const float rmA = fmaxf(fmaxf(redA[rA * 4], redA[rA * 4 + 1]),
                                fmaxf(redA[rA * 4 + 2], redA[rA * 4 + 3]));
        const float rmB = fmaxf(fmaxf(redA[rB * 4], redA[rB * 4 + 1]),
                                fmaxf(redA[rB * 4 + 2], redA[rB * 4 + 3]));
        const float shA = diag[rA] + rmA;
        const float shB = diag[rB] + rmB;
        float dA = 0.f, dB = 0.f;
#pragma unroll
        for (int j = 0; j < 8; j++) {
            const int col = warpN * 64 + (j >> 1) * 16 + (j & 1) * 8 + tig * 2;
            float p0 = RATIO * (__expf(acc[i][j][0] - shA) + EPSF);
            float p1 = RATIO * (__expf(acc[i][j][1] - shA) + EPSF);
            float p2 = RATIO * (__expf(acc[i][j][2] - shB) + EPSF);
            float p3 = RATIO * (__expf(acc[i][j][3] - shB) + EPSF);
            float2 kv = *(const float2*)(kcS + col);
            dA += p0 * kv.x + p1 * kv.y;
            dB += p2 * kv.x + p3 * kv.y;
            *(float2*)(qp + ((long)bh * NQ + n0 + rA) * MF + col) = make_float2(p0, p1);
            *(float2*)(qp + ((long)bh * NQ + n0 + rB) * MF + col) = make_float2(p2, p3);
        }
        dA += __shfl_xor_sync(0xffffffffu, dA, 1);
        dA += __shfl_xor_sync(0xffffffffu, dA, 2);
        dB += __shfl_xor_sync(0xffffffffu, dB, 1);
        dB += __shfl_xor_sync(0xffffffffu, dB, 2);
        if (tig == 0) {
            redB[rA * 4 + warpN] = dA;
            redB[rB * 4 + warpN] = dB;
        }
    }
    __syncthreads();
    if (warpN == 0 && tig == 0) {
#pragma unroll
        for (int i = 0; i < 4; i++) {
            const int rA = warpM * 64 + i * 16 + gid;
            const int rB = rA + 8;
            denom[(long)bh * NQ + n0 + rA] =
                (redB[rA * 4] + redB[rA * 4 + 1]) + (redB[rA * 4 + 2] + redB[rA * 4 + 3]);
            denom[(long)bh * NQ + n0 + rB] =
                (redB[rB * 4] + redB[rB * 4 + 1]) + (redB[rB * 4 + 2] + redB[rB * 4 + 3]);
        }
    }
}

// -------------------- small kernels ----------------------------------------
__global__ void init_stab(unsigned* __restrict__ s) {
    s[threadIdx.x] = 0u;
}

__global__ void kc_final8(const float* __restrict__ part, float* __restrict__ kc) {
    int bh = blockIdx.x, t = threadIdx.x;
    float s = 0.f;
#pragma unroll
    for (int sp = 0; sp < 8; sp++) s += part[((long)(sp * BHN + bh)) * MF + t];
    kc[bh * MF + t] = s;
}

__global__ void reduce_ctx8(const float* __restrict__ p, float* __restrict__ c) {
    int i = blockIdx.x * 256 + threadIdx.x;   // 1048576 total
    float s0 = p[i] + p[i + 1 * 1048576];
    float s1 = p[i + 2 * 1048576] + p[i + 3 * 1048576];
    float s2 = p[i + 4 * 1048576] + p[i + 5 * 1048576];
    float s3 = p[i + 6 * 1048576] + p[i + 7 * 1048576];
    c[i] = (s0 + s1) + (s2 + s3);
}

// ---------------------------------------------------------------------------
extern "C" void kernel_launch(void* const* d_in, const int* in_sizes, int n_in,
                              void* d_out, int out_size)
{
    (void)in_sizes; (void)n_in; (void)out_size;
    const float* x       = (const float*)d_in[0];
    const float* context = (const float*)d_in[1];
    const float* Wq      = (const float*)d_in[2];
    const float* Wk      = (const float*)d_in[3];
    const float* Wv      = (const float*)d_in[4];
    const float* Wo      = (const float*)d_in[5];
    const float* bo      = (const float*)d_in[6];
    const float* proj    = (const float*)d_in[7];
    float* out = (float*)d_out;

    float *Q, *K, *V, *qp, *kcPart, *kc, *denom;
    float *ctxPart, *ctx, *attn;
    unsigned* stabEnc;
    cudaGetSymbolAddress((void**)&Q, g_Q);
    cudaGetSymbolAddress((void**)&K, g_K);
    cudaGetSymbolAddress((void**)&V, g_V);
    cudaGetSymbolAddress((void**)&qp, g_qp);
    cudaGetSymbolAddress((void**)&stabEnc, g_stabEnc);
    cudaGetSymbolAddress((void**)&kcPart, g_kcPart);
    cudaGetSymbolAddress((void**)&kc, g_kc);
    cudaGetSymbolAddress((void**)&denom, g_denom);
    cudaGetSymbolAddress((void**)&ctxPart, g_ctxPart);
    cudaGetSymbolAddress((void**)&ctx, g_ctx);
    cudaGetSymbolAddress((void**)&attn, g_attn);

    const int SM_DK = (128 * DQ_P + 256 * DQ_P) * 4;                      // 104448
    const int SM_C2 = (256 * DQ_P + 64 * DQ_P + 64 * C2_FP + 64 * C2_VP + 64) * 4; // 173312
    const int SM_DQ = (128 * DQ_P + 256 * DQ_P + 128 + 256 + 1024) * 4;   // 110080
    cudaFuncSetAttribute(dashk_max, cudaFuncAttributeMaxDynamicSharedMemorySize, SM_DK);
    cudaFuncSetAttribute(ctx_fused2, cudaFuncAttributeMaxDynamicSharedMemorySize, SM_C2);
    cudaFuncSetAttribute(dashq_phi, cudaFuncAttributeMaxDynamicSharedMemorySize, SM_DQ);

    init_stab<<<1, BHN>>>(stabEnc);

    // Q/K/V projections (fp16 MMA)
    tmma2h<<<dim3(4, 64), 128>>>(x, Wq, Q, nullptr, DMODEL, DMODEL, DMODEL, DMODEL);
    tmma2h<<<dim3(4, 256), 128>>>(context, Wk, K, nullptr, DMODEL, DMODEL, DMODEL, DMODEL);
    tmma2h<<<dim3(4, 256), 128>>>(context, Wv, V, nullptr, DMODEL, DMODEL, DMODEL, DMODEL);

    // key stabilizer max (no dash store)
    dashk_max<<<dim3(32, 64), 256, SM_DK>>>(K, proj, stabEnc);

    // fused dash-recompute + phi + kc + ctx
    ctx_fused2<<<dim3(8, 64), 256, SM_C2>>>(K, V, proj, stabEnc, ctxPart, kcPart);
    reduce_ctx8<<<4096, 256>>>(ctxPart, ctx);
    kc_final8<<<BHN, 256>>>(kcPart, kc);

    // fused dashQ + phi_q + denominator
    dashq_phi<<<dim3(8, 64), 256, SM_DQ>>>(Q, proj, kc, qp, denom);

    // attn = (qp @ ctx) / denom, merged-head layout (z = b*8 + h)
    tmma2<64, false><<<dim3(1, 8, BHN), 128>>>(qp, ctx, attn, nullptr, denom, nullptr,
        MF, MF, DHD, DMODEL,
        8, 8,
        0, (long)NH * NQ * MF, (long)NQ * MF,
        0, (long)NH * MF * DHD, (long)MF * DHD,
        0, (long)NQ * DMODEL, DHD,
        (long)NH * NQ, NQ, 1.f);

    // final projection + bias (fp16 MMA)
    tmma2h<<<dim3(4, 64), 128>>>(attn, Wo, out, bo, DMODEL, DMODEL, DMODEL, DMODEL);
}

// round 16
// speedup vs baseline: 1.3899x; 1.0090x over previous
#include <cuda_runtime.h>
#include <cuda_fp16.h>
#include <math.h>
#include <stdint.h>

// ---------------------------------------------------------------------------
// Performer FAVOR+ cross-attention forward.
// B=8, Nq=1024, Nk=4096, D=512, H=8, DH=64, M=256
// Round 15: byte-identical resubmit of R14 (broker infra failure; variant has
// never executed). Projections on a 3-stage cp.async fp16 pipeline
// (tmma2h_cp) over pre-converted half operands. Dash/ctx/phi path identical
// to R13 (passed, 694us).
// ---------------------------------------------------------------------------

#define BATCH 8
#define NQ 1024
#define NK 4096
#define DMODEL 512
#define NH 8
#define DHD 64
#define MF 256
#define BHN 64          // BATCH * NH

#define DN_SCALE 0.35355339059327379f  // 64^-0.25
#define RATIO 0.0625f                  // 256^-0.5
#define EPSF 1e-4f

// -------------------- scratch (static device allocations) ------------------
__device__ float g_Q[BATCH * NQ * DMODEL];          // 16 MB
__device__ float g_K[BATCH * NK * DMODEL];          // 64 MB
__device__ float g_V[BATCH * NK * DMODEL];          // 64 MB
__device__ __half g_xH[BATCH * NQ * DMODEL];        // 8 MB
__device__ __half g_ctxH[BATCH * NK * DMODEL];      // 32 MB
__device__ __half g_WqT[DMODEL * DMODEL];           // half [N][K], 512 KB
__device__ __half g_WkT[DMODEL * DMODEL];
__device__ __half g_WvT[DMODEL * DMODEL];
__device__ __half g_WoT[DMODEL * DMODEL];
__device__ __half g_attnH[BATCH * NQ * DMODEL];     // 8 MB
__device__ float g_qp[BHN * NQ * MF];               // phi(dashQ), 64 MB
__device__ unsigned g_stabEnc[BHN];
__device__ float g_kcPart[8 * BHN * MF];
__device__ float g_kc[BHN * MF];
__device__ float g_denom[BHN * NQ];
__device__ float g_ctxPart[8 * BHN * MF * DHD];     // 32 MB
__device__ float g_ctx[BHN * MF * DHD];             // 4 MB

// -------------------- helpers ----------------------------------------------
__device__ __forceinline__ uint32_t f2tf32(float f) {
    uint32_t u;
    asm("cvt.rna.tf32.f32 %0, %1;" : "=r"(u) : "f"(f));
    return u;
}
__device__ __forceinline__ float f2tf32f(float f) {
    return __uint_as_float(f2tf32(f));
}

__device__ __forceinline__ unsigned encodeF(float f) {
    unsigned u = __float_as_uint(f);
    return (u & 0x80000000u) ? ~u : (u | 0x80000000u);
}
__device__ __forceinline__ float decodeF(unsigned e) {
    unsigned u = (e & 0x80000000u) ? (e ^ 0x80000000u) : ~e;
    return __uint_as_float(u);
}

#define MMA_TF32(d, a, b)                                               \
    asm volatile(                                                       \
        "mma.sync.aligned.m16n8k8.row.col.f32.tf32.tf32.f32 "           \
        "{%0,%1,%2,%3}, {%4,%5,%6,%7}, {%8,%9}, {%0,%1,%2,%3};\n"       \
        : "+f"(d[0]), "+f"(d[1]), "+f"(d[2]), "+f"(d[3])                \
        : "r"(a[0]), "r"(a[1]), "r"(a[2]), "r"(a[3]),                   \
          "r"(b[0]), "r"(b[1]))

#define MMA_F16(d, a, b)                                                \
    asm volatile(                                                       \
        "mma.sync.aligned.m16n8k16.row.col.f32.f16.f16.f32 "            \
        "{%0,%1,%2,%3}, {%4,%5,%6,%7}, {%8,%9}, {%0,%1,%2,%3};\n"       \
        : "+f"(d[0]), "+f"(d[1]), "+f"(d[2]), "+f"(d[3])                \
        : "r"(a[0]), "r"(a[1]), "r"(a[2]), "r"(a[3]),                   \
          "r"(b[0]), "r"(b[1]))

#define LDSM4(r0, r1, r2, r3, addr)                                     \
    asm volatile(                                                       \
        "ldmatrix.sync.aligned.m8n8.x4.shared.b16 {%0,%1,%2,%3}, [%4];" \
        : "=r"(r0), "=r"(r1), "=r"(r2), "=r"(r3) : "r"(addr))

__device__ __forceinline__ void cpAsync16(uint32_t dst, const void* src) {
    asm volatile("cp.async.cg.shared.global [%0], [%1], 16;\n"
                 :: "r"(dst), "l"(src));
}
#define CP_COMMIT() asm volatile("cp.async.commit_group;\n")
#define CP_WAIT1()  asm volatile("cp.async.wait_group 1;\n")

__device__ __forceinline__ float warpRedMax(float v) {
#pragma unroll
    for (int o = 16; o > 0; o >>= 1) v = fmaxf(v, __shfl_xor_sync(0xffffffffu, v, o));
    return v;
}

// ---------------------------------------------------------------------------
// tmma2h_cp: fp16 GEMM, 3-stage cp.async pipeline. C = A @ B^T (+ bias).
// A: half [M][512] row-major. BT: half [N][512] row-major (= B transposed).
// Block 128x128x16, 128 threads, 4 warps (2x2), warp tile 64x64.
// smem pitch 12 u32 (48 B, 16-aligned; STS/cp.async + LDSM conflict-free).
// ---------------------------------------------------------------------------
#define HP 12                 // fp16 smem row pitch in u32
#define HS (128 * HP)         // u32 per stage per matrix
__global__ __launch_bounds__(128) void tmma2h_cp(
    const __half* __restrict__ A, const __half* __restrict__ BT,
    float* __restrict__ C, const float* __restrict__ bias, int ldc)
{
    __shared__ uint32_t SA[3][128][HP];
    __shared__ uint32_t SB[3][128][HP];

    const int tid = threadIdx.x;
    const int lane = tid & 31;
    const int warp = tid >> 5;
    const int warpM = warp >> 1;          // 0..1
    const int warpN = warp & 1;           // 0..1
    const int gid = lane >> 2;
    const int tig = lane & 3;

    const int m0 = blockIdx.y * 128;
    const int n0 = blockIdx.x * 128;

    const unsigned saU = (unsigned)__cvta_generic_to_shared(&SA[0][0][0]);
    const unsigned sbU = (unsigned)__cvta_generic_to_shared(&SB[0][0][0]);
    const int lr = lane & 15;             // ldsm row within 16-row group
    const int lc = (lane >> 4) * 4;       // ldsm u32 col: 0 or 4

    float acc[4][8][4];
#pragma unroll
    for (int i = 0; i < 4; i++)
#pragma unroll
        for (int j = 0; j < 8; j++)
#pragma unroll
            for (int r = 0; r < 4; r++) acc[i][j][r] = 0.f;

    const __half* Arow = A + (long)(m0 + tid) * DMODEL;
    const __half* Brow = BT + (long)(n0 + tid) * DMODEL;

    auto issueStage = [&](int kt, int s) {
        const __half* Ap = Arow + kt * 16;
        const uint32_t da = saU + (uint32_t)(s * HS + tid * HP) * 4u;
        cpAsync16(da, Ap);
        cpAsync16(da + 16, Ap + 8);
        const __half* Bp = Brow + kt * 16;
        const uint32_t db = sbU + (uint32_t)(s * HS + tid * HP) * 4u;
        cpAsync16(db, Bp);
        cpAsync16(db + 16, Bp + 8);
    };

    auto computeStage = [&](int s) {
        uint32_t af[4][4];
        uint32_t bf[8][2];
#pragma unroll
        for (int i = 0; i < 4; i++) {
            unsigned addr = saU + (unsigned)((s * HS +
                (warpM * 64 + i * 16 + lr) * HP + lc) * 4);
            LDSM4(af[i][0], af[i][1], af[i][2], af[i][3], addr);
        }
#pragma unroll
        for (int jj = 0; jj < 4; jj++) {
            unsigned addr = sbU + (unsigned)((s * HS +
                (warpN * 64 + jj * 16 + lr) * HP + lc) * 4);
            uint32_t r0, r1, r2, r3;
            LDSM4(r0, r1, r2, r3, addr);
            bf[jj * 2][0] = r0; bf[jj * 2 + 1][0] = r1;
            bf[jj * 2][1] = r2; bf[jj * 2 + 1][1] = r3;
        }
#pragma unroll
        for (int i = 0; i < 4; i++)
#pragma unroll
            for (int j = 0; j < 8; j++)
                MMA_F16(acc[i][j], af[i], bf[j]);
    };

    const int ntiles = DMODEL / 16;       // 32
    issueStage(0, 0); CP_COMMIT();
    issueStage(1, 1); CP_COMMIT();
    for (int kt = 0; kt < ntiles; kt++) {
        CP_WAIT1();
        __syncthreads();
        if (kt + 2 < ntiles) issueStage(kt + 2, (kt + 2) % 3);
        CP_COMMIT();
        computeStage(kt % 3);
    }

    // ---- epilogue (fp32 out) ----
#pragma unroll
    for (int i = 0; i < 4; i++) {
        const int rL = m0 + warpM * 64 + i * 16 + gid;
#pragma unroll
        for (int j = 0; j < 8; j++) {
            const int col = n0 + warpN * 64 + (j >> 1) * 16 + (j & 1) * 8 + tig * 2;
            float v0 = acc[i][j][0], v1 = acc[i][j][1];
            float v2 = acc[i][j][2], v3 = acc[i][j][3];
            if (bias) {
                float2 bv = *(const float2*)(bias + col);
                v0 += bv.x; v1 += bv.y; v2 += bv.x; v3 += bv.y;
            }
            *(float2*)(C + (long)rL * ldc + col) = make_float2(v0, v1);
            *(float2*)(C + (long)(rL + 8) * ldc + col) = make_float2(v2, v3);
        }
    }
}

// ---------------------------------------------------------------------------
// tmma2 (proven): TF32 GEMM, block 128 x BN x 16, 128 threads, 4 warps.
// Used only (BN=64) for the attn = (qp @ ctx)/denom GEMM; writes HALF out.
// ---------------------------------------------------------------------------
template <int BN, bool TRANSA>
__global__ __launch_bounds__(128, 2) void tmma2(
    const float* __restrict__ A, const float* __restrict__ B,
    __half* __restrict__ Ch, const float* __restrict__ bias,
    const float* __restrict__ rowdiv, unsigned* __restrict__ maxOut,
    int K, int lda, int ldb, int ldc,
    int d2, int d3,
    long oA1, long oA2, long oA3,
    long oB1, long oB2, long oB3,
    long oC1, long oC2, long oC3,
    long oD2, long oD3,
    float alpha)
{
    constexpr int WN = BN / 2;
    constexpr int NJ = WN / 8;
    constexpr int NJJ = WN / 16;

    {
        int z = blockIdx.z;
        int z3 = z % d3;
        int zq = z / d3;
        int z2 = zq % d2;
        int z1 = zq / d2;
        A += z1 * oA1 + z2 * oA2 + z3 * oA3;
        B += z1 * oB1 + z2 * oB2 + z3 * oB3;
        Ch += z1 * oC1 + z2 * oC2 + z3 * oC3;
        if (rowdiv) rowdiv += z2 * oD2 + z3 * oD3;
    }

    __shared__ uint32_t As[2][128][20];
    __shared__ uint32_t Bs[2][BN][20];
    __shared__ float redMax[4];

    const int tid = threadIdx.x;
    const int lane = tid & 31;
    const int warp = tid >> 5;
    const int warpM = warp >> 1;
    const int warpN = warp & 1;
    const int gid = lane >> 2;
    const int tig = lane & 3;

    const int m0 = blockIdx.y * 128;
    const int n0 = blockIdx.x * BN;

    const unsigned asU = (unsigned)__cvta_generic_to_shared(&As[0][0][0]);
    const unsigned bsU = (unsigned)__cvta_generic_to_shared(&Bs[0][0][0]);
    const int ldsmRow = (lane & 7) + ((lane >> 3) & 1) * 8;
    const int ldsmK   = (lane >> 4) * 4;

    float acc[4][NJ][4];
#pragma unroll
    for (int i = 0; i < 4; i++)
#pragma unroll
        for (int j = 0; j < NJ; j++)
#pragma unroll
            for (int r = 0; r < 4; r++) acc[i][j][r] = 0.f;

    const int ntiles = K >> 4;
    float pa[16], pb[16];

    auto loadTile = [&](int k0) {
        if (!TRANSA) {
            const float* Ap = A + (long)(m0 + tid) * lda + k0;
            *(float4*)(pa + 0)  = *(const float4*)(Ap + 0);
            *(float4*)(pa + 4)  = *(const float4*)(Ap + 4);
            *(float4*)(pa + 8)  = *(const float4*)(Ap + 8);
            *(float4*)(pa + 12) = *(const float4*)(Ap + 12);
        } else {
            const float* Ap = A + (long)k0 * lda + m0 + tid;
#pragma unroll
            for (int k = 0; k < 16; k++) pa[k] = Ap[(long)k * lda];
        }
        if (BN == 128) {
            const float* Bp = B + (long)k0 * ldb + n0 + tid;
#pragma unroll
            for (int k = 0; k < 16; k++) pb[k] = Bp[(long)k * ldb];
        } else {
            const float* Bp = B + (long)(k0 + (tid >> 6) * 8) * ldb + n0 + (tid & 63);
#pragma unroll
            for (int k = 0; k < 8; k++) pb[k] = Bp[(long)k * ldb];
        }
    };

    auto storeTile = [&](int buf) {
#pragma unroll
        for (int g = 0; g < 4; g++) {
            uint4 u;
            u.x = f2tf32(pa[g * 4 + 0]); u.y = f2tf32(pa[g * 4 + 1]);
            u.z = f2tf32(pa[g * 4 + 2]); u.w = f2tf32(pa[g * 4 + 3]);
            *(uint4*)&As[buf][tid][g * 4] = u;
        }
        if (BN == 128) {
#pragma unroll
            for (int g = 0; g < 4; g++) {
                uint4 u;
                u.x = f2tf32(pb[g * 4 + 0]); u.y = f2tf32(pb[g * 4 + 1]);
                u.z = f2tf32(pb[g * 4 + 2]); u.w = f2tf32(pb[g * 4 + 3]);
                *(uint4*)&Bs[buf][tid][g * 4] = u;
            }
        } else {
            const int n = tid & 63, kg = (tid >> 6) * 8;
#pragma unroll
            for (int g = 0; g < 2; g++) {
                uint4 u;
                u.x = f2tf32(pb[g * 4 + 0]); u.y = f2tf32(pb[g * 4 + 1]);
                u.z = f2tf32(pb[g * 4 + 2]); u.w = f2tf32(pb[g * 4 + 3]);
                *(uint4*)&Bs[buf][n][kg + g * 4] = u;
            }
        }
    };

    auto computeTile = [&](int buf) {
#pragma unroll
        for (int ks = 0; ks < 16; ks += 8) {
            uint32_t af[4][4];
            uint32_t bf[NJ][2];
#pragma unroll
            for (int i = 0; i < 4; i++) {
                unsigned addr = asU + (unsigned)((buf * 128 * 20 +
                    (warpM * 64 + i * 16 + ldsmRow) * 20 + ks + ldsmK) * 4);
                LDSM4(af[i][0], af[i][1], af[i][2], af[i][3], addr);
            }
#pragma unroll
            for (int jj = 0; jj < NJJ; jj++) {
                unsigned addr = bsU + (unsigned)((buf * BN * 20 +
                    (warpN * WN + jj * 16 + ldsmRow) * 20 + ks + ldsmK) * 4);
                uint32_t r0, r1, r2, r3;
                LDSM4(r0, r1, r2, r3, addr);
                bf[jj * 2][0] = r0; bf[jj * 2 + 1][0] = r1;
                bf[jj * 2][1] = r2; bf[jj * 2 + 1][1] = r3;
            }
#pragma unroll
            for (int i = 0; i < 4; i++)
#pragma unroll
                for (int j = 0; j < NJ; j++)
                    MMA_TF32(acc[i][j], af[i], bf[j]);
        }
    };

    loadTile(0);
    storeTile(0);
    __syncthreads();
    for (int kt = 0; kt < ntiles; kt++) {
        const int buf = kt & 1;
        const bool more = (kt + 1) < ntiles;
        if (more) loadTile((kt + 1) << 4);
        computeTile(buf);
        if (more) storeTile(buf ^ 1);
        __syncthreads();
    }

    float vmax = -1e30f;
#pragma unroll
    for (int i = 0; i < 4; i++) {
        const int rL = m0 + warpM * 64 + i * 16 + gid;
        float dv0 = 1.f, dv1 = 1.f;
        if (rowdiv) { dv0 = 1.0f / rowdiv[rL]; dv1 = 1.0f / rowdiv[rL + 8]; }
#pragma unroll
        for (int j = 0; j < NJ; j++) {
            const int col = n0 + warpN * WN + (j >> 1) * 16 + (j & 1) * 8 + tig * 2;
            float v0 = alpha * acc[i][j][0], v1 = alpha * acc[i][j][1];
            float v2 = alpha * acc[i][j][2], v3 = alpha * acc[i][j][3];
            if (maxOut)
                vmax = fmaxf(vmax, fmaxf(fmaxf(v0, v1), fmaxf(v2, v3)));
            if (bias) {
                float2 bv = *(const float2*)(bias + col);
                v0 += bv.x; v1 += bv.y; v2 += bv.x; v3 += bv.y;
            }
            v0 *= dv0; v1 *= dv0; v2 *= dv1; v3 *= dv1;
            *(__half2*)(Ch + (long)rL * ldc + col) = __floats2half2_rn(v0, v1);
            *(__half2*)(Ch + (long)(rL + 8) * ldc + col) = __floats2half2_rn(v2, v3);
        }
    }

    if (maxOut) {
        vmax = warpRedMax(vmax);
        if (lane == 0) redMax[warp] = vmax;
        __syncthreads();
        if (tid == 0) {
            float m = fmaxf(fmaxf(redMax[0], redMax[1]), fmaxf(redMax[2], redMax[3]));
            atomicMax(maxOut + blockIdx.z, encodeF(m));
        }
    }
}

// ---------------------------------------------------------------------------
// dashk_max (proven R13): dash GEMM in registers; global max only, no store.
// ---------------------------------------------------------------------------
#define DQ_P 68
__global__ __launch_bounds__(256) void dashk_max(
    const float* __restrict__ Km, const float* __restrict__ proj,
    unsigned* __restrict__ stabEnc)
{
    extern __shared__ float sm[];
    float* As = sm;                        // 128 * 68
    float* Bs = As + 128 * DQ_P;           // 256 * 68
    __shared__ float red[8];

    const int rt = blockIdx.x, bh = blockIdx.y;
    const int b = bh >> 3, h = bh & 7;
    const int s0 = rt * 128;
    const int t = threadIdx.x;
    const int lane = t & 31, warp = t >> 5;
    const int warpM = warp >> 2;          // 0..1
    const int warpN = warp & 3;           // 0..3
    const unsigned asU = (unsigned)__cvta_generic_to_shared(As);
    const unsigned bsU = (unsigned)__cvta_generic_to_shared(Bs);
    const int ldsmRow = (lane & 7) + ((lane >> 3) & 1) * 8;
    const int ldsmK   = (lane >> 4) * 4;

#pragma unroll
    for (int i = 0; i < 8; i++) {
        int linear = i * 256 + t;
        int n = linear >> 4, c4 = linear & 15;
        float4 v = *(const float4*)(Km + ((long)(b * NK + s0 + n)) * DMODEL + h * DHD + c4 * 4);
        v.x = f2tf32f(v.x); v.y = f2tf32f(v.y);
        v.z = f2tf32f(v.z); v.w = f2tf32f(v.w);
        *(float4*)(As + n * DQ_P + c4 * 4) = v;
    }
#pragma unroll
    for (int i = 0; i < 16; i++) {
        int linear = i * 256 + t;
        int r = linear >> 4, c4 = linear & 15;
        float4 v = *(const float4*)(proj + (long)r * DHD + c4 * 4);
        v.x = f2tf32f(v.x); v.y = f2tf32f(v.y);
        v.z = f2tf32f(v.z); v.w = f2tf32f(v.w);
        *(float4*)(Bs + r * DQ_P + c4 * 4) = v;
    }
    __syncthreads();

    float acc[4][8][4];
#pragma unroll
    for (int i = 0; i < 4; i++)
#pragma unroll
        for (int j = 0; j < 8; j++)
#pragma unroll
            for (int r = 0; r < 4; r++) acc[i][j][r] = 0.f;

#pragma unroll
    for (int ks = 0; ks < 64; ks += 8) {
        uint32_t af[4][4], bf[8][2];
#pragma unroll
        for (int i = 0; i < 4; i++) {
            unsigned addr = asU + (unsigned)(((warpM * 64 + i * 16 + ldsmRow) * DQ_P
                                              + ks + ldsmK) * 4);
            LDSM4(af[i][0], af[i][1], af[i][2], af[i][3], addr);
        }
#pragma unroll
        for (int jj = 0; jj < 4; jj++) {
            unsigned addr = bsU + (unsigned)(((warpN * 64 + jj * 16 + ldsmRow) * DQ_P
                                              + ks + ldsmK) * 4);
            uint32_t r0, r1, r2, r3;
            LDSM4(r0, r1, r2, r3, addr);
            bf[jj * 2][0] = r0; bf[jj * 2 + 1][0] = r1;
            bf[jj * 2][1] = r2; bf[jj * 2 + 1][1] = r3;
        }
#pragma unroll
        for (int i = 0; i < 4; i++)
#pragma unroll
            for (int j = 0; j < 8; j++)
                MMA_TF32(acc[i][j], af[i], bf[j]);
    }

    float vmax = -1e30f;
#pragma unroll
    for (int i = 0; i < 4; i++)
#pragma unroll
        for (int j = 0; j < 8; j++)
#pragma unroll
            for (int r = 0; r < 4; r++) vmax = fmaxf(vmax, acc[i][j][r]);
    vmax *= DN_SCALE;
    vmax = warpRedMax(vmax);
    if (lane == 0) red[warp] = vmax;
    __syncthreads();
    if (t == 0) {
        float m = red[0];
#pragma unroll
        for (int i = 1; i < 8; i++) m = fmaxf(m, red[i]);
        atomicMax(stabEnc + bh, encodeF(m));
    }
}

// ---------------------------------------------------------------------------
// ctx_fused2 (proven R13): recompute dash in-SM, phi, kc, ctx MMA per chunk.
// ---------------------------------------------------------------------------
#define C2_FP 264
#define C2_VP 72
__global__ __launch_bounds__(256) void ctx_fused2(
    const float* __restrict__ Km, const float* __restrict__ V,
    const float* __restrict__ proj, const unsigned* __restrict__ stabEnc,
    float* __restrict__ ctxPart, float* __restrict__ kcPart)
{
    extern __shared__ float sm[];
    float* Bp = sm;                        // proj [256][68]
    float* Ak = Bp + 256 * DQ_P;           // K chunk [64][68]
    float* Ph = Ak + 64 * DQ_P;            // phi [64][264]
    float* Bv = Ph + 64 * C2_FP;           // V chunk [64][72]
    float* diag = Bv + 64 * C2_VP;         // [64]
    const uint32_t* PhU = (const uint32_t*)Ph;
    const uint32_t* BvU = (const uint32_t*)Bv;

    const int split = blockIdx.x, bh = blockIdx.y;
    const int b = bh >> 3, h = bh & 7;
    const int t = threadIdx.x;
    const int lane = t & 31, warp = t >> 5;
    const int gid = lane >> 2, tig = lane & 3;
    const unsigned bpU = (unsigned)__cvta_generic_to_shared(Bp);
    const unsigned akU = (unsigned)__cvta_generic_to_shared(Ak);
    const int ldsmRow = (lane & 7) + ((lane >> 3) & 1) * 8;
    const int ldsmK   = (lane >> 4) * 4;
    const float stab = decodeF(stabEnc[bh]);
    const int sBase = split * 512;

    const int warpM = warp >> 1;          // 0..3
    const int warpN = warp & 1;           // 0..1

#pragma unroll
    for (int i = 0; i < 16; i++) {
        int linear = i * 256 + t;
        int r = linear >> 4, c4 = linear & 15;
        float4 v = *(const float4*)(proj + (long)r * DHD + c4 * 4);
        v.x = f2tf32f(v.x); v.y = f2tf32f(v.y);
        v.z = f2tf32f(v.z); v.w = f2tf32f(v.w);
        *(float4*)(Bp + r * DQ_P + c4 * 4) = v;
    }

    float ctxAcc[4][4][4];
#pragma unroll
    for (int i = 0; i < 4; i++)
#pragma unroll
        for (int j = 0; j < 4; j++)
#pragma unroll
            for (int r = 0; r < 4; r++) ctxAcc[i][j][r] = 0.f;
    float kcAcc[4][2];
#pragma unroll
    for (int j = 0; j < 4; j++) { kcAcc[j][0] = 0.f; kcAcc[j][1] = 0.f; }

    for (int chunk = 0; chunk < 8; chunk++) {
        const int s0 = sBase + chunk * 64;
        __syncthreads();

        {
            const int r = t >> 2, p = t & 3;
            const float* kr = Km + ((long)(b * NK + s0 + r)) * DMODEL + h * DHD + p * 16;
            float ss = 0.f;
#pragma unroll
            for (int i = 0; i < 4; i++) {
                float4 v = *(const float4*)(kr + i * 4);
                ss += v.x * v.x + v.y * v.y + v.z * v.z + v.w * v.w;
                v.x = f2tf32f(v.x); v.y = f2tf32f(v.y);
                v.z = f2tf32f(v.z); v.w = f2tf32f(v.w);
                *(float4*)(Ak + r * DQ_P + p * 16 + i * 4) = v;
            }
            ss += __shfl_xor_sync(0xffffffffu, ss, 1);
            ss += __shfl_xor_sync(0xffffffffu, ss, 2);
            if (p == 0) diag[r] = ss * 0.0625f;
        }
        {
            const float* vsrc = V + ((long)(b * NK + s0)) * DMODEL + h * DHD;
#pragma unroll
            for (int i = 0; i < 4; i++) {
                int linear = i * 256 + t;
                int s = linear >> 4, c4 = linear & 15;
                float4 v = *(const float4*)(vsrc + (long)s * DMODEL + c4 * 4);
                v.x = f2tf32f(v.x); v.y = f2tf32f(v.y);
                v.z = f2tf32f(v.z); v.w = f2tf32f(v.w);
                *(float4*)(Bv + s * C2_VP + c4 * 4) = v;
            }
        }
        __syncthreads();

        float dacc[4][4][4];
#pragma unroll
        for (int i = 0; i < 4; i++)
#pragma unroll
            for (int j = 0; j < 4; j++)
#pragma unroll
                for (int r = 0; r < 4; r++) dacc[i][j][r] = 0.f;

#pragma unroll
        for (int ks = 0; ks < 64; ks += 8) {
            uint32_t af[4][4], bf[4][2];
#pragma unroll
            for (int i = 0; i < 4; i++) {
                unsigned addr = akU + (unsigned)(((i * 16 + ldsmRow) * DQ_P
                                                  + ks + ldsmK) * 4);
                LDSM4(af[i][0], af[i][1], af[i][2], af[i][3], addr);
            }
#pragma unroll
            for (int jj = 0; jj < 2; jj++) {
                unsigned addr = bpU + (unsigned)(((warp * 32 + jj * 16 + ldsmRow) * DQ_P
                                                  + ks + ldsmK) * 4);
                uint32_t r0, r1, r2, r3;
                LDSM4(r0, r1, r2, r3, addr);
                bf[jj * 2][0] = r0; bf[jj * 2 + 1][0] = r1;
                bf[jj * 2][1] = r2; bf[jj * 2 + 1][1] = r3;
            }
#pragma unroll
            for (int i = 0; i < 4; i++)
#pragma unroll
                for (int j = 0; j < 4; j++)
                    MMA_TF32(dacc[i][j], af[i], bf[j]);
        }

#pragma unroll
        for (int i = 0; i < 4; i++) {
            const int rA = i * 16 + gid;
            const int rB = rA + 8;
            const float shA = diag[rA] + stab;
            const float shB = diag[rB] + stab;
#pragma unroll
            for (int j = 0; j < 4; j++) {
                const int col = warp * 32 + j * 8 + tig * 2;
                float p0 = RATIO * (__expf(dacc[i][j][0] * DN_SCALE - shA) + EPSF);
                float p1 = RATIO * (__expf(dacc[i][j][1] * DN_SCALE - shA) + EPSF);
                float p2 = RATIO * (__expf(dacc[i][j][2] * DN_SCALE - shB) + EPSF);
                float p3 = RATIO * (__expf(dacc[i][j][3] * DN_SCALE - shB) + EPSF);
                kcAcc[j][0] += p0 + p2;
                kcAcc[j][1] += p1 + p3;
                *(float2*)(Ph + rA * C2_FP + col) = make_float2(f2tf32f(p0), f2tf32f(p1));
                *(float2*)(Ph + rB * C2_FP + col) = make_float2(f2tf32f(p2), f2tf32f(p3));
            }
        }
        __syncthreads();

#pragma unroll
        for (int ks = 0; ks < 64; ks += 8) {
            uint32_t af[4][4], bf[4][2];
#pragma unroll
            for (int i = 0; i < 4; i++) {
                const int mB = warpM * 64 + i * 16;
                af[i][0] = PhU[(ks + tig) * C2_FP + mB + gid];
                af[i][1] = PhU[(ks + tig) * C2_FP + mB + gid + 8];
                af[i][2] = PhU[(ks + tig + 4) * C2_FP + mB + gid];
                af[i][3] = PhU[(ks + tig + 4) * C2_FP + mB + gid + 8];
            }
#pragma unroll
            for (int j = 0; j < 4; j++) {
                const int nB = warpN * 32 + j * 8;
                bf[j][0] = BvU[(ks + tig) * C2_VP + nB + gid];
                bf[j][1] = BvU[(ks + tig + 4) * C2_VP + nB + gid];
            }
#pragma unroll
            for (int i = 0; i < 4; i++)
#pragma unroll
                for (int j = 0; j < 4; j++)
                    MMA_TF32(ctxAcc[i][j], af[i], bf[j]);
        }
    }

    float* cp = ctxPart + ((long)(split * BHN + bh)) * MF * DHD;
#pragma unroll
    for (int i = 0; i < 4; i++) {
        const int m = warpM * 64 + i * 16 + gid;
#pragma unroll
        for (int j = 0; j < 4; j++) {
            const int d = warpN * 32 + j * 8 + tig * 2;
            *(float2*)(cp + (long)m * DHD + d) = make_float2(ctxAcc[i][j][0], ctxAcc[i][j][1]);
            *(float2*)(cp + (long)(m + 8) * DHD + d) = make_float2(ctxAcc[i][j][2], ctxAcc[i][j][3]);
        }
    }
#pragma unroll
    for (int j = 0; j < 4; j++) {
#pragma unroll
        for (int p = 0; p < 2; p++) {
            float v = kcAcc[j][p];
            v += __shfl_xor_sync(0xffffffffu, v, 4);
            v += __shfl_xor_sync(0xffffffffu, v, 8);
            v += __shfl_xor_sync(0xffffffffu, v, 16);
            if (gid == 0) {
                const int col = warp * 32 + j * 8 + tig * 2 + p;
                kcPart[((long)(split * BHN + bh)) * MF + col] = v;
            }
        }
    }
}

// ---------------------------------------------------------------------------
// dashq_phi (proven R13): dashQ GEMM + rowmax + phi + denominator.
// ---------------------------------------------------------------------------
__global__ __launch_bounds__(256) void dashq_phi(
    const float* __restrict__ Q, const float* __restrict__ proj,
    const float* __restrict__ kc, float* __restrict__ qp,
    float* __restrict__ denom)
{
    extern __shared__ float sm[];
    float* As = sm;                        // 128 * 68
    float* Bs = As + 128 * DQ_P;           // 256 * 68
    float* diag = Bs + 256 * DQ_P;         // 128
    float* kcS = diag + 128;               // 256
    float* redA = kcS + 256;               // 128 * 4
    float* redB = redA + 512;              // 128 * 4

    const int rt = blockIdx.x, bh = blockIdx.y;
    const int b = bh >> 3, h = bh & 7;
    const int n0 = rt * 128;
    const int t = threadIdx.x;
    const int lane = t & 31, warp = t >> 5;
    const int warpM = warp >> 2;          // 0..1
    const int warpN = warp & 3;           // 0..3
    const int gid = lane >> 2, tig = lane & 3;
    const unsigned asU = (unsigned)__cvta_generic_to_shared(As);
    const unsigned bsU = (unsigned)__cvta_generic_to_shared(Bs);
    const int ldsmRow = (lane & 7) + ((lane >> 3) & 1) * 8;
    const int ldsmK   = (lane >> 4) * 4;

#pragma unroll
    for (int i = 0; i < 8; i++) {
        int linear = i * 256 + t;
        int n = linear >> 4, c4 = linear & 15;
        float4 v = *(const float4*)(Q + ((long)(b * NQ + n0 + n)) * DMODEL + h * DHD + c4 * 4);
        v.x = f2tf32f(v.x); v.y = f2tf32f(v.y);
        v.z = f2tf32f(v.z); v.w = f2tf32f(v.w);
        *(float4*)(As + n * DQ_P + c4 * 4) = v;
    }
#pragma unroll
    for (int i = 0; i < 16; i++) {
        int linear = i * 256 + t;
        int r = linear >> 4, c4 = linear & 15;
        float4 v = *(const float4*)(proj + (long)r * DHD + c4 * 4);
        v.x = f2tf32f(v.x); v.y = f2tf32f(v.y);
        v.z = f2tf32f(v.z); v.w = f2tf32f(v.w);
        *(float4*)(Bs + r * DQ_P + c4 * 4) = v;
    }
    {
        int r = t >> 1, half = t & 1;
        const float* qr = Q + ((long)(b * NQ + n0 + r)) * DMODEL + h * DHD + half * 32;
        float ss = 0.f;
#pragma unroll
        for (int i = 0; i < 8; i++) {
            float4 v = *(const float4*)(qr + i * 4);
            ss += v.x * v.x + v.y * v.y + v.z * v.z + v.w * v.w;
        }
        ss += __shfl_xor_sync(0xffffffffu, ss, 1);
        if (half == 0) diag[r] = ss * 0.0625f;
    }
    kcS[t] = kc[bh * MF + t];
    __syncthreads();

    float acc[4][8][4];
#pragma unroll
    for (int i = 0; i < 4; i++)
#pragma unroll
        for (int j = 0; j < 8; j++)
#pragma unroll
            for (int r = 0; r < 4; r++) acc[i][j][r] = 0.f;

#pragma unroll
    for (int ks = 0; ks < 64; ks += 8) {
        uint32_t af[4][4], bf[8][2];
#pragma unroll
        for (int i = 0; i < 4; i++) {
            unsigned addr = asU + (unsigned)(((warpM * 64 + i * 16 + ldsmRow) * DQ_P
                                              + ks + ldsmK) * 4);
            LDSM4(af[i][0], af[i][1], af[i][2], af[i][3], addr);
        }
#pragma unroll
        for (int jj = 0; jj < 4; jj++) {
            unsigned addr = bsU + (unsigned)(((warpN * 64 + jj * 16 + ldsmRow) * DQ_P
                                              + ks + ldsmK) * 4);
            uint32_t r0, r1, r2, r3;
            LDSM4(r0, r1, r2, r3, addr);
            bf[jj * 2][0] = r0; bf[jj * 2 + 1][0] = r1;
            bf[jj * 2][1] = r2; bf[jj * 2 + 1][1] = r3;
        }
#pragma unroll
        for (int i = 0; i < 4; i++)
#pragma unroll
            for (int j = 0; j < 8; j++)
                MMA_TF32(acc[i][j], af[i], bf[j]);
    }

#pragma unroll
    for (int i = 0; i < 4; i++)
#pragma unroll
        for (int j = 0; j < 8; j++)
#pragma unroll
            for (int r = 0; r < 4; r++) acc[i][j][r] *= DN_SCALE;

#pragma unroll
    for (int i = 0; i < 4; i++) {
        const int rA = warpM * 64 + i * 16 + gid;
        float mA = -1e30f, mB = -1e30f;
#pragma unroll
        for (int j = 0; j < 8; j++) {
            mA = fmaxf(mA, fmaxf(acc[i][j][0], acc[i][j][1]));
            mB = fmaxf(mB, fmaxf(acc[i][j][2], acc[i][j][3]));
        }
        mA = fmaxf(mA, __shfl_xor_sync(0xffffffffu, mA, 1));
        mA = fmaxf(mA, __shfl_xor_sync(0xffffffffu, mA, 2));
        mB = fmaxf(mB, __shfl_xor_sync(0xffffffffu, mB, 1));
        mB = fmaxf(mB, __shfl_xor_sync(0xffffffffu, mB, 2));
        if (tig == 0) {
            redA[rA * 4 + warpN] = mA;
            redA[(rA + 8) * 4 + warpN] = mB;
        }
    }
    __syncthreads();

#pragma unroll
    for (int i = 0; i < 4; i++) {
        const int rA = warpM * 64 + i * 16 + gid;
        const int rB = rA + 8;
        const float rmA = fmaxf(fmaxf(redA[rA * 4], redA[rA * 4 + 1]),
                                fmaxf(redA[rA * 4 + 2], redA[rA * 4 + 3]));
        const float rmB = fmaxf(fmaxf(redA[rB * 4], redA[rB * 4 + 1]),
                                fmaxf(redA[rB * 4 + 2], redA[rB * 4 + 3]));
        const float shA = diag[rA] + rmA;
        const float shB = diag[rB] + rmB;
        float dA = 0.f, dB = 0.f;
#pragma unroll
        for (int j = 0; j < 8; j++) {
            const int col = warpN * 64 + (j >> 1) * 16 + (j & 1) * 8 + tig * 2;
            float p0 = RATIO * (__expf(acc[i][j][0] - shA) + EPSF);
            float p1 = RATIO * (__expf(acc[i][j][1] - shA) + EPSF);
            float p2 = RATIO * (__expf(acc[i][j][2] - shB) + EPSF);
            float p3 = RATIO * (__expf(acc[i][j][3] - shB) + EPSF);
            float2 kv = *(const float2*)(kcS + col);
            dA += p0 * kv.x + p1 * kv.y;
            dB += p2 * kv.x + p3 * kv.y;
            *(float2*)(qp + ((long)bh * NQ + n0 + rA) * MF + col) = make_float2(p0, p1);
            *(float2*)(qp + ((long)bh * NQ + n0 + rB) * MF + col) = make_float2(p2, p3);
        }
        dA += __shfl_xor_sync(0xffffffffu, dA, 1);
        dA += __shfl_xor_sync(0xffffffffu, dA, 2);
        dB += __shfl_xor_sync(0xffffffffu, dB, 1);
        dB += __shfl_xor_sync(0xffffffffu, dB, 2);
        if (tig == 0) {
            redB[rA * 4 + warpN] = dA;
            redB[rB * 4 + warpN] = dB;
        }
    }
    __syncthreads();
    if (warpN == 0 && tig == 0) {
#pragma unroll
        for (int i = 0; i < 4; i++) {
            const int rA = warpM * 64 + i * 16 + gid;
            const int rB = rA + 8;
            denom[(long)bh * NQ + n0 + rA] =
                (redB[rA * 4] + redB[rA * 4 + 1]) + (redB[rA * 4 + 2] + redB[rA * 4 + 3]);
            denom[(long)bh * NQ + n0 + rB] =
                (redB[rB * 4] + redB[rB * 4 + 1]) + (redB[rB * 4 + 2] + redB[rB * 4 + 3]);
        }
    }
}

// -------------------- small kernels ----------------------------------------
__global__ void init_stab(unsigned* __restrict__ s) {
    s[threadIdx.x] = 0u;
}

// float -> half streaming conversion (2 elems per thread)
__global__ void to_half(const float2* __restrict__ in, __half2* __restrict__ out) {
    long i = (long)blockIdx.x * 256 + threadIdx.x;
    float2 v = in[i];
    out[i] = __floats2half2_rn(v.x, v.y);
}

// W [K=512][N=512] fp32 -> WT half [N][K]
__global__ void transpose_half(const float* __restrict__ in, __half* __restrict__ out) {
    __shared__ float t[32][33];
    int bx = blockIdx.x * 32, by = blockIdx.y * 32;
    int tx = threadIdx.x;
    for (int i = threadIdx.y; i < 32; i += 8)
        t[i][tx] = in[(by + i) * DMODEL + bx + tx];
    __syncthreads();
    for (int i = threadIdx.y; i < 32; i += 8)
        out[(long)(bx + i) * DMODEL + by + tx] = __float2half(t[tx][i]);
}

__global__ void kc_final8(const float* __restrict__ part, float* __restrict__ kc) {
    int bh = blockIdx.x, t = threadIdx.x;
    float s = 0.f;
#pragma unroll
    for (int sp = 0; sp < 8; sp++) s += part[((long)(sp * BHN + bh)) * MF + t];
    kc[bh * MF + t] = s;
}

__global__ void reduce_ctx8(const float* __restrict__ p, float* __restrict__ c) {
    int i = blockIdx.x * 256 + threadIdx.x;   // 1048576 total
    float s0 = p[i] + p[i + 1 * 1048576];
    float s1 = p[i + 2 * 1048576] + p[i + 3 * 1048576];
    float s2 = p[i + 4 * 1048576] + p[i + 5 * 1048576];
    float s3 = p[i + 6 * 1048576] + p[i + 7 * 1048576];
    c[i] = (s0 + s1) + (s2 + s3);
}

// ---------------------------------------------------------------------------
extern "C" void kernel_launch(void* const* d_in, const int* in_sizes, int n_in,
                              void* d_out, int out_size)
{
    (void)in_sizes; (void)n_in; (void)out_size;
    const float* x       = (const float*)d_in[0];
    const float* context = (const float*)d_in[1];
    const float* Wq      = (const float*)d_in[2];
    const float* Wk      = (const float*)d_in[3];
    const float* Wv      = (const float*)d_in[4];
    const float* Wo      = (const float*)d_in[5];
    const float* bo      = (const float*)d_in[6];
    const float* proj    = (const float*)d_in[7];
    float* out = (float*)d_out;

    float *Q, *K, *V, *qp, *kcPart, *kc, *denom, *ctxPart, *ctx;
    __half *xH, *ctxH, *WqT, *WkT, *WvT, *WoT, *attnH;
    unsigned* stabEnc;
    cudaGetSymbolAddress((void**)&Q, g_Q);
    cudaGetSymbolAddress((void**)&K, g_K);
    cudaGetSymbolAddress((void**)&V, g_V);
    cudaGetSymbolAddress((void**)&xH, g_xH);
    cudaGetSymbolAddress((void**)&ctxH, g_ctxH);
    cudaGetSymbolAddress((void**)&WqT, g_WqT);
    cudaGetSymbolAddress((void**)&WkT, g_WkT);
    cudaGetSymbolAddress((void**)&WvT, g_WvT);
    cudaGetSymbolAddress((void**)&WoT, g_WoT);
    cudaGetSymbolAddress((void**)&attnH, g_attnH);
    cudaGetSymbolAddress((void**)&qp, g_qp);
    cudaGetSymbolAddress((void**)&stabEnc, g_stabEnc);
    cudaGetSymbolAddress((void**)&kcPart, g_kcPart);
    cudaGetSymbolAddress((void**)&kc, g_kc);
    cudaGetSymbolAddress((void**)&denom, g_denom);
    cudaGetSymbolAddress((void**)&ctxPart, g_ctxPart);
    cudaGetSymbolAddress((void**)&ctx, g_ctx);

    const int SM_DK = (128 * DQ_P + 256 * DQ_P) * 4;                      // 104448
    const int SM_C2 = (256 * DQ_P + 64 * DQ_P + 64 * C2_FP + 64 * C2_VP + 64) * 4; // 173312
    const int SM_DQ = (128 * DQ_P + 256 * DQ_P + 128 + 256 + 1024) * 4;   // 110080
    cudaFuncSetAttribute(dashk_max, cudaFuncAttributeMaxDynamicSharedMemorySize, SM_DK);
    cudaFuncSetAttribute(ctx_fused2, cudaFuncAttributeMaxDynamicSharedMemorySize, SM_C2);
    cudaFuncSetAttribute(dashq_phi, cudaFuncAttributeMaxDynamicSharedMemorySize, SM_DQ);

    init_stab<<<1, BHN>>>(stabEnc);

    // half conversions
    to_half<<<8192, 256>>>((const float2*)x, (__half2*)xH);         // 4M
    to_half<<<32768, 256>>>((const float2*)context, (__half2*)ctxH); // 16M
    transpose_half<<<dim3(16, 16), dim3(32, 8)>>>(Wq, WqT);
    transpose_half<<<dim3(16, 16), dim3(32, 8)>>>(Wk, WkT);
    transpose_half<<<dim3(16, 16), dim3(32, 8)>>>(Wv, WvT);
    transpose_half<<<dim3(16, 16), dim3(32, 8)>>>(Wo, WoT);

    // Q/K/V projections (fp16 cp.async pipeline)
    tmma2h_cp<<<dim3(4, 64), 128>>>(xH, WqT, Q, nullptr, DMODEL);
    tmma2h_cp<<<dim3(4, 256), 128>>>(ctxH, WkT, K, nullptr, DMODEL);
    tmma2h_cp<<<dim3(4, 256), 128>>>(ctxH, WvT, V, nullptr, DMODEL);

    // key stabilizer max (no dash store)
    dashk_max<<<dim3(32, 64), 256, SM_DK>>>(K, proj, stabEnc);

    // fused dash-recompute + phi + kc + ctx
    ctx_fused2<<<dim3(8, 64), 256, SM_C2>>>(K, V, proj, stabEnc, ctxPart, kcPart);
    reduce_ctx8<<<4096, 256>>>(ctxPart, ctx);
    kc_final8<<<BHN, 256>>>(kcPart, kc);

    // fused dashQ + phi_q + denominator
    dashq_phi<<<dim3(8, 64), 256, SM_DQ>>>(Q, proj, kc, qp, denom);

    // attn = (qp @ ctx) / denom, merged-head layout, HALF out (z = b*8 + h)
    tmma2<64, false><<<dim3(1, 8, BHN), 128>>>(qp, ctx, attnH, nullptr, denom, nullptr,
        MF, MF, DHD, DMODEL,
        8, 8,
        0, (long)NH * NQ * MF, (long)NQ * MF,
        0, (long)NH * MF * DHD, (long)MF * DHD,
        0, (long)NQ * DMODEL, DHD,
        (long)NH * NQ, NQ, 1.f);

    // final projection + bias (fp16 cp.async pipeline)
    tmma2h_cp<<<dim3(4, 64), 128>>>(attnH, WoT, out, bo, DMODEL);
}

// round 17
// speedup vs baseline: 1.5105x; 1.0867x over previous
#include <cuda_runtime.h>
#include <cuda_fp16.h>
#include <math.h>
#include <stdint.h>

// ---------------------------------------------------------------------------
// Performer FAVOR+ cross-attention forward.
// B=8, Nq=1024, Nk=4096, D=512, H=8, DH=64, M=256
// Round 16: fp16 m16n8k16 dash GEMMs inside dashk_max / ctx_fused2 /
// dashq_phi (same fragment pattern as the validated projection kernel;
// dashk_max and ctx_fused2 produce bitwise-identical dash, so the stabilizer
// stays exact). Projections (fp16 cp.async), ctx/attn (tf32) unchanged (R15,
// 688us).
// ---------------------------------------------------------------------------

#define BATCH 8
#define NQ 1024
#define NK 4096
#define DMODEL 512
#define NH 8
#define DHD 64
#define MF 256
#define BHN 64          // BATCH * NH

#define DN_SCALE 0.35355339059327379f  // 64^-0.25
#define RATIO 0.0625f                  // 256^-0.5
#define EPSF 1e-4f

// -------------------- scratch (static device allocations) ------------------
__device__ float g_Q[BATCH * NQ * DMODEL];          // 16 MB
__device__ float g_K[BATCH * NK * DMODEL];          // 64 MB
__device__ float g_V[BATCH * NK * DMODEL];          // 64 MB
__device__ __half g_xH[BATCH * NQ * DMODEL];        // 8 MB
__device__ __half g_ctxH[BATCH * NK * DMODEL];      // 32 MB
__device__ __half g_WqT[DMODEL * DMODEL];           // half [N][K]
__device__ __half g_WkT[DMODEL * DMODEL];
__device__ __half g_WvT[DMODEL * DMODEL];
__device__ __half g_WoT[DMODEL * DMODEL];
__device__ __half g_attnH[BATCH * NQ * DMODEL];     // 8 MB
__device__ float g_qp[BHN * NQ * MF];               // phi(dashQ), 64 MB
__device__ unsigned g_stabEnc[BHN];
__device__ float g_kcPart[8 * BHN * MF];
__device__ float g_kc[BHN * MF];
__device__ float g_denom[BHN * NQ];
__device__ float g_ctxPart[8 * BHN * MF * DHD];     // 32 MB
__device__ float g_ctx[BHN * MF * DHD];             // 4 MB

// -------------------- helpers ----------------------------------------------
__device__ __forceinline__ uint32_t f2tf32(float f) {
    uint32_t u;
    asm("cvt.rna.tf32.f32 %0, %1;" : "=r"(u) : "f"(f));
    return u;
}
__device__ __forceinline__ float f2tf32f(float f) {
    return __uint_as_float(f2tf32(f));
}
__device__ __forceinline__ uint32_t packh2(float a, float b) {
    __half2 h = __floats2half2_rn(a, b);
    return *(uint32_t*)&h;
}

__device__ __forceinline__ unsigned encodeF(float f) {
    unsigned u = __float_as_uint(f);
    return (u & 0x80000000u) ? ~u : (u | 0x80000000u);
}
__device__ __forceinline__ float decodeF(unsigned e) {
    unsigned u = (e & 0x80000000u) ? (e ^ 0x80000000u) : ~e;
    return __uint_as_float(u);
}

#define MMA_TF32(d, a, b)                                               \
    asm volatile(                                                       \
        "mma.sync.aligned.m16n8k8.row.col.f32.tf32.tf32.f32 "           \
        "{%0,%1,%2,%3}, {%4,%5,%6,%7}, {%8,%9}, {%0,%1,%2,%3};\n"       \
        : "+f"(d[0]), "+f"(d[1]), "+f"(d[2]), "+f"(d[3])                \
        : "r"(a[0]), "r"(a[1]), "r"(a[2]), "r"(a[3]),                   \
          "r"(b[0]), "r"(b[1]))

#define MMA_F16(d, a, b)                                                \
    asm volatile(                                                       \
        "mma.sync.aligned.m16n8k16.row.col.f32.f16.f16.f32 "            \
        "{%0,%1,%2,%3}, {%4,%5,%6,%7}, {%8,%9}, {%0,%1,%2,%3};\n"       \
        : "+f"(d[0]), "+f"(d[1]), "+f"(d[2]), "+f"(d[3])                \
        : "r"(a[0]), "r"(a[1]), "r"(a[2]), "r"(a[3]),                   \
          "r"(b[0]), "r"(b[1]))

#define LDSM4(r0, r1, r2, r3, addr)                                     \
    asm volatile(                                                       \
        "ldmatrix.sync.aligned.m8n8.x4.shared.b16 {%0,%1,%2,%3}, [%4];" \
        : "=r"(r0), "=r"(r1), "=r"(r2), "=r"(r3) : "r"(addr))

__device__ __forceinline__ void cpAsync16(uint32_t dst, const void* src) {
    asm volatile("cp.async.cg.shared.global [%0], [%1], 16;\n"
                 :: "r"(dst), "l"(src));
}
#define CP_COMMIT() asm volatile("cp.async.commit_group;\n")
#define CP_WAIT1()  asm volatile("cp.async.wait_group 1;\n")

__device__ __forceinline__ float warpRedMax(float v) {
#pragma unroll
    for (int o = 16; o > 0; o >>= 1) v = fmaxf(v, __shfl_xor_sync(0xffffffffu, v, o));
    return v;
}

// ---------------------------------------------------------------------------
// tmma2h_cp (R15, proven): fp16 GEMM, 3-stage cp.async pipeline.
// C = A @ B^T (+ bias). A half [M][512], BT half [N][512].
// ---------------------------------------------------------------------------
#define HP 12                 // fp16 smem row pitch in u32
#define HS (128 * HP)         // u32 per stage per matrix
__global__ __launch_bounds__(128) void tmma2h_cp(
    const __half* __restrict__ A, const __half* __restrict__ BT,
    float* __restrict__ C, const float* __restrict__ bias, int ldc)
{
    __shared__ uint32_t SA[3][128][HP];
    __shared__ uint32_t SB[3][128][HP];

    const int tid = threadIdx.x;
    const int lane = tid & 31;
    const int warp = tid >> 5;
    const int warpM = warp >> 1;
    const int warpN = warp & 1;
    const int gid = lane >> 2;
    const int tig = lane & 3;

    const int m0 = blockIdx.y * 128;
    const int n0 = blockIdx.x * 128;

    const unsigned saU = (unsigned)__cvta_generic_to_shared(&SA[0][0][0]);
    const unsigned sbU = (unsigned)__cvta_generic_to_shared(&SB[0][0][0]);
    const int lr = lane & 15;
    const int lc = (lane >> 4) * 4;

    float acc[4][8][4];
#pragma unroll
    for (int i = 0; i < 4; i++)
#pragma unroll
        for (int j = 0; j < 8; j++)
#pragma unroll
            for (int r = 0; r < 4; r++) acc[i][j][r] = 0.f;

    const __half* Arow = A + (long)(m0 + tid) * DMODEL;
    const __half* Brow = BT + (long)(n0 + tid) * DMODEL;

    auto issueStage = [&](int kt, int s) {
        const __half* Ap = Arow + kt * 16;
        const uint32_t da = saU + (uint32_t)(s * HS + tid * HP) * 4u;
        cpAsync16(da, Ap);
        cpAsync16(da + 16, Ap + 8);
        const __half* Bp = Brow + kt * 16;
        const uint32_t db = sbU + (uint32_t)(s * HS + tid * HP) * 4u;
        cpAsync16(db, Bp);
        cpAsync16(db + 16, Bp + 8);
    };

    auto computeStage = [&](int s) {
        uint32_t af[4][4];
        uint32_t bf[8][2];
#pragma unroll
        for (int i = 0; i < 4; i++) {
            unsigned addr = saU + (unsigned)((s * HS +
                (warpM * 64 + i * 16 + lr) * HP + lc) * 4);
            LDSM4(af[i][0], af[i][1], af[i][2], af[i][3], addr);
        }
#pragma unroll
        for (int jj = 0; jj < 4; jj++) {
            unsigned addr = sbU + (unsigned)((s * HS +
                (warpN * 64 + jj * 16 + lr) * HP + lc) * 4);
            uint32_t r0, r1, r2, r3;
            LDSM4(r0, r1, r2, r3, addr);
            bf[jj * 2][0] = r0; bf[jj * 2 + 1][0] = r1;
            bf[jj * 2][1] = r2; bf[jj * 2 + 1][1] = r3;
        }
#pragma unroll
        for (int i = 0; i < 4; i++)
#pragma unroll
            for (int j = 0; j < 8; j++)
                MMA_F16(acc[i][j], af[i], bf[j]);
    };

    const int ntiles = DMODEL / 16;
    issueStage(0, 0); CP_COMMIT();
    issueStage(1, 1); CP_COMMIT();
    for (int kt = 0; kt < ntiles; kt++) {
        CP_WAIT1();
        __syncthreads();
        if (kt + 2 < ntiles) issueStage(kt + 2, (kt + 2) % 3);
        CP_COMMIT();
        computeStage(kt % 3);
    }

#pragma unroll
    for (int i = 0; i < 4; i++) {
        const int rL = m0 + warpM * 64 + i * 16 + gid;
#pragma unroll
        for (int j = 0; j < 8; j++) {
            const int col = n0 + warpN * 64 + (j >> 1) * 16 + (j & 1) * 8 + tig * 2;
            float v0 = acc[i][j][0], v1 = acc[i][j][1];
            float v2 = acc[i][j][2], v3 = acc[i][j][3];
            if (bias) {
                float2 bv = *(const float2*)(bias + col);
                v0 += bv.x; v1 += bv.y; v2 += bv.x; v3 += bv.y;
            }
            *(float2*)(C + (long)rL * ldc + col) = make_float2(v0, v1);
            *(float2*)(C + (long)(rL + 8) * ldc + col) = make_float2(v2, v3);
        }
    }
}

// ---------------------------------------------------------------------------
// tmma2 (proven): TF32 GEMM, used (BN=64) for attn = (qp@ctx)/denom, half out.
// ---------------------------------------------------------------------------
template <int BN, bool TRANSA>
__global__ __launch_bounds__(128, 2) void tmma2(
    const float* __restrict__ A, const float* __restrict__ B,
    __half* __restrict__ Ch, const float* __restrict__ bias,
    const float* __restrict__ rowdiv, unsigned* __restrict__ maxOut,
    int K, int lda, int ldb, int ldc,
    int d2, int d3,
    long oA1, long oA2, long oA3,
    long oB1, long oB2, long oB3,
    long oC1, long oC2, long oC3,
    long oD2, long oD3,
    float alpha)
{
    constexpr int WN = BN / 2;
    constexpr int NJ = WN / 8;
    constexpr int NJJ = WN / 16;

    {
        int z = blockIdx.z;
        int z3 = z % d3;
        int zq = z / d3;
        int z2 = zq % d2;
        int z1 = zq / d2;
        A += z1 * oA1 + z2 * oA2 + z3 * oA3;
        B += z1 * oB1 + z2 * oB2 + z3 * oB3;
        Ch += z1 * oC1 + z2 * oC2 + z3 * oC3;
        if (rowdiv) rowdiv += z2 * oD2 + z3 * oD3;
    }

    __shared__ uint32_t As[2][128][20];
    __shared__ uint32_t Bs[2][BN][20];
    __shared__ float redMax[4];

    const int tid = threadIdx.x;
    const int lane = tid & 31;
    const int warp = tid >> 5;
    const int warpM = warp >> 1;
    const int warpN = warp & 1;
    const int gid = lane >> 2;
    const int tig = lane & 3;

    const int m0 = blockIdx.y * 128;
    const int n0 = blockIdx.x * BN;

    const unsigned asU = (unsigned)__cvta_generic_to_shared(&As[0][0][0]);
    const unsigned bsU = (unsigned)__cvta_generic_to_shared(&Bs[0][0][0]);
    const int ldsmRow = (lane & 7) + ((lane >> 3) & 1) * 8;
    const int ldsmK   = (lane >> 4) * 4;

    float acc[4][NJ][4];
#pragma unroll
    for (int i = 0; i < 4; i++)
#pragma unroll
        for (int j = 0; j < NJ; j++)
#pragma unroll
            for (int r = 0; r < 4; r++) acc[i][j][r] = 0.f;

    const int ntiles = K >> 4;
    float pa[16], pb[16];

    auto loadTile = [&](int k0) {
        if (!TRANSA) {
            const float* Ap = A + (long)(m0 + tid) * lda + k0;
            *(float4*)(pa + 0)  = *(const float4*)(Ap + 0);
            *(float4*)(pa + 4)  = *(const float4*)(Ap + 4);
            *(float4*)(pa + 8)  = *(const float4*)(Ap + 8);
            *(float4*)(pa + 12) = *(const float4*)(Ap + 12);
        } else {
            const float* Ap = A + (long)k0 * lda + m0 + tid;
#pragma unroll
            for (int k = 0; k < 16; k++) pa[k] = Ap[(long)k * lda];
        }
        if (BN == 128) {
            const float* Bp = B + (long)k0 * ldb + n0 + tid;
#pragma unroll
            for (int k = 0; k < 16; k++) pb[k] = Bp[(long)k * ldb];
        } else {
            const float* Bp = B + (long)(k0 + (tid >> 6) * 8) * ldb + n0 + (tid & 63);
#pragma unroll
            for (int k = 0; k < 8; k++) pb[k] = Bp[(long)k * ldb];
        }
    };

    auto storeTile = [&](int buf) {
#pragma unroll
        for (int g = 0; g < 4; g++) {
            uint4 u;
            u.x = f2tf32(pa[g * 4 + 0]); u.y = f2tf32(pa[g * 4 + 1]);
            u.z = f2tf32(pa[g * 4 + 2]); u.w = f2tf32(pa[g * 4 + 3]);
            *(uint4*)&As[buf][tid][g * 4] = u;
        }
        if (BN == 128) {
#pragma unroll
            for (int g = 0; g < 4; g++) {
                uint4 u;
                u.x = f2tf32(pb[g * 4 + 0]); u.y = f2tf32(pb[g * 4 + 1]);
                u.z = f2tf32(pb[g * 4 + 2]); u.w = f2tf32(pb[g * 4 + 3]);
                *(uint4*)&Bs[buf][tid][g * 4] = u;
            }
        } else {
            const int n = tid & 63, kg = (tid >> 6) * 8;
#pragma unroll
            for (int g = 0; g < 2; g++) {
                uint4 u;
                u.x = f2tf32(pb[g * 4 + 0]); u.y = f2tf32(pb[g * 4 + 1]);
                u.z = f2tf32(pb[g * 4 + 2]); u.w = f2tf32(pb[g * 4 + 3]);
                *(uint4*)&Bs[buf][n][kg + g * 4] = u;
            }
        }
    };

    auto computeTile = [&](int buf) {
#pragma unroll
        for (int ks = 0; ks < 16; ks += 8) {
            uint32_t af[4][4];
            uint32_t bf[NJ][2];
#pragma unroll
            for (int i = 0; i < 4; i++) {
                unsigned addr = asU + (unsigned)((buf * 128 * 20 +
                    (warpM * 64 + i * 16 + ldsmRow) * 20 + ks + ldsmK) * 4);
                LDSM4(af[i][0], af[i][1], af[i][2], af[i][3], addr);
            }
#pragma unroll
            for (int jj = 0; jj < NJJ; jj++) {
                unsigned addr = bsU + (unsigned)((buf * BN * 20 +
                    (warpN * WN + jj * 16 + ldsmRow) * 20 + ks + ldsmK) * 4);
                uint32_t r0, r1, r2, r3;
                LDSM4(r0, r1, r2, r3, addr);
                bf[jj * 2][0] = r0; bf[jj * 2 + 1][0] = r1;
                bf[jj * 2][1] = r2; bf[jj * 2 + 1][1] = r3;
            }
#pragma unroll
            for (int i = 0; i < 4; i++)
#pragma unroll
                for (int j = 0; j < NJ; j++)
                    MMA_TF32(acc[i][j], af[i], bf[j]);
        }
    };

    loadTile(0);
    storeTile(0);
    __syncthreads();
    for (int kt = 0; kt < ntiles; kt++) {
        const int buf = kt & 1;
        const bool more = (kt + 1) < ntiles;
        if (more) loadTile((kt + 1) << 4);
        computeTile(buf);
        if (more) storeTile(buf ^ 1);
        __syncthreads();
    }

    float vmax = -1e30f;
#pragma unroll
    for (int i = 0; i < 4; i++) {
        const int rL = m0 + warpM * 64 + i * 16 + gid;
        float dv0 = 1.f, dv1 = 1.f;
        if (rowdiv) { dv0 = 1.0f / rowdiv[rL]; dv1 = 1.0f / rowdiv[rL + 8]; }
#pragma unroll
        for (int j = 0; j < NJ; j++) {
            const int col = n0 + warpN * WN + (j >> 1) * 16 + (j & 1) * 8 + tig * 2;
            float v0 = alpha * acc[i][j][0], v1 = alpha * acc[i][j][1];
            float v2 = alpha * acc[i][j][2], v3 = alpha * acc[i][j][3];
            if (maxOut)
                vmax = fmaxf(vmax, fmaxf(fmaxf(v0, v1), fmaxf(v2, v3)));
            if (bias) {
                float2 bv = *(const float2*)(bias + col);
                v0 += bv.x; v1 += bv.y; v2 += bv.x; v3 += bv.y;
            }
            v0 *= dv0; v1 *= dv0; v2 *= dv1; v3 *= dv1;
            *(__half2*)(Ch + (long)rL * ldc + col) = __floats2half2_rn(v0, v1);
            *(__half2*)(Ch + (long)(rL + 8) * ldc + col) = __floats2half2_rn(v2, v3);
        }
    }

    if (maxOut) {
        vmax = warpRedMax(vmax);
        if (lane == 0) redMax[warp] = vmax;
        __syncthreads();
        if (tid == 0) {
            float m = fmaxf(fmaxf(redMax[0], redMax[1]), fmaxf(redMax[2], redMax[3]));
            atomicMax(maxOut + blockIdx.z, encodeF(m));
        }
    }
}

// ---------------------------------------------------------------------------
// dashk_max (fp16 dash): dash GEMM in registers; global max only, no store.
// A = K rows fp16 [128][36], B = proj fp16 [256][36]; m16n8k16 fragments.
// ---------------------------------------------------------------------------
#define HPD 36                 // 64 halfs (32 u32) + 4 u32 pad
__global__ __launch_bounds__(256) void dashk_max(
    const float* __restrict__ Km, const float* __restrict__ proj,
    unsigned* __restrict__ stabEnc)
{
    extern __shared__ uint32_t smu[];
    uint32_t* AsH = smu;               // [128][36]
    uint32_t* BsH = smu + 128 * HPD;   // [256][36]
    __shared__ float red[8];

    const int rt = blockIdx.x, bh = blockIdx.y;
    const int b = bh >> 3, h = bh & 7;
    const int s0 = rt * 128;
    const int t = threadIdx.x;
    const int lane = t & 31, warp = t >> 5;
    const int warpM = warp >> 2;          // 0..1
    const int warpN = warp & 3;           // 0..3
    const unsigned asU = (unsigned)__cvta_generic_to_shared(AsH);
    const unsigned bsU = (unsigned)__cvta_generic_to_shared(BsH);
    const int lr = lane & 15;
    const int lc = (lane >> 4) * 4;

    // stage A = K rows [128][64] fp16
#pragma unroll
    for (int i = 0; i < 8; i++) {
        int linear = i * 256 + t;
        int n = linear >> 4, c4 = linear & 15;
        float4 v = *(const float4*)(Km + ((long)(b * NK + s0 + n)) * DMODEL + h * DHD + c4 * 4);
        uint2 u = make_uint2(packh2(v.x, v.y), packh2(v.z, v.w));
        *(uint2*)&AsH[n * HPD + c4 * 2] = u;
    }
    // stage B = proj [256][64] fp16
#pragma unroll
    for (int i = 0; i < 16; i++) {
        int linear = i * 256 + t;
        int r = linear >> 4, c4 = linear & 15;
        float4 v = *(const float4*)(proj + (long)r * DHD + c4 * 4);
        uint2 u = make_uint2(packh2(v.x, v.y), packh2(v.z, v.w));
        *(uint2*)&BsH[r * HPD + c4 * 2] = u;
    }
    __syncthreads();

    float acc[4][8][4];
#pragma unroll
    for (int i = 0; i < 4; i++)
#pragma unroll
        for (int j = 0; j < 8; j++)
#pragma unroll
            for (int r = 0; r < 4; r++) acc[i][j][r] = 0.f;

#pragma unroll
    for (int g = 0; g < 4; g++) {
        uint32_t af[4][4], bf[8][2];
#pragma unroll
        for (int i = 0; i < 4; i++) {
            unsigned addr = asU + (unsigned)(((warpM * 64 + i * 16 + lr) * HPD
                                              + g * 8 + lc) * 4);
            LDSM4(af[i][0], af[i][1], af[i][2], af[i][3], addr);
        }
#pragma unroll
        for (int jj = 0; jj < 4; jj++) {
            unsigned addr = bsU + (unsigned)(((warpN * 64 + jj * 16 + lr) * HPD
                                              + g * 8 + lc) * 4);
            uint32_t r0, r1, r2, r3;
            LDSM4(r0, r1, r2, r3, addr);
            bf[jj * 2][0] = r0; bf[jj * 2 + 1][0] = r1;
            bf[jj * 2][1] = r2; bf[jj * 2 + 1][1] = r3;
        }
#pragma unroll
        for (int i = 0; i < 4; i++)
#pragma unroll
            for (int j = 0; j < 8; j++)
                MMA_F16(acc[i][j], af[i], bf[j]);
    }

    float vmax = -1e30f;
#pragma unroll
    for (int i = 0; i < 4; i++)
#pragma unroll
        for (int j = 0; j < 8; j++)
#pragma unroll
            for (int r = 0; r < 4; r++) vmax = fmaxf(vmax, acc[i][j][r]);
    vmax *= DN_SCALE;
    vmax = warpRedMax(vmax);
    if (lane == 0) red[warp] = vmax;
    __syncthreads();
    if (t == 0) {
        float m = red[0];
#pragma unroll
        for (int i = 1; i < 8; i++) m = fmaxf(m, red[i]);
        atomicMax(stabEnc + bh, encodeF(m));
    }
}

// ---------------------------------------------------------------------------
// ctx_fused2 (fp16 dash): recompute dash in-SM (fp16 m16n8k16, fragments
// bitwise-consistent with dashk_max), phi, kc, ctx MMA (tf32) per chunk.
// ---------------------------------------------------------------------------
#define C2_FP 264
#define C2_VP 72
__global__ __launch_bounds__(256) void ctx_fused2(
    const float* __restrict__ Km, const float* __restrict__ V,
    const float* __restrict__ proj, const unsigned* __restrict__ stabEnc,
    float* __restrict__ ctxPart, float* __restrict__ kcPart)
{
    extern __shared__ uint32_t smu[];
    uint32_t* BpH = smu;                   // proj fp16 [256][36] = 9216 u32
    uint32_t* AkH = smu + 9216;            // K chunk fp16 [64][36] = 2304 u32
    float* Ph = (float*)(smu + 11520);     // phi [64][264]
    float* Bv = Ph + 64 * C2_FP;           // V chunk [64][72]
    float* diag = Bv + 64 * C2_VP;         // [64]
    const uint32_t* PhU = (const uint32_t*)Ph;
    const uint32_t* BvU = (const uint32_t*)Bv;

    const int split = blockIdx.x, bh = blockIdx.y;
    const int b = bh >> 3, h = bh & 7;
    const int t = threadIdx.x;
    const int lane = t & 31, warp = t >> 5;
    const int gid = lane >> 2, tig = lane & 3;
    const unsigned bpU = (unsigned)__cvta_generic_to_shared(BpH);
    const unsigned akU = (unsigned)__cvta_generic_to_shared(AkH);
    const int lr = lane & 15;
    const int lc = (lane >> 4) * 4;
    const float stab = decodeF(stabEnc[bh]);
    const int sBase = split * 512;

    const int warpM = warp >> 1;          // 0..3 (ctx phase)
    const int warpN = warp & 1;           // 0..1 (ctx phase)

    // stage proj once [256][64] fp16
#pragma unroll
    for (int i = 0; i < 16; i++) {
        int linear = i * 256 + t;
        int r = linear >> 4, c4 = linear & 15;
        float4 v = *(const float4*)(proj + (long)r * DHD + c4 * 4);
        uint2 u = make_uint2(packh2(v.x, v.y), packh2(v.z, v.w));
        *(uint2*)&BpH[r * HPD + c4 * 2] = u;
    }

    float ctxAcc[4][4][4];
#pragma unroll
    for (int i = 0; i < 4; i++)
#pragma unroll
        for (int j = 0; j < 4; j++)
#pragma unroll
            for (int r = 0; r < 4; r++) ctxAcc[i][j][r] = 0.f;
    float kcAcc[4][2];
#pragma unroll
    for (int j = 0; j < 4; j++) { kcAcc[j][0] = 0.f; kcAcc[j][1] = 0.f; }

    for (int chunk = 0; chunk < 8; chunk++) {
        const int s0 = sBase + chunk * 64;
        __syncthreads();

        // K chunk: fp16 into AkH, unrounded squares -> diag
        {
            const int r = t >> 2, p = t & 3;
            const float* kr = Km + ((long)(b * NK + s0 + r)) * DMODEL + h * DHD + p * 16;
            float ss = 0.f;
            uint32_t hw[8];
#pragma unroll
            for (int i = 0; i < 4; i++) {
                float4 v = *(const float4*)(kr + i * 4);
                ss += v.x * v.x + v.y * v.y + v.z * v.z + v.w * v.w;
                hw[i * 2]     = packh2(v.x, v.y);
                hw[i * 2 + 1] = packh2(v.z, v.w);
            }
            *(uint4*)&AkH[r * HPD + p * 8]     = make_uint4(hw[0], hw[1], hw[2], hw[3]);
            *(uint4*)&AkH[r * HPD + p * 8 + 4] = make_uint4(hw[4], hw[5], hw[6], hw[7]);
            ss += __shfl_xor_sync(0xffffffffu, ss, 1);
            ss += __shfl_xor_sync(0xffffffffu, ss, 2);
            if (p == 0) diag[r] = ss * 0.0625f;
        }
        // V chunk (tf32-rounded, for the tf32 ctx MMA)
        {
            const float* vsrc = V + ((long)(b * NK + s0)) * DMODEL + h * DHD;
#pragma unroll
            for (int i = 0; i < 4; i++) {
                int linear = i * 256 + t;
                int s = linear >> 4, c4 = linear & 15;
                float4 v = *(const float4*)(vsrc + (long)s * DMODEL + c4 * 4);
                v.x = f2tf32f(v.x); v.y = f2tf32f(v.y);
                v.z = f2tf32f(v.z); v.w = f2tf32f(v.w);
                *(float4*)(Bv + s * C2_VP + c4 * 4) = v;
            }
        }
        __syncthreads();

        // dash MMA (fp16): rows = 64 keys, cols = warp's 32 features, K=64
        float dacc[4][4][4];
#pragma unroll
        for (int i = 0; i < 4; i++)
#pragma unroll
            for (int j = 0; j < 4; j++)
#pragma unroll
                for (int r = 0; r < 4; r++) dacc[i][j][r] = 0.f;

#pragma unroll
        for (int g = 0; g < 4; g++) {
            uint32_t af[4][4], bf[4][2];
#pragma unroll
            for (int i = 0; i < 4; i++) {
                unsigned addr = akU + (unsigned)(((i * 16 + lr) * HPD
                                                  + g * 8 + lc) * 4);
                LDSM4(af[i][0], af[i][1], af[i][2], af[i][3], addr);
            }
#pragma unroll
            for (int jj = 0; jj < 2; jj++) {
                unsigned addr = bpU + (unsigned)(((warp * 32 + jj * 16 + lr) * HPD
                                                  + g * 8 + lc) * 4);
                uint32_t r0, r1, r2, r3;
                LDSM4(r0, r1, r2, r3, addr);
                bf[jj * 2][0] = r0; bf[jj * 2 + 1][0] = r1;
                bf[jj * 2][1] = r2; bf[jj * 2 + 1][1] = r3;
            }
#pragma unroll
            for (int i = 0; i < 4; i++)
#pragma unroll
                for (int j = 0; j < 4; j++)
                    MMA_F16(dacc[i][j], af[i], bf[j]);
        }

        // phi + kc + store phi tile (tf32-rounded fp32, for tf32 ctx MMA)
#pragma unroll
        for (int i = 0; i < 4; i++) {
            const int rA = i * 16 + gid;
            const int rB = rA + 8;
            const float shA = diag[rA] + stab;
            const float shB = diag[rB] + stab;
#pragma unroll
            for (int j = 0; j < 4; j++) {
                const int col = warp * 32 + j * 8 + tig * 2;
                float p0 = RATIO * (__expf(dacc[i][j][0] * DN_SCALE - shA) + EPSF);
                float p1 = RATIO * (__expf(dacc[i][j][1] * DN_SCALE - shA) + EPSF);
                float p2 = RATIO * (__expf(dacc[i][j][2] * DN_SCALE - shB) + EPSF);
                float p3 = RATIO * (__expf(dacc[i][j][3] * DN_SCALE - shB) + EPSF);
                kcAcc[j][0] += p0 + p2;
                kcAcc[j][1] += p1 + p3;
                *(float2*)(Ph + rA * C2_FP + col) = make_float2(f2tf32f(p0), f2tf32f(p1));
                *(float2*)(Ph + rB * C2_FP + col) = make_float2(f2tf32f(p2), f2tf32f(p3));
            }
        }
        __syncthreads();

        // ctx MMA (tf32 scalar frags, unchanged)
#pragma unroll
        for (int ks = 0; ks < 64; ks += 8) {
            uint32_t af[4][4], bf[4][2];
#pragma unroll
            for (int i = 0; i < 4; i++) {
                const int mB = warpM * 64 + i * 16;
                af[i][0] = PhU[(ks + tig) * C2_FP + mB + gid];
                af[i][1] = PhU[(ks + tig) * C2_FP + mB + gid + 8];
                af[i][2] = PhU[(ks + tig + 4) * C2_FP + mB + gid];
                af[i][3] = PhU[(ks + tig + 4) * C2_FP + mB + gid + 8];
            }
#pragma unroll
            for (int j = 0; j < 4; j++) {
                const int nB = warpN * 32 + j * 8;
                bf[j][0] = BvU[(ks + tig) * C2_VP + nB + gid];
                bf[j][1] = BvU[(ks + tig + 4) * C2_VP + nB + gid];
            }
#pragma unroll
            for (int i = 0; i < 4; i++)
#pragma unroll
                for (int j = 0; j < 4; j++)
                    MMA_TF32(ctxAcc[i][j], af[i], bf[j]);
        }
    }

    float* cp = ctxPart + ((long)(split * BHN + bh)) * MF * DHD;
#pragma unroll
    for (int i = 0; i < 4; i++) {
        const int m = warpM * 64 + i * 16 + gid;
#pragma unroll
        for (int j = 0; j < 4; j++) {
            const int d = warpN * 32 + j * 8 + tig * 2;
            *(float2*)(cp + (long)m * DHD + d) = make_float2(ctxAcc[i][j][0], ctxAcc[i][j][1]);
            *(float2*)(cp + (long)(m + 8) * DHD + d) = make_float2(ctxAcc[i][j][2], ctxAcc[i][j][3]);
        }
    }
#pragma unroll
    for (int j = 0; j < 4; j++) {
#pragma unroll
        for (int p = 0; p < 2; p++) {
            float v = kcAcc[j][p];
            v += __shfl_xor_sync(0xffffffffu, v, 4);
            v += __shfl_xor_sync(0xffffffffu, v, 8);
            v += __shfl_xor_sync(0xffffffffu, v, 16);
            if (gid == 0) {
                const int col = warp * 32 + j * 8 + tig * 2 + p;
                kcPart[((long)(split * BHN + bh)) * MF + col] = v;
            }
        }
    }
}

// ---------------------------------------------------------------------------
// dashq_phi (fp16 dash): dashQ GEMM (fp16) + rowmax + phi + denominator.
// ---------------------------------------------------------------------------
__global__ __launch_bounds__(256) void dashq_phi(
    const float* __restrict__ Q, const float* __restrict__ proj,
    const float* __restrict__ kc, float* __restrict__ qp,
    float* __restrict__ denom)
{
    extern __shared__ uint32_t smu[];
    uint32_t* AsH = smu;                   // Q fp16 [128][36] = 4608 u32
    uint32_t* BsH = smu + 4608;            // proj fp16 [256][36] = 9216 u32
    float* diag = (float*)(smu + 13824);   // [128]
    float* kcS = diag + 128;               // [256]
    float* redA = kcS + 256;               // [512]
    float* redB = redA + 512;              // [512]

    const int rt = blockIdx.x, bh = blockIdx.y;
    const int b = bh >> 3, h = bh & 7;
    const int n0 = rt * 128;
    const int t = threadIdx.x;
    const int lane = t & 31, warp = t >> 5;
    const int warpM = warp >> 2;          // 0..1
    const int warpN = warp & 3;           // 0..3
    const int gid = lane >> 2, tig = lane & 3;
    const unsigned asU = (unsigned)__cvta_generic_to_shared(AsH);
    const unsigned bsU = (unsigned)__cvta_generic_to_shared(BsH);
    const int lr = lane & 15;
    const int lc = (lane >> 4) * 4;

    // stage A = Q rows [128][64] fp16
#pragma unroll
    for (int i = 0; i < 8; i++) {
        int linear = i * 256 + t;
        int n = linear >> 4, c4 = linear & 15;
        float4 v = *(const float4*)(Q + ((long)(b * NQ + n0 + n)) * DMODEL + h * DHD + c4 * 4);
        uint2 u = make_uint2(packh2(v.x, v.y), packh2(v.z, v.w));
        *(uint2*)&AsH[n * HPD + c4 * 2] = u;
    }
    // stage B = proj [256][64] fp16
#pragma unroll
    for (int i = 0; i < 16; i++) {
        int linear = i * 256 + t;
        int r = linear >> 4, c4 = linear & 15;
        float4 v = *(const float4*)(proj + (long)r * DHD + c4 * 4);
        uint2 u = make_uint2(packh2(v.x, v.y), packh2(v.z, v.w));
        *(uint2*)&BsH[r * HPD + c4 * 2] = u;
    }
    {
        int r = t >> 1, half = t & 1;
        const float* qr = Q + ((long)(b * NQ + n0 + r)) * DMODEL + h * DHD + half * 32;
        float ss = 0.f;
#pragma unroll
        for (int i = 0; i < 8; i++) {
            float4 v = *(const float4*)(qr + i * 4);
            ss += v.x * v.x + v.y * v.y + v.z * v.z + v.w * v.w;
        }
        ss += __shfl_xor_sync(0xffffffffu, ss, 1);
        if (half == 0) diag[r] = ss * 0.0625f;
    }
    kcS[t] = kc[bh * MF + t];
    __syncthreads();

    float acc[4][8][4];
#pragma unroll
    for (int i = 0; i < 4; i++)
#pragma unroll
        for (int j = 0; j < 8; j++)
#pragma unroll
            for (int r = 0; r < 4; r++) acc[i][j][r] = 0.f;

#pragma unroll
    for (int g = 0; g < 4; g++) {
        uint32_t af[4][4], bf[8][2];
#pragma unroll
        for (int i = 0; i < 4; i++) {
            unsigned addr = asU + (unsigned)(((warpM * 64 + i * 16 + lr) * HPD
                                              + g * 8 + lc) * 4);
            LDSM4(af[i][0], af[i][1], af[i][2], af[i][3], addr);
        }
#pragma unroll
        for (int jj = 0; jj < 4; jj++) {
            unsigned addr = bsU + (unsigned)(((warpN * 64 + jj * 16 + lr) * HPD
                                              + g * 8 + lc) * 4);
            uint32_t r0, r1, r2, r3;
            LDSM4(r0, r1, r2, r3, addr);
            bf[jj * 2][0] = r0; bf[jj * 2 + 1][0] = r1;
            bf[jj * 2][1] = r2; bf[jj * 2 + 1][1] = r3;
        }
#pragma unroll
        for (int i = 0; i < 4; i++)
#pragma unroll
            for (int j = 0; j < 8; j++)
                MMA_F16(acc[i][j], af[i], bf[j]);
    }

#pragma unroll
    for (int i = 0; i < 4; i++)
#pragma unroll
        for (int j = 0; j < 8; j++)
#pragma unroll
            for (int r = 0; r < 4; r++) acc[i][j][r] *= DN_SCALE;

#pragma unroll
    for (int i = 0; i < 4; i++) {
        const int rA = warpM * 64 + i * 16 + gid;
        float mA = -1e30f, mB = -1e30f;
#pragma unroll
        for (int j = 0; j < 8; j++) {
            mA = fmaxf(mA, fmaxf(acc[i][j][0], acc[i][j][1]));
            mB = fmaxf(mB, fmaxf(acc[i][j][2], acc[i][j][3]));
        }
        mA = fmaxf(mA, __shfl_xor_sync(0xffffffffu, mA, 1));
        mA = fmaxf(mA, __shfl_xor_sync(0xffffffffu, mA, 2));
        mB = fmaxf(mB, __shfl_xor_sync(0xffffffffu, mB, 1));
        mB = fmaxf(mB, __shfl_xor_sync(0xffffffffu, mB, 2));
        if (tig == 0) {
            redA[rA * 4 + warpN] = mA;
            redA[(rA + 8) * 4 + warpN] = mB;
        }
    }
    __syncthreads();

#pragma unroll
    for (int i = 0; i < 4; i++) {
        const int rA = warpM * 64 + i * 16 + gid;
        const int rB = rA + 8;
        const float rmA = fmaxf(fmaxf(redA[rA * 4], redA[rA * 4 + 1]),
                                fmaxf(redA[rA * 4 + 2], redA[rA * 4 + 3]));
        const float rmB = fmaxf(fmaxf(redA[rB * 4], redA[rB * 4 + 1]),
                                fmaxf(redA[rB * 4 + 2], redA[rB * 4 + 3]));
        const float shA = diag[rA] + rmA;
        const float shB = diag[rB] + rmB;
        float dA = 0.f, dB = 0.f;
#pragma unroll
        for (int j = 0; j < 8; j++) {
            const int col = warpN * 64 + (j >> 1) * 16 + (j & 1) * 8 + tig * 2;
            float p0 = RATIO * (__expf(acc[i][j][0] - shA) + EPSF);
            float p1 = RATIO * (__expf(acc[i][j][1] - shA) + EPSF);
            float p2 = RATIO * (__expf(acc[i][j][2] - shB) + EPSF);
            float p3 = RATIO * (__expf(acc[i][j][3] - shB) + EPSF);
            float2 kv = *(const float2*)(kcS + col);
            dA += p0 * kv.x + p1 * kv.y;
            dB += p2 * kv.x + p3 * kv.y;
            *(float2*)(qp + ((long)bh * NQ + n0 + rA) * MF + col) = make_float2(p0, p1);
            *(float2*)(qp + ((long)bh * NQ + n0 + rB) * MF + col) = make_float2(p2, p3);
        }
        dA += __shfl_xor_sync(0xffffffffu, dA, 1);
        dA += __shfl_xor_sync(0xffffffffu, dA, 2);
        dB += __shfl_xor_sync(0xffffffffu, dB, 1);
        dB += __shfl_xor_sync(0xffffffffu, dB, 2);
        if (tig == 0) {
            redB[rA * 4 + warpN] = dA;
            redB[rB * 4 + warpN] = dB;
        }
    }
    __syncthreads();
    if (warpN == 0 && tig == 0) {
#pragma unroll
        for (int i = 0; i < 4; i++) {
            const int rA = warpM * 64 + i * 16 + gid;
            const int rB = rA + 8;
            denom[(long)bh * NQ + n0 + rA] =
                (redB[rA * 4] + redB[rA * 4 + 1]) + (redB[rA * 4 + 2] + redB[rA * 4 + 3]);
            denom[(long)bh * NQ + n0 + rB] =
                (redB[rB * 4] + redB[rB * 4 + 1]) + (redB[rB * 4 + 2] + redB[rB * 4 + 3]);
        }
    }
}

// -------------------- small kernels ----------------------------------------
__global__ void init_stab(unsigned* __restrict__ s) {
    s[threadIdx.x] = 0u;
}

__global__ void to_half(const float2* __restrict__ in, __half2* __restrict__ out) {
    long i = (long)blockIdx.x * 256 + threadIdx.x;
    float2 v = in[i];
    out[i] = __floats2half2_rn(v.x, v.y);
}

__global__ void transpose_half(const float* __restrict__ in, __half* __restrict__ out) {
    __shared__ float t[32][33];
    int bx = blockIdx.x * 32, by = blockIdx.y * 32;
    int tx = threadIdx.x;
    for (int i = threadIdx.y; i < 32; i += 8)
        t[i][tx] = in[(by + i) * DMODEL + bx + tx];
    __syncthreads();
    for (int i = threadIdx.y; i < 32; i += 8)
        out[(long)(bx + i) * DMODEL + by + tx] = __float2half(t[tx][i]);
}

__global__ void kc_final8(const float* __restrict__ part, float* __restrict__ kc) {
    int bh = blockIdx.x, t = threadIdx.x;
    float s = 0.f;
#pragma unroll
    for (int sp = 0; sp < 8; sp++) s += part[((long)(sp * BHN + bh)) * MF + t];
    kc[bh * MF + t] = s;
}

__global__ void reduce_ctx8(const float* __restrict__ p, float* __restrict__ c) {
    int i = blockIdx.x * 256 + threadIdx.x;   // 1048576 total
    float s0 = p[i] + p[i + 1 * 1048576];
    float s1 = p[i + 2 * 1048576] + p[i + 3 * 1048576];
    float s2 = p[i + 4 * 1048576] + p[i + 5 * 1048576];
    float s3 = p[i + 6 * 1048576] + p[i + 7 * 1048576];
    c[i] = (s0 + s1) + (s2 + s3);
}

// ---------------------------------------------------------------------------
extern "C" void kernel_launch(void* const* d_in, const int* in_sizes, int n_in,
                              void* d_out, int out_size)
{
    (void)in_sizes; (void)n_in; (void)out_size;
    const float* x       = (const float*)d_in[0];
    const float* context = (const float*)d_in[1];
    const float* Wq      = (const float*)d_in[2];
    const float* Wk      = (const float*)d_in[3];
    const float* Wv      = (const float*)d_in[4];
    const float* Wo      = (const float*)d_in[5];
    const float* bo      = (const float*)d_in[6];
    const float* proj    = (const float*)d_in[7];
    float* out = (float*)d_out;

    float *Q, *K, *V, *qp, *kcPart, *kc, *denom, *ctxPart, *ctx;
    __half *xH, *ctxH, *WqT, *WkT, *WvT, *WoT, *attnH;
    unsigned* stabEnc;
    cudaGetSymbolAddress((void**)&Q, g_Q);
    cudaGetSymbolAddress((void**)&K, g_K);
    cudaGetSymbolAddress((void**)&V, g_V);
    cudaGetSymbolAddress((void**)&xH, g_xH);
    cudaGetSymbolAddress((void**)&ctxH, g_ctxH);
    cudaGetSymbolAddress((void**)&WqT, g_WqT);
    cudaGetSymbolAddress((void**)&WkT, g_WkT);
    cudaGetSymbolAddress((void**)&WvT, g_WvT);
    cudaGetSymbolAddress((void**)&WoT, g_WoT);
    cudaGetSymbolAddress((void**)&attnH, g_attnH);
    cudaGetSymbolAddress((void**)&qp, g_qp);
    cudaGetSymbolAddress((void**)&stabEnc, g_stabEnc);
    cudaGetSymbolAddress((void**)&kcPart, g_kcPart);
    cudaGetSymbolAddress((void**)&kc, g_kc);
    cudaGetSymbolAddress((void**)&denom, g_denom);
    cudaGetSymbolAddress((void**)&ctxPart, g_ctxPart);
    cudaGetSymbolAddress((void**)&ctx, g_ctx);

    const int SM_DK = (128 * HPD + 256 * HPD) * 4;                        // 55296
    const int SM_C2 = (9216 + 2304 + 64 * C2_FP + 64 * C2_VP + 64) * 4;   // 132352
    const int SM_DQ = (4608 + 9216 + 128 + 256 + 512 + 512) * 4;          // 60928
    cudaFuncSetAttribute(dashk_max, cudaFuncAttributeMaxDynamicSharedMemorySize, SM_DK);
    cudaFuncSetAttribute(ctx_fused2, cudaFuncAttributeMaxDynamicSharedMemorySize, SM_C2);
    cudaFuncSetAttribute(dashq_phi, cudaFuncAttributeMaxDynamicSharedMemorySize, SM_DQ);

    init_stab<<<1, BHN>>>(stabEnc);

    // half conversions
    to_half<<<8192, 256>>>((const float2*)x, (__half2*)xH);
    to_half<<<32768, 256>>>((const float2*)context, (__half2*)ctxH);
    transpose_half<<<dim3(16, 16), dim3(32, 8)>>>(Wq, WqT);
    transpose_half<<<dim3(16, 16), dim3(32, 8)>>>(Wk, WkT);
    transpose_half<<<dim3(16, 16), dim3(32, 8)>>>(Wv, WvT);
    transpose_half<<<dim3(16, 16), dim3(32, 8)>>>(Wo, WoT);

    // Q/K/V projections (fp16 cp.async pipeline)
    tmma2h_cp<<<dim3(4, 64), 128>>>(xH, WqT, Q, nullptr, DMODEL);
    tmma2h_cp<<<dim3(4, 256), 128>>>(ctxH, WkT, K, nullptr, DMODEL);
    tmma2h_cp<<<dim3(4, 256), 128>>>(ctxH, WvT, V, nullptr, DMODEL);

    // key stabilizer max (fp16 dash, no store)
    dashk_max<<<dim3(32, 64), 256, SM_DK>>>(K, proj, stabEnc);

    // fused dash-recompute (fp16) + phi + kc + ctx (tf32)
    ctx_fused2<<<dim3(8, 64), 256, SM_C2>>>(K, V, proj, stabEnc, ctxPart, kcPart);
    reduce_ctx8<<<4096, 256>>>(ctxPart, ctx);
    kc_final8<<<BHN, 256>>>(kcPart, kc);

    // fused dashQ (fp16) + phi_q + denominator
    dashq_phi<<<dim3(8, 64), 256, SM_DQ>>>(Q, proj, kc, qp, denom);

    // attn = (qp @ ctx) / denom, merged-head layout, HALF out (z = b*8 + h)
    tmma2<64, false><<<dim3(1, 8, BHN), 128>>>(qp, ctx, attnH, nullptr, denom, nullptr,
        MF, MF, DHD, DMODEL,
        8, 8,
        0, (long)NH * NQ * MF, (long)NQ * MF,
        0, (long)NH * MF * DHD, (long)MF * DHD,
        0, (long)NQ * DMODEL, DHD,
        (long)NH * NQ, NQ, 1.f);

    // final projection + bias (fp16 cp.async pipeline)
    tmma2h_cp<<<dim3(4, 64), 128>>>(attnH, WoT, out, bo, DMODEL);
}